// round 11
// baseline (speedup 1.0000x reference)
#include <cuda_runtime.h>
#include <cuda_fp16.h>
#include <math.h>
#include <stdint.h>

#define H 128
#define NMAX 100000
#define EMAX 200000
#define GMAX 4096

#define CDIV(a,b) (((a)+(b)-1)/(b))

// ---------------- scratch ----------------
__device__ __align__(16) float g_node[(size_t)NMAX*H];
__device__ __align__(16) float g_edge[(size_t)EMAX*H];
__device__ __align__(16) float g_agg [(size_t)NMAX*H];
__device__ __align__(16) float g_m   [(size_t)NMAX*H];
__device__ __align__(16) float g_gates[(size_t)NMAX*3*H];   // [N][384]: r | z | n_i
__device__ __align__(16) float g_qs  [(size_t)GMAX*2*H];
__device__ __align__(16) float g_hl  [(size_t)GMAX*H];
__device__ __align__(16) float g_cl  [(size_t)GMAX*H];
__device__ __align__(16) float g_gl  [(size_t)GMAX*4*H];
__device__ __align__(16) float g_fc  [(size_t)GMAX*H];
// prepared weights (fp16, mma-fragment order)
__device__ __align__(16) __half t_gin1[2*H*H];
__device__ __align__(16) __half t_gin2[2*H*H];
__device__ __align__(16) __half t_em1 [2*H*H];
__device__ __align__(16) __half t_em2 [2*H*H];
__device__ __align__(16) __half t_fc1 [H*2*H];       // C=128, K=256
__device__ __align__(16) __half t_gall[384*256];     // C=384, K=256
__device__ __align__(16) __half t_gnh [H*H];         // C=128, K=128
__device__ __align__(16) __half t_lw  [512*384];     // C=512, K=384
__device__ __align__(16) float t_gallb[384];
__device__ __align__(16) float t_lb  [512];

// ---------------- helpers ----------------
__device__ __forceinline__ float sigf(float x) { return 1.f / (1.f + expf(-x)); }

__device__ __forceinline__ unsigned long long fma2(unsigned long long a,
                                                   unsigned long long b,
                                                   unsigned long long c) {
    unsigned long long d;
    asm("fma.rn.f32x2 %0, %1, %2, %3;" : "=l"(d) : "l"(a), "l"(b), "l"(c));
    return d;
}
union U64F2 { unsigned long long u; float2 f; };
union U128 { float4 v; unsigned long long u[2]; uint32_t w[4]; };

__device__ __forceinline__ uint32_t h2pack(float a, float b) {
    __half2 h = __floats2half2_rn(a, b);
    return *(uint32_t*)&h;
}
__device__ __forceinline__ void mma16(float* c, const uint32_t* a, const uint32_t* b) {
    asm volatile(
        "mma.sync.aligned.m16n8k16.row.col.f32.f16.f16.f32 "
        "{%0,%1,%2,%3}, {%4,%5,%6,%7}, {%8,%9}, {%0,%1,%2,%3};"
        : "+f"(c[0]), "+f"(c[1]), "+f"(c[2]), "+f"(c[3])
        : "r"(a[0]), "r"(a[1]), "r"(a[2]), "r"(a[3]), "r"(b[0]), "r"(b[1]));
}
__device__ __forceinline__ void redv4(float* p, float a, float b, float c, float d) {
    asm volatile("red.global.add.v4.f32 [%0], {%1, %2, %3, %4};"
                 :: "l"(p), "f"(a), "f"(b), "f"(c), "f"(d) : "memory");
}
__device__ __forceinline__ void redv2(float* p, float a, float b) {
    asm volatile("red.global.add.v2.f32 [%0], {%1, %2};"
                 :: "l"(p), "f"(a), "f"(b) : "memory");
}
__device__ __forceinline__ void cpasync16(uint32_t saddr, const void* g) {
    asm volatile("cp.async.ca.shared.global [%0], [%1], 16;" :: "r"(saddr), "l"(g));
}
#define CP_COMMIT() asm volatile("cp.async.commit_group;" ::: "memory")
#define CP_WAIT0()  asm volatile("cp.async.wait_group 0;" ::: "memory")
#define CP_WAIT1()  asm volatile("cp.async.wait_group 1;" ::: "memory")

// fragment offset for weights: matrix [C cols][K k], chunk = 8KB per (colblock,kblock)
__device__ __forceinline__ size_t fragoff(int col, int k, int K) {
    int cb = col >> 7, kb = k >> 5;
    int nt = (col >> 4) & 7, cc = col & 15;
    int kq = (k >> 1) & 15, ks = kq >> 3, kk = kq & 7;
    int lane = (cc & 7) * 4 + (kk & 3);
    int reg = ((kk >> 2) << 1) | (cc >> 3);
    return ((((size_t)(cb * (K >> 5) + kb) * 16 + nt * 2 + ks) * 32 + lane) * 4 + reg) * 2
           + (k & 1);
}

// stage one 8KB weight chunk (fragment-ready) via cp.async; 128 threads
__device__ __forceinline__ void stage_Bf(uint32_t* Bs, const __half* src, int tid) {
#pragma unroll
    for (int i = 0; i < 4; i++) {
        int u = tid + i * 128;
        uint32_t sa = (uint32_t)__cvta_generic_to_shared(Bs + u * 4);
        cpasync16(sa, src + (size_t)u * 8);
    }
}

// LDG 8 rows of A (32-k block), concat support
__device__ __forceinline__ void ldg_A(float4* aR,
                                      const float* A, int lda, int K1,
                                      const float* A2, int lda2,
                                      int k0, int row0, int r_, int f4_, int M)
{
    const float* s = (k0 < K1) ? A : A2;
    int ld = (k0 < K1) ? lda : lda2;
    int koff = (k0 < K1) ? k0 : k0 - K1;
#pragma unroll
    for (int i = 0; i < 8; i++) {
        int row = row0 + r_ + 16 * i;
        aR[i] = make_float4(0.f, 0.f, 0.f, 0.f);
        if (row < M) aR[i] = *(const float4*)&s[(size_t)row * ld + koff + f4_ * 4];
    }
}

// scatter-STS A regs into fragment layout As[(mt*2+ks)*32+lane][reg]
__device__ __forceinline__ void sts_Af(uint32_t* As, const float4* aR, int r_, int f4_) {
    const int ks = f4_ >> 2;
    const int reg = ((((2 * f4_) & 7) >> 2) << 1) | (r_ >> 3);
    const int lane = (r_ & 7) * 4 + 2 * (f4_ & 1);
#pragma unroll
    for (int i = 0; i < 8; i++) {
        uint32_t* p = &As[((i * 2 + ks) * 32 + lane) * 4 + reg];
        p[0] = h2pack(aR[i].x, aR[i].y);
        p[4] = h2pack(aR[i].z, aR[i].w);
    }
}

// mma over one 32-k block: warp tile 64x64 (4 m-frags x 8 n-frags)
__device__ __forceinline__ void mma_block64(const uint32_t* As, const uint32_t* Bs,
                                            float acc[4][8][4], int mtb, int ntb, int lane)
{
#pragma unroll
    for (int ks = 0; ks < 2; ks++) {
        uint32_t af[4][4];
#pragma unroll
        for (int m = 0; m < 4; m++) {
            U128 t;
            t.v = *(const float4*)&As[(((mtb + m) * 2 + ks) * 32 + lane) * 4];
            af[m][0] = t.w[0]; af[m][1] = t.w[1]; af[m][2] = t.w[2]; af[m][3] = t.w[3];
        }
        uint32_t bf[8][2];
#pragma unroll
        for (int n2 = 0; n2 < 4; n2++) {
            U128 t;
            t.v = *(const float4*)&Bs[(((ntb + n2) * 2 + ks) * 32 + lane) * 4];
            bf[2 * n2][0] = t.w[0]; bf[2 * n2 + 1][0] = t.w[1];
            bf[2 * n2][1] = t.w[2]; bf[2 * n2 + 1][1] = t.w[3];
        }
#pragma unroll
        for (int m = 0; m < 4; m++)
#pragma unroll
            for (int n = 0; n < 8; n++) mma16(acc[m][n], af[m], bf[n]);
    }
}

// ---------------- k_tmma: O[M, col0+128] = act(concat(A,A2)[M,K] @ Wf^T + bias) ----------------
// Wf fragment-packed with full-K = Kfull. flags: bit0 relu, bit1 accum, bit2 GRU-finalize.
// Ky2 overrides K for blockIdx.y==2 (zero-padded gate chunk).
__global__ void __launch_bounds__(128, 2) k_tmma(
    const float* __restrict__ A, int lda, int K1,
    const float* __restrict__ A2, int lda2,
    const __half* __restrict__ Wf, int Kfull,
    const float* __restrict__ bias,
    float* __restrict__ O, int ldo,
    int M, int K, int Ky2, int flags,
    const float* __restrict__ gates, float* __restrict__ aggw,
    const float* __restrict__ eps, int epsidx)
{
    __shared__ uint32_t As[2048];
    __shared__ uint32_t BsB[2][2048];
    const int tid = threadIdx.x;
    const int wid = tid >> 5, lane = tid & 31;
    const int lr = lane >> 2, lc = lane & 3;
    const int row0 = blockIdx.x * 128;
    const int col0 = blockIdx.y * 128;
    const int rw = (wid & 1) * 64;
    const int cw = (wid >> 1) * 64;
    const int mtb = (wid & 1) * 4;      // base m-tile
    const int ntb = (wid >> 1) * 4;     // base n-tile (16-col groups)
    const int r_ = tid >> 3, f4_ = tid & 7;

    if (blockIdx.y == 2 && Ky2) K = Ky2;
    const __half* Wc = Wf + (size_t)(col0 >> 7) * (Kfull >> 5) * 4096;

    float acc[4][8][4];
#pragma unroll
    for (int m = 0; m < 4; m++)
#pragma unroll
        for (int n = 0; n < 8; n++)
#pragma unroll
            for (int c = 0; c < 4; c++) acc[m][n][c] = 0.f;

    const int nb = K >> 5;
    float4 aR[8];
    ldg_A(aR, A, lda, K1, A2, lda2, 0, row0, r_, f4_, M);
    stage_Bf(BsB[0], Wc, tid);
    CP_COMMIT();

    for (int kb = 0; kb < nb; kb++) {
        sts_Af(As, aR, r_, f4_);
        if (kb + 1 < nb) {
            stage_Bf(BsB[(kb + 1) & 1], Wc + (size_t)(kb + 1) * 4096, tid);
            CP_COMMIT();
            ldg_A(aR, A, lda, K1, A2, lda2, (kb + 1) * 32, row0, r_, f4_, M);
            CP_WAIT1();
        } else {
            CP_WAIT0();
        }
        __syncthreads();
        mma_block64(As, BsB[kb & 1], acc, mtb, ntb, lane);
        __syncthreads();
    }

    if (flags & 4) {
        float escale = (epsidx >= 0) ? (1.f + eps[epsidx]) : 0.f;
#pragma unroll
        for (int m = 0; m < 4; m++) {
#pragma unroll
            for (int n = 0; n < 8; n++) {
                int col = cw + n * 8 + lc * 2;
                float b0 = bias[col], b1 = bias[col + 1];
#pragma unroll
                for (int half = 0; half < 2; half++) {
                    int row = row0 + rw + m * 16 + lr + half * 8;
                    if (row < M) {
                        float nh0 = acc[m][n][half * 2] + b0;
                        float nh1 = acc[m][n][half * 2 + 1] + b1;
                        const float* gr = &gates[(size_t)row * 384];
                        float2 rr = *(const float2*)&gr[col];
                        float2 zz = *(const float2*)&gr[col + 128];
                        float2 ni = *(const float2*)&gr[col + 256];
                        float* hp = &O[(size_t)row * ldo + col];
                        float2 hv = *(float2*)hp;
                        float r0 = sigf(rr.x), z0 = sigf(zz.x);
                        float nn0 = tanhf(ni.x + r0 * nh0);
                        float h0 = (1.f - z0) * nn0 + z0 * hv.x;
                        float r1 = sigf(rr.y), z1 = sigf(zz.y);
                        float nn1 = tanhf(ni.y + r1 * nh1);
                        float h1 = (1.f - z1) * nn1 + z1 * hv.y;
                        float2 ho = {h0, h1};
                        *(float2*)hp = ho;
                        if (epsidx >= 0) {
                            float2 ao = {escale * h0, escale * h1};
                            *(float2*)&aggw[(size_t)row * 128 + col] = ao;
                        }
                    }
                }
            }
        }
        return;
    }

#pragma unroll
    for (int m = 0; m < 4; m++) {
#pragma unroll
        for (int n = 0; n < 8; n++) {
            int col = col0 + cw + n * 8 + lc * 2;
            float b0 = bias[col], b1 = bias[col + 1];
#pragma unroll
            for (int half = 0; half < 2; half++) {
                int row = row0 + rw + m * 16 + lr + half * 8;
                if (row < M) {
                    float v0 = acc[m][n][half * 2] + b0;
                    float v1 = acc[m][n][half * 2 + 1] + b1;
                    float* op = &O[(size_t)row * ldo + col];
                    if (flags & 2) { v0 += op[0]; v1 += op[1]; }
                    if (flags & 1) { v0 = fmaxf(v0, 0.f); v1 = fmaxf(v1, 0.f); }
                    float2 ov = {v0, v1};
                    *(float2*)op = ov;
                }
            }
        }
    }
}

// ---------------- fused 2-layer MLP core (64x64 warp tiles) ----------------
// sm: As 2048 u32 | Bs 2x2048 u32 | As2 8192 u32 (fragment order, K=128 -> 8 ksteps)
__device__ __forceinline__ void mlp2_core(
    const float* __restrict__ A, int lda,
    const __half* __restrict__ W1f, const float* __restrict__ b1,
    const __half* __restrict__ W2f, int M, int row0,
    uint32_t* sm, float acc[4][8][4])
{
    uint32_t* As = sm;
    uint32_t* Bs0 = sm + 2048;
    uint32_t* Bs1 = sm + 4096;
    uint32_t* As2 = sm + 6144;
    uint32_t* BsB[2] = { Bs0, Bs1 };
    const int tid = threadIdx.x;
    const int wid = tid >> 5, lane = tid & 31;
    const int lr = lane >> 2, lc = lane & 3;
    const int rw = (wid & 1) * 64;
    const int cw = (wid >> 1) * 64;
    const int mtb = (wid & 1) * 4;
    const int ntb = (wid >> 1) * 4;
    const int r_ = tid >> 3, f4_ = tid & 7;

#pragma unroll
    for (int m = 0; m < 4; m++)
#pragma unroll
        for (int n = 0; n < 8; n++)
#pragma unroll
            for (int c = 0; c < 4; c++) acc[m][n][c] = 0.f;

    float4 aR[8];
    ldg_A(aR, A, lda, 1 << 30, A, lda, 0, row0, r_, f4_, M);
    stage_Bf(BsB[0], W1f, tid);
    CP_COMMIT();

    // GEMM1: 4 k-blocks
#pragma unroll
    for (int kb = 0; kb < 4; kb++) {
        sts_Af(As, aR, r_, f4_);
        if (kb + 1 < 4) {
            stage_Bf(BsB[(kb + 1) & 1], W1f + (size_t)(kb + 1) * 4096, tid);
            CP_COMMIT();
            ldg_A(aR, A, lda, 1 << 30, A, lda, (kb + 1) * 32, row0, r_, f4_, M);
            CP_WAIT1();
        } else {
            CP_WAIT0();
        }
        __syncthreads();
        mma_block64(As, BsB[kb & 1], acc, mtb, ntb, lane);
        __syncthreads();
    }

    // mid epilogue: relu(+b1) -> As2 in fragment order (mt, ks over 8)
#pragma unroll
    for (int m = 0; m < 4; m++) {
#pragma unroll
        for (int n = 0; n < 8; n++) {
            int c2 = (cw >> 1) + n * 4 + lc;     // k2 of GEMM2
            int col = cw + n * 8 + lc * 2;
            float b0 = b1[col], bb1 = b1[col + 1];
            int ks = c2 >> 3, kk = c2 & 7;
#pragma unroll
            for (int half = 0; half < 2; half++) {
                int row = rw + m * 16 + lr + half * 8;
                int mt = row >> 4, rr = row & 15;
                int lane_w = (rr & 7) * 4 + (kk & 3);
                int reg = ((kk >> 2) << 1) | (rr >> 3);
                As2[((mt * 8 + ks) * 32 + lane_w) * 4 + reg] =
                    h2pack(fmaxf(acc[m][n][half * 2] + b0, 0.f),
                           fmaxf(acc[m][n][half * 2 + 1] + bb1, 0.f));
            }
#pragma unroll
            for (int c = 0; c < 4; c++) acc[m][n][c] = 0.f;
        }
    }
    __syncthreads();

    // GEMM2: As2(frag) @ W2f, B double-buffered
    stage_Bf(BsB[0], W2f, tid);
    CP_COMMIT();
#pragma unroll
    for (int kb = 0; kb < 4; kb++) {
        if (kb + 1 < 4) {
            stage_Bf(BsB[(kb + 1) & 1], W2f + (size_t)(kb + 1) * 4096, tid);
            CP_COMMIT();
            CP_WAIT1();
        } else {
            CP_WAIT0();
        }
        __syncthreads();
        const uint32_t* Bs = BsB[kb & 1];
#pragma unroll
        for (int ks2 = 0; ks2 < 2; ks2++) {
            const int ks = kb * 2 + ks2;
            uint32_t af[4][4];
#pragma unroll
            for (int m = 0; m < 4; m++) {
                U128 t;
                t.v = *(const float4*)&As2[(((mtb + m) * 8 + ks) * 32 + lane) * 4];
                af[m][0] = t.w[0]; af[m][1] = t.w[1]; af[m][2] = t.w[2]; af[m][3] = t.w[3];
            }
            uint32_t bf[8][2];
#pragma unroll
            for (int n2 = 0; n2 < 4; n2++) {
                U128 t;
                t.v = *(const float4*)&Bs[(((ntb + n2) * 2 + ks2) * 32 + lane) * 4];
                bf[2 * n2][0] = t.w[0]; bf[2 * n2 + 1][0] = t.w[1];
                bf[2 * n2][1] = t.w[2]; bf[2 * n2 + 1][1] = t.w[3];
            }
#pragma unroll
            for (int m = 0; m < 4; m++)
#pragma unroll
                for (int n = 0; n < 8; n++) mma16(acc[m][n], af[m], bf[n]);
        }
        __syncthreads();
    }
}

#define SMEM_MLP2_U32 (2048 + 2 * 2048 + 8192)

// GIN MLP: plain output
__global__ void __launch_bounds__(128, 2) k_mlp2(
    const float* __restrict__ A, int lda,
    const __half* __restrict__ W1f, const float* __restrict__ b1,
    const __half* __restrict__ W2f, const float* __restrict__ b2,
    float* __restrict__ O, int ldo, int M)
{
    extern __shared__ uint32_t sm[];
    float acc[4][8][4];
    const int row0 = blockIdx.x * 128;
    mlp2_core(A, lda, W1f, b1, W2f, M, row0, sm, acc);

    const int tid = threadIdx.x;
    const int wid = tid >> 5, lane = tid & 31;
    const int lr = lane >> 2, lc = lane & 3;
    const int rw = (wid & 1) * 64, cw = (wid >> 1) * 64;
#pragma unroll
    for (int m = 0; m < 4; m++) {
#pragma unroll
        for (int n = 0; n < 8; n++) {
            int col = cw + n * 8 + lc * 2;
            float b0 = b2[col], bb1 = b2[col + 1];
#pragma unroll
            for (int half = 0; half < 2; half++) {
                int row = row0 + rw + m * 16 + lr + half * 8;
                if (row < M) {
                    float2 ov = {acc[m][n][half * 2] + b0, acc[m][n][half * 2 + 1] + bb1};
                    *(float2*)&O[(size_t)row * ldo + col] = ov;
                }
            }
        }
    }
}

// edge MLP + fused GINE scatter
__global__ void __launch_bounds__(128, 2) k_mlp2s(
    const float* __restrict__ A, int lda,
    const __half* __restrict__ W1f, const float* __restrict__ b1,
    const __half* __restrict__ W2f, const float* __restrict__ b2,
    const int* __restrict__ src, const int* __restrict__ dst,
    const float* __restrict__ node, float* __restrict__ agg, int M)
{
    extern __shared__ uint32_t sm[];
    float acc[4][8][4];
    const int row0 = blockIdx.x * 128;
    mlp2_core(A, lda, W1f, b1, W2f, M, row0, sm, acc);

    const int tid = threadIdx.x;
    const int wid = tid >> 5, lane = tid & 31;
    const int lr = lane >> 2, lc = lane & 3;
    const int rw = (wid & 1) * 64, cw = (wid >> 1) * 64;
#pragma unroll
    for (int m = 0; m < 4; m++) {
#pragma unroll
        for (int n = 0; n < 8; n++) {
            int col = cw + n * 8 + lc * 2;
            float b0 = b2[col], bb1 = b2[col + 1];
#pragma unroll
            for (int half = 0; half < 2; half++) {
                int e = row0 + rw + m * 16 + lr + half * 8;
                if (e < M) {
                    float v0 = acc[m][n][half * 2] + b0;
                    float v1 = acc[m][n][half * 2 + 1] + bb1;
                    int s = src[e], d = dst[e];
                    float2 nv = *(const float2*)&node[(size_t)s * 128 + col];
                    float m0 = fmaxf(nv.x + v0, 0.f);
                    float m1 = fmaxf(nv.y + v1, 0.f);
                    redv2(&agg[(size_t)d * 128 + col], m0, m1);
                }
            }
        }
    }
}

// ---------------- FFMA2 GEMM for embeddings; mode 0: node(+agg init), mode 1: edge(+scatter)
__global__ void __launch_bounds__(256) k_gemm(
    const float* __restrict__ A, int lda,
    const float* __restrict__ W, int ldw,
    const float* __restrict__ bias,
    float* __restrict__ O, int M, int K, int mode,
    const float* __restrict__ eps, float* __restrict__ agg,
    const int* __restrict__ src, const int* __restrict__ dst,
    const float* __restrict__ node)
{
    __shared__ __align__(16) unsigned long long Asd[16][65];
    __shared__ __align__(16) float Ws[16][128];
    const int tid = threadIdx.x;
    const int tx = tid & 31, ty = tid >> 5;
    const int row0 = blockIdx.x * 64;

    unsigned long long acc[8][2];
#pragma unroll
    for (int r = 0; r < 8; r++) { acc[r][0] = 0ULL; acc[r][1] = 0ULL; }

    for (int k0 = 0; k0 < K; k0 += 16) {
#pragma unroll
        for (int i = tid; i < 1024; i += 256) {
            int r = i >> 4, k = i & 15;
            int row = row0 + r, kk = k0 + k;
            float v = (row < M && kk < K) ? A[(size_t)row * lda + kk] : 0.f;
            U64F2 p; p.f.x = v; p.f.y = v;
            Asd[k][r] = p.u;
        }
#pragma unroll
        for (int i = tid; i < 2048; i += 256) {
            int k = i >> 7, j = i & 127;
            int kk = k0 + k;
            Ws[k][j] = (kk < K) ? W[(size_t)kk * ldw + j] : 0.f;
        }
        __syncthreads();
#pragma unroll
        for (int k = 0; k < 16; k++) {
            U128 w; w.v = *(const float4*)&Ws[k][tx << 2];
#pragma unroll
            for (int r = 0; r < 8; r++) {
                unsigned long long a = Asd[k][(ty << 3) + r];
                acc[r][0] = fma2(a, w.u[0], acc[r][0]);
                acc[r][1] = fma2(a, w.u[1], acc[r][1]);
            }
        }
        __syncthreads();
    }
    const int col = tx << 2;
    float4 b4 = *(const float4*)&bias[col];
    float escale = (mode == 0) ? (1.f + eps[0]) : 0.f;
#pragma unroll
    for (int r = 0; r < 8; r++) {
        int row = row0 + (ty << 3) + r;
        if (row < M) {
            U64F2 p0, p1; p0.u = acc[r][0]; p1.u = acc[r][1];
            float v0 = p0.f.x + b4.x, v1 = p0.f.y + b4.y;
            float v2 = p1.f.x + b4.z, v3 = p1.f.y + b4.w;
            float4 ov = {v0, v1, v2, v3};
            *(float4*)&O[(size_t)row * 128 + col] = ov;
            if (mode == 0) {
                float4 av = {escale * v0, escale * v1, escale * v2, escale * v3};
                *(float4*)&agg[(size_t)row * 128 + col] = av;
            } else {
                int s = src[row], d = dst[row];
                float4 nv = *(const float4*)&node[(size_t)s * 128 + col];
                redv4(&agg[(size_t)d * 128 + col],
                      fmaxf(nv.x + v0, 0.f), fmaxf(nv.y + v1, 0.f),
                      fmaxf(nv.z + v2, 0.f), fmaxf(nv.w + v3, 0.f));
            }
        }
    }
}

// ---------------- prep: weight transposes/stacks -> fp16 fragment layout ----------------
__global__ void k_prep(const float* __restrict__ gin1, const float* __restrict__ gin2,
                       const float* __restrict__ em1, const float* __restrict__ em2,
                       const float* __restrict__ fcw1,
                       const float* __restrict__ gwih, const float* __restrict__ gwhh,
                       const float* __restrict__ gbih, const float* __restrict__ gbhh,
                       const float* __restrict__ lwih, const float* __restrict__ lwhh,
                       const float* __restrict__ lbih, const float* __restrict__ lbhh,
                       __half* __restrict__ tg1, __half* __restrict__ tg2,
                       __half* __restrict__ te1, __half* __restrict__ te2,
                       __half* __restrict__ tf1,
                       __half* __restrict__ tgall, float* __restrict__ tgallb,
                       __half* __restrict__ tgnh,
                       __half* __restrict__ tlw, float* __restrict__ tlb)
{
    int i = blockIdx.x * blockDim.x + threadIdx.x;
    if (i < 131072) {
        int m = i >> 14, j = i & 16383;
        int k = j >> 7, c = j & 127;     // source row = k, source col = out col
        int l = m & 1, which = m >> 1;
        const float* s = (which == 0) ? gin1 : (which == 1) ? gin2 : (which == 2) ? em1 : em2;
        __half* d = (which == 0) ? tg1 : (which == 1) ? tg2 : (which == 2) ? te1 : te2;
        d[(size_t)l * 16384 + fragoff(c, k, 128)] = __float2half_rn(s[(size_t)l * 16384 + j]);
    } else if (i < 163840) {
        int j = i - 131072;              // fcw1 [256][128]: k=row, col
        int k = j >> 7, c = j & 127;
        tf1[fragoff(c, k, 256)] = __float2half_rn(fcw1[j]);
    } else if (i < 262144) {
        int j = i - 163840;              // tgall: col c (0..383), k (0..255)
        int c = j >> 8, k = j & 255;
        float v = (k < 128) ? gwih[c * 128 + k]
                            : ((c < 256) ? gwhh[c * 128 + (k - 128)] : 0.f);
        tgall[fragoff(c, k, 256)] = __float2half_rn(v);
    } else if (i < 458752) {
        int j = i - 262144;              // tlw: col c (0..511), k (0..383)
        int c = j / 384, k = j % 384;
        float v = (k < 256) ? lwih[c * 256 + k] : lwhh[c * 128 + (k - 256)];
        tlw[fragoff(c, k, 384)] = __float2half_rn(v);
    } else if (i < 475136) {
        int j = i - 458752;              // tgnh: col=j>>7, k=j&127
        int c = j >> 7, k = j & 127;
        tgnh[fragoff(c, k, 128)] = __float2half_rn(gwhh[256 * 128 + j]);
    } else if (i < 475520) {
        int j = i - 475136;
        tgallb[j] = (j < 256) ? gbih[j] + gbhh[j] : gbih[j];
    } else if (i < 476032) {
        int j = i - 475520;
        tlb[j] = lbih[j] + lbhh[j];
    }
}

__global__ void k_zero3(float4* __restrict__ a, int na, float4* __restrict__ b, int nb,
                        float4* __restrict__ c, int nc)
{
    int i = blockIdx.x * blockDim.x + threadIdx.x;
    float4 z = make_float4(0.f, 0.f, 0.f, 0.f);
    if (i < na) a[i] = z;
    if (i < nb) b[i] = z;
    if (i < nc) c[i] = z;
}

__device__ __forceinline__ void lstm1(float i_, float f_, float g_, float o_,
                                      float& c, float& hh) {
    c = sigf(f_) * c + sigf(i_) * tanhf(g_);
    hh = sigf(o_) * tanhf(c);
}

__global__ void k_lstm(const float* __restrict__ gl, float* __restrict__ hl,
                       float* __restrict__ cl, int nw)
{
    int idx = blockIdx.x * blockDim.x + threadIdx.x;
    if (idx >= nw) return;
    int g = idx >> 5, j = (idx & 31) * 4;
    const float* gr = &gl[(size_t)g * 512];
    float4 i_ = *(const float4*)&gr[j];
    float4 f_ = *(const float4*)&gr[j + 128];
    float4 g_ = *(const float4*)&gr[j + 256];
    float4 o_ = *(const float4*)&gr[j + 384];
    float4* cp = (float4*)&cl[(size_t)g * 128 + j];
    float4* hp = (float4*)&hl[(size_t)g * 128 + j];
    float4 c = *cp, hh;
    lstm1(i_.x, f_.x, g_.x, o_.x, c.x, hh.x);
    lstm1(i_.y, f_.y, g_.y, o_.y, c.y, hh.y);
    lstm1(i_.z, f_.z, g_.z, o_.z, c.z, hh.z);
    lstm1(i_.w, f_.w, g_.w, o_.w, c.w, hh.w);
    *cp = c;
    *hp = hh;
}

__global__ void k_set2set(const int* __restrict__ batch, const float* __restrict__ node,
                          const float* __restrict__ hl, float* __restrict__ qs,
                          int N, int G)
{
    int warp = (blockIdx.x * blockDim.x + threadIdx.x) >> 5;
    if (warp >= G) return;
    const int lane = threadIdx.x & 31;
    const int g = warp;

    int lo = 0, hi = N;
    while (lo < hi) { int mid = (lo + hi) >> 1; if (batch[mid] < g) lo = mid + 1; else hi = mid; }
    const int s0 = lo;
    hi = N;
    while (lo < hi) { int mid = (lo + hi) >> 1; if (batch[mid] < g + 1) lo = mid + 1; else hi = mid; }
    const int s1 = lo;

    float4 qv = *(const float4*)&hl[(size_t)g * H + lane * 4];

    float mx = -INFINITY, den = 0.f;
    float4 racc = make_float4(0.f, 0.f, 0.f, 0.f);
    for (int i = s0; i < s1; i++) {
        float4 nv = *(const float4*)&node[(size_t)i * H + lane * 4];
        float d = nv.x * qv.x + nv.y * qv.y + nv.z * qv.z + nv.w * qv.w;
#pragma unroll
        for (int o = 16; o; o >>= 1) d += __shfl_xor_sync(0xffffffffu, d, o);
        float nm = fmaxf(mx, d);
        float sc = expf(mx - nm);
        float ex = expf(d - nm);
        den = den * sc + ex;
        racc.x = racc.x * sc + ex * nv.x;
        racc.y = racc.y * sc + ex * nv.y;
        racc.z = racc.z * sc + ex * nv.z;
        racc.w = racc.w * sc + ex * nv.w;
        mx = nm;
    }
    float inv = 1.f / fmaxf(den, 1e-9f);
    float* qrow = &qs[(size_t)g * 2 * H];
    *(float4*)&qrow[lane * 4] = qv;
    float4 rv = {racc.x * inv, racc.y * inv, racc.z * inv, racc.w * inv};
    *(float4*)&qrow[H + lane * 4] = rv;
}

__global__ void k_fc2(const float* __restrict__ fcin, const float* __restrict__ w2,
                      const float* __restrict__ b2, float* __restrict__ out, int G)
{
    int tid = blockIdx.x * blockDim.x + threadIdx.x;
    int g = tid >> 5;
    if (g >= G) return;
    int lane = tid & 31;
    float s = 0.f;
#pragma unroll
    for (int t = 0; t < 4; t++) {
        int j = lane + t * 32;
        s += fcin[(size_t)g * H + j] * w2[j];
    }
#pragma unroll
    for (int off = 16; off; off >>= 1) s += __shfl_xor_sync(0xffffffffu, s, off);
    if (lane == 0) out[g] = s + b2[0];
}

// ---------------- host launcher ----------------
extern "C" void kernel_launch(void* const* d_in, const int* in_sizes, int n_in,
                              void* d_out, int out_size)
{
    const float* x       = (const float*)d_in[0];
    const float* eattr   = (const float*)d_in[1];
    const int*   eindex  = (const int*)d_in[2];
    const int*   batch   = (const int*)d_in[3];
    const float* node_w  = (const float*)d_in[4];
    const float* node_b  = (const float*)d_in[5];
    const float* edge_w  = (const float*)d_in[6];
    const float* edge_b  = (const float*)d_in[7];
    const float* eps     = (const float*)d_in[8];
    const float* gin_w1  = (const float*)d_in[9];
    const float* gin_b1  = (const float*)d_in[10];
    const float* gin_w2  = (const float*)d_in[11];
    const float* gin_b2  = (const float*)d_in[12];
    const float* em_w1   = (const float*)d_in[13];
    const float* em_b1   = (const float*)d_in[14];
    const float* em_w2   = (const float*)d_in[15];
    const float* em_b2   = (const float*)d_in[16];
    const float* gru_wih = (const float*)d_in[17];
    const float* gru_whh = (const float*)d_in[18];
    const float* gru_bih = (const float*)d_in[19];
    const float* gru_bhh = (const float*)d_in[20];
    const float* lstm_wih= (const float*)d_in[21];
    const float* lstm_whh= (const float*)d_in[22];
    const float* lstm_bih= (const float*)d_in[23];
    const float* lstm_bhh= (const float*)d_in[24];
    const float* fc_w1   = (const float*)d_in[25];
    const float* fc_b1   = (const float*)d_in[26];
    const float* fc_w2   = (const float*)d_in[27];
    const float* fc_b2   = (const float*)d_in[28];

    const int N = in_sizes[0] / 14;
    const int E = in_sizes[1] / 4;
    const int G = out_size;

    float *p_node, *p_edge, *p_agg, *p_m, *p_gates;
    float *p_qs, *p_hl, *p_cl, *p_gl, *p_fc;
    __half *p_tg1, *p_tg2, *p_te1, *p_te2, *p_tf1, *p_tgall, *p_tgnh, *p_tlw;
    float *p_tgallb, *p_tlb;
    cudaGetSymbolAddress((void**)&p_node, g_node);
    cudaGetSymbolAddress((void**)&p_edge, g_edge);
    cudaGetSymbolAddress((void**)&p_agg,  g_agg);
    cudaGetSymbolAddress((void**)&p_m,    g_m);
    cudaGetSymbolAddress((void**)&p_gates, g_gates);
    cudaGetSymbolAddress((void**)&p_qs,   g_qs);
    cudaGetSymbolAddress((void**)&p_hl,   g_hl);
    cudaGetSymbolAddress((void**)&p_cl,   g_cl);
    cudaGetSymbolAddress((void**)&p_gl,   g_gl);
    cudaGetSymbolAddress((void**)&p_fc,   g_fc);
    cudaGetSymbolAddress((void**)&p_tg1,  t_gin1);
    cudaGetSymbolAddress((void**)&p_tg2,  t_gin2);
    cudaGetSymbolAddress((void**)&p_te1,  t_em1);
    cudaGetSymbolAddress((void**)&p_te2,  t_em2);
    cudaGetSymbolAddress((void**)&p_tf1,  t_fc1);
    cudaGetSymbolAddress((void**)&p_tgall, t_gall);
    cudaGetSymbolAddress((void**)&p_tgallb, t_gallb);
    cudaGetSymbolAddress((void**)&p_tgnh, t_gnh);
    cudaGetSymbolAddress((void**)&p_tlw,  t_lw);
    cudaGetSymbolAddress((void**)&p_tlb,  t_lb);

    const int TB = 256;
    const int SMEM_MLP2 = SMEM_MLP2_U32 * 4;
    cudaFuncSetAttribute(k_mlp2, cudaFuncAttributeMaxDynamicSharedMemorySize, SMEM_MLP2);
    cudaFuncSetAttribute(k_mlp2s, cudaFuncAttributeMaxDynamicSharedMemorySize, SMEM_MLP2);

    k_prep<<<CDIV(476032, TB), TB>>>(gin_w1, gin_w2, em_w1, em_w2, fc_w1,
                                     gru_wih, gru_whh, gru_bih, gru_bhh,
                                     lstm_wih, lstm_whh, lstm_bih, lstm_bhh,
                                     p_tg1, p_tg2, p_te1, p_te2, p_tf1,
                                     p_tgall, p_tgallb, p_tgnh, p_tlw, p_tlb);

    const int* src = eindex;
    const int* dst = eindex + E;

    k_gemm<<<CDIV(N, 64), 256>>>(x, 14, node_w, 128, node_b, p_node, N, 14, 0,
                                 eps, p_agg, nullptr, nullptr, nullptr);
    k_gemm<<<CDIV(E, 64), 256>>>(eattr, 4, edge_w, 128, edge_b, p_edge, E, 4, 1,
                                 eps, p_agg, src, dst, p_node);

    const int NT = CDIV(N, 128), ET = CDIV(E, 128), GT = CDIV(G, 128);

    for (int l = 0; l < 2; l++) {
        k_mlp2<<<NT, 128, SMEM_MLP2>>>(p_agg, 128, p_tg1 + l * 16384, gin_b1 + l * H,
                                       p_tg2 + l * 16384, gin_b2 + l * H, p_m, 128, N);
        // gates: r|z use K=256 ([m|h]); n_i chunk (y==2) uses K=128 (m only)
        k_tmma<<<dim3(NT, 3), 128>>>(p_m, 128, 128, p_node, 128, p_tgall, 256, p_tgallb,
                                     p_gates, 384, N, 256, 128, 0,
                                     nullptr, nullptr, nullptr, 0);
        k_tmma<<<dim3(NT, 1), 128>>>(p_node, 128, 128, p_node, 128, p_tgnh, 128,
                                     gru_bhh + 256, p_node, 128, N, 128, 0, 4,
                                     p_gates, p_agg, eps, (l == 0) ? 1 : -1);
        if (l == 0) {
            k_mlp2s<<<ET, 128, SMEM_MLP2>>>(p_edge, 128, p_te1, em_b1, p_te2, em_b2,
                                            src, dst, p_node, p_agg, E);
        }
    }

    // Set2Set
    k_zero3<<<CDIV(G * 64, TB), TB>>>((float4*)p_qs, G * 64, (float4*)p_hl, G * 32, (float4*)p_cl, G * 32);
    for (int step = 0; step < 3; step++) {
        k_tmma<<<dim3(GT, 4), 128>>>(p_qs, 256, 256, p_hl, 128, p_tlw, 384, p_tlb,
                                     p_gl, 512, G, 384, 0, 0,
                                     nullptr, nullptr, nullptr, 0);
        k_lstm<<<CDIV(G * 32, TB), TB>>>(p_gl, p_hl, p_cl, G * 32);
        k_set2set<<<CDIV(G * 32, TB), TB>>>(batch, p_node, p_hl, p_qs, N, G);
    }

    // final MLP
    k_tmma<<<dim3(GT, 1), 128>>>(p_qs, 256, 256, p_qs, 256, p_tf1, 256, fc_b1,
                                 p_fc, 128, G, 256, 0, 1,
                                 nullptr, nullptr, nullptr, 0);
    k_fc2<<<CDIV(G * 32, TB), TB>>>(p_fc, fc_w2, fc_b2, (float*)d_out, G);
}

// round 12
// speedup vs baseline: 1.3867x; 1.3867x over previous
#include <cuda_runtime.h>
#include <cuda_fp16.h>
#include <math.h>
#include <stdint.h>

#define H 128
#define NMAX 100000
#define EMAX 200000
#define GMAX 4096

#define CDIV(a,b) (((a)+(b)-1)/(b))

// ---------------- scratch ----------------
__device__ __align__(16) float g_node[(size_t)NMAX*H];
__device__ __align__(16) float g_edge[(size_t)EMAX*H];
__device__ __align__(16) float g_agg [(size_t)NMAX*H];
__device__ __align__(16) float g_m   [(size_t)NMAX*H];
__device__ __align__(16) float g_gates[(size_t)NMAX*3*H];   // [N][384]: r | z | n_i
__device__ __align__(16) float g_qs  [(size_t)GMAX*2*H];
__device__ __align__(16) float g_hl  [(size_t)GMAX*H];
__device__ __align__(16) float g_cl  [(size_t)GMAX*H];
__device__ __align__(16) float g_gl  [(size_t)GMAX*4*H];
__device__ __align__(16) float g_fc  [(size_t)GMAX*H];
// prepared weights (fp16)
__device__ __align__(16) __half t_gin1[2*H*H];
__device__ __align__(16) __half t_gin2[2*H*H];
__device__ __align__(16) __half t_em1 [2*H*H];
__device__ __align__(16) __half t_em2 [2*H*H];
__device__ __align__(16) __half t_fc1 [H*2*H];       // [128,256]
__device__ __align__(16) __half t_gall[384*256];     // rz (wih|whh) + n_i (wih|0)
__device__ __align__(16) __half t_gnh [H*H];         // gru_whh n-part [128,128]
__device__ __align__(16) __half t_lw  [512*384];     // lwih(256)|lwhh(128)
__device__ __align__(16) float t_gallb[384];
__device__ __align__(16) float t_lb  [512];

// ---------------- helpers ----------------
__device__ __forceinline__ float sigf(float x) { return 1.f / (1.f + expf(-x)); }

__device__ __forceinline__ unsigned long long fma2(unsigned long long a,
                                                   unsigned long long b,
                                                   unsigned long long c) {
    unsigned long long d;
    asm("fma.rn.f32x2 %0, %1, %2, %3;" : "=l"(d) : "l"(a), "l"(b), "l"(c));
    return d;
}
union U64F2 { unsigned long long u; float2 f; };
union U128 { float4 v; unsigned long long u[2]; };

__device__ __forceinline__ uint32_t h2pack(float a, float b) {
    __half2 h = __floats2half2_rn(a, b);
    return *(uint32_t*)&h;
}
__device__ __forceinline__ void mma16(float* c, const uint32_t* a, const uint32_t* b) {
    asm volatile(
        "mma.sync.aligned.m16n8k16.row.col.f32.f16.f16.f32 "
        "{%0,%1,%2,%3}, {%4,%5,%6,%7}, {%8,%9}, {%0,%1,%2,%3};"
        : "+f"(c[0]), "+f"(c[1]), "+f"(c[2]), "+f"(c[3])
        : "r"(a[0]), "r"(a[1]), "r"(a[2]), "r"(a[3]), "r"(b[0]), "r"(b[1]));
}
__device__ __forceinline__ void redv4(float* p, float a, float b, float c, float d) {
    asm volatile("red.global.add.v4.f32 [%0], {%1, %2, %3, %4};"
                 :: "l"(p), "f"(a), "f"(b), "f"(c), "f"(d) : "memory");
}
__device__ __forceinline__ void redv2(float* p, float a, float b) {
    asm volatile("red.global.add.v2.f32 [%0], {%1, %2};"
                 :: "l"(p), "f"(a), "f"(b) : "memory");
}
__device__ __forceinline__ void cpasync8(uint32_t saddr, const void* g) {
    asm volatile("cp.async.ca.shared.global [%0], [%1], 8;" :: "r"(saddr), "l"(g));
}

#define LDA2 20   // half2 units per row (16 data + 4 pad)
#define LD2H 68   // mid-stage half2 row stride

// fp16 mma inner loop ([row][k2] layout, LDA2 stride)
__device__ __forceinline__ void mma_block(const uint32_t* As, const uint32_t* Bs,
                                          float acc[2][8][4], int rw, int cw,
                                          int lr, int lc)
{
#pragma unroll
    for (int kk2 = 0; kk2 < 16; kk2 += 8) {
        uint32_t af[2][4];
#pragma unroll
        for (int m = 0; m < 2; m++) {
            int base = (rw + m * 16 + lr) * LDA2 + kk2 + lc;
            af[m][0] = As[base];
            af[m][1] = As[base + 8 * LDA2];
            af[m][2] = As[base + 4];
            af[m][3] = As[base + 8 * LDA2 + 4];
        }
        uint32_t bf[8][2];
#pragma unroll
        for (int n = 0; n < 8; n++) {
            int base = (cw + n * 8 + lr) * LDA2 + kk2 + lc;
            bf[n][0] = Bs[base];
            bf[n][1] = Bs[base + 4];
        }
#pragma unroll
        for (int m = 0; m < 2; m++)
#pragma unroll
            for (int n = 0; n < 8; n++) mma16(acc[m][n], af[m], bf[n]);
    }
}

// stage B tile [128 cols x 32 k] via cp.async
__device__ __forceinline__ void stage_B(uint32_t* Bs, const __half* Bt, int ldb,
                                        int col0, int k0, int tid)
{
#pragma unroll
    for (int i = 0; i < 4; i++) {
        int r = (tid >> 3) + i * 32;
        int e = tid & 7;
        uint32_t sa = (uint32_t)__cvta_generic_to_shared(&Bs[r * LDA2 + e * 2]);
        cpasync8(sa, &Bt[(size_t)(col0 + r) * ldb + k0 + e * 4]);
    }
}

// ---------------- k_tmma: O[M, col0+128] = act(concat(A,A2)[M,K] @ Bt^T + bias) ----------------
// flags: bit0 relu, bit1 accumulate, bit2 GRU-finalize. Ky2 overrides K when blockIdx.y==2.
__global__ void __launch_bounds__(256, 2) k_tmma(
    const float* __restrict__ A, int lda, int K1,
    const float* __restrict__ A2, int lda2,
    const __half* __restrict__ Bt, int ldb,
    const float* __restrict__ bias,
    float* __restrict__ O, int ldo,
    int M, int K, int Ky2, int flags,
    const float* __restrict__ gates, float* __restrict__ aggw,
    const float* __restrict__ eps, int epsidx)
{
    __shared__ uint32_t As[128 * LDA2];
    __shared__ uint32_t Bs[128 * LDA2];
    const int tid = threadIdx.x;
    const int wid = tid >> 5, lane = tid & 31;
    const int lr = lane >> 2, lc = lane & 3;
    const int row0 = blockIdx.x * 128;
    const int col0 = blockIdx.y * 128;
    const int rw = (wid & 3) * 32;
    const int cw = (wid >> 2) * 64;
    const int r_ = tid >> 3, f4_ = tid & 7;

    if (blockIdx.y == 2 && Ky2) K = Ky2;

    float acc[2][8][4];
#pragma unroll
    for (int m = 0; m < 2; m++)
#pragma unroll
        for (int n = 0; n < 8; n++)
#pragma unroll
            for (int c = 0; c < 4; c++) acc[m][n][c] = 0.f;

    float4 aR[4];
    {
        const float* srcA = (0 < K1) ? A : A2;
        int ldx = (0 < K1) ? lda : lda2;
#pragma unroll
        for (int i = 0; i < 4; i++) {
            int row = row0 + r_ + i * 32;
            aR[i] = make_float4(0.f, 0.f, 0.f, 0.f);
            if (row < M) aR[i] = *(const float4*)&srcA[(size_t)row * ldx + f4_ * 4];
        }
    }

    for (int k0 = 0; k0 < K; k0 += 32) {
        stage_B(Bs, Bt, ldb, col0, k0, tid);
        asm volatile("cp.async.commit_group;" ::: "memory");
#pragma unroll
        for (int i = 0; i < 4; i++) {
            int r = r_ + i * 32;
            uint32_t* p = &As[r * LDA2 + f4_ * 2];
            p[0] = h2pack(aR[i].x, aR[i].y);
            p[1] = h2pack(aR[i].z, aR[i].w);
        }
        int kn = k0 + 32;
        if (kn < K) {
            const float* srcA = (kn < K1) ? A : A2;
            int koff = (kn < K1) ? kn : kn - K1;
            int ldx = (kn < K1) ? lda : lda2;
#pragma unroll
            for (int i = 0; i < 4; i++) {
                int row = row0 + r_ + i * 32;
                aR[i] = make_float4(0.f, 0.f, 0.f, 0.f);
                if (row < M) aR[i] = *(const float4*)&srcA[(size_t)row * ldx + koff + f4_ * 4];
            }
        }
        asm volatile("cp.async.wait_group 0;" ::: "memory");
        __syncthreads();
        mma_block(As, Bs, acc, rw, cw, lr, lc);
        __syncthreads();
    }

    if (flags & 4) {
        float escale = (epsidx >= 0) ? (1.f + eps[epsidx]) : 0.f;
#pragma unroll
        for (int m = 0; m < 2; m++) {
#pragma unroll
            for (int n = 0; n < 8; n++) {
                int col = cw + n * 8 + lc * 2;
                float b0 = bias[col], b1 = bias[col + 1];
#pragma unroll
                for (int half = 0; half < 2; half++) {
                    int row = row0 + rw + m * 16 + lr + half * 8;
                    if (row < M) {
                        float nh0 = acc[m][n][half * 2] + b0;
                        float nh1 = acc[m][n][half * 2 + 1] + b1;
                        const float* gr = &gates[(size_t)row * 384];
                        float2 rr = *(const float2*)&gr[col];
                        float2 zz = *(const float2*)&gr[col + 128];
                        float2 ni = *(const float2*)&gr[col + 256];
                        float* hp = &O[(size_t)row * ldo + col];
                        float2 hv = *(float2*)hp;
                        float r0 = sigf(rr.x), z0 = sigf(zz.x);
                        float nn0 = tanhf(ni.x + r0 * nh0);
                        float h0 = (1.f - z0) * nn0 + z0 * hv.x;
                        float r1 = sigf(rr.y), z1 = sigf(zz.y);
                        float nn1 = tanhf(ni.y + r1 * nh1);
                        float h1 = (1.f - z1) * nn1 + z1 * hv.y;
                        float2 ho = {h0, h1};
                        *(float2*)hp = ho;
                        if (epsidx >= 0) {
                            float2 ao = {escale * h0, escale * h1};
                            *(float2*)&aggw[(size_t)row * 128 + col] = ao;
                        }
                    }
                }
            }
        }
        return;
    }

#pragma unroll
    for (int m = 0; m < 2; m++) {
#pragma unroll
        for (int n = 0; n < 8; n++) {
            int col = col0 + cw + n * 8 + lc * 2;
            float b0 = bias[col], b1 = bias[col + 1];
            int r1 = row0 + rw + m * 16 + lr;
            int r2 = r1 + 8;
            if (r1 < M) {
                float v0 = acc[m][n][0] + b0, v1 = acc[m][n][1] + b1;
                float* op = &O[(size_t)r1 * ldo + col];
                if (flags & 2) { v0 += op[0]; v1 += op[1]; }
                if (flags & 1) { v0 = fmaxf(v0, 0.f); v1 = fmaxf(v1, 0.f); }
                float2 ov = {v0, v1};
                *(float2*)op = ov;
            }
            if (r2 < M) {
                float v0 = acc[m][n][2] + b0, v1 = acc[m][n][3] + b1;
                float* op = &O[(size_t)r2 * ldo + col];
                if (flags & 2) { v0 += op[0]; v1 += op[1]; }
                if (flags & 1) { v0 = fmaxf(v0, 0.f); v1 = fmaxf(v1, 0.f); }
                float2 ov = {v0, v1};
                *(float2*)op = ov;
            }
        }
    }
}

// ---------------- fused 2-layer MLP core ----------------
__device__ __forceinline__ void mlp2_core(
    const float* __restrict__ A, int lda,
    const __half* __restrict__ W1t, const float* __restrict__ b1,
    const __half* __restrict__ W2t, int M, int row0,
    uint32_t* As, uint32_t* Bs, uint32_t* As2, float acc[2][8][4])
{
    const int tid = threadIdx.x;
    const int wid = tid >> 5, lane = tid & 31;
    const int lr = lane >> 2, lc = lane & 3;
    const int rw = (wid & 3) * 32;
    const int cw = (wid >> 2) * 64;
    const int r_ = tid >> 3, f4_ = tid & 7;

#pragma unroll
    for (int m = 0; m < 2; m++)
#pragma unroll
        for (int n = 0; n < 8; n++)
#pragma unroll
            for (int c = 0; c < 4; c++) acc[m][n][c] = 0.f;

    float4 aR[4];
#pragma unroll
    for (int i = 0; i < 4; i++) {
        int row = row0 + r_ + i * 32;
        aR[i] = make_float4(0.f, 0.f, 0.f, 0.f);
        if (row < M) aR[i] = *(const float4*)&A[(size_t)row * lda + f4_ * 4];
    }

    // GEMM1
    for (int k0 = 0; k0 < 128; k0 += 32) {
        stage_B(Bs, W1t, 128, 0, k0, tid);
        asm volatile("cp.async.commit_group;" ::: "memory");
#pragma unroll
        for (int i = 0; i < 4; i++) {
            int r = r_ + i * 32;
            uint32_t* p = &As[r * LDA2 + f4_ * 2];
            p[0] = h2pack(aR[i].x, aR[i].y);
            p[1] = h2pack(aR[i].z, aR[i].w);
        }
        int kn = k0 + 32;
        if (kn < 128) {
#pragma unroll
            for (int i = 0; i < 4; i++) {
                int row = row0 + r_ + i * 32;
                aR[i] = make_float4(0.f, 0.f, 0.f, 0.f);
                if (row < M) aR[i] = *(const float4*)&A[(size_t)row * lda + kn + f4_ * 4];
            }
        }
        asm volatile("cp.async.wait_group 0;" ::: "memory");
        __syncthreads();
        mma_block(As, Bs, acc, rw, cw, lr, lc);
        __syncthreads();
    }

    // mid epilogue: relu(+b1) -> As2 (half2 per col pair)
#pragma unroll
    for (int m = 0; m < 2; m++) {
#pragma unroll
        for (int n = 0; n < 8; n++) {
            int c2 = (cw >> 1) + n * 4 + lc;
            int col = cw + n * 8 + lc * 2;
            float b0 = b1[col], bb1 = b1[col + 1];
            int r1 = rw + m * 16 + lr, r2 = r1 + 8;
            As2[r1 * LD2H + c2] = h2pack(fmaxf(acc[m][n][0] + b0, 0.f),
                                         fmaxf(acc[m][n][1] + bb1, 0.f));
            As2[r2 * LD2H + c2] = h2pack(fmaxf(acc[m][n][2] + b0, 0.f),
                                         fmaxf(acc[m][n][3] + bb1, 0.f));
            acc[m][n][0] = acc[m][n][1] = acc[m][n][2] = acc[m][n][3] = 0.f;
        }
    }
    __syncthreads();

    // GEMM2: As2 @ W2t
    for (int k0 = 0; k0 < 128; k0 += 32) {
        stage_B(Bs, W2t, 128, 0, k0, tid);
        asm volatile("cp.async.commit_group;" ::: "memory");
        asm volatile("cp.async.wait_group 0;" ::: "memory");
        __syncthreads();
        const int k2b = k0 >> 1;
#pragma unroll
        for (int kk2 = 0; kk2 < 16; kk2 += 8) {
            uint32_t af[2][4];
#pragma unroll
            for (int m = 0; m < 2; m++) {
                int base = (rw + m * 16 + lr) * LD2H + k2b + kk2 + lc;
                af[m][0] = As2[base];
                af[m][1] = As2[base + 8 * LD2H];
                af[m][2] = As2[base + 4];
                af[m][3] = As2[base + 8 * LD2H + 4];
            }
            uint32_t bf[8][2];
#pragma unroll
            for (int n = 0; n < 8; n++) {
                int base = (cw + n * 8 + lr) * LDA2 + kk2 + lc;
                bf[n][0] = Bs[base];
                bf[n][1] = Bs[base + 4];
            }
#pragma unroll
            for (int m = 0; m < 2; m++)
#pragma unroll
                for (int n = 0; n < 8; n++) mma16(acc[m][n], af[m], bf[n]);
        }
        __syncthreads();
    }
}

// GIN MLP: plain output
__global__ void __launch_bounds__(256, 2) k_mlp2(
    const float* __restrict__ A, int lda,
    const __half* __restrict__ W1t, const float* __restrict__ b1,
    const __half* __restrict__ W2t, const float* __restrict__ b2,
    float* __restrict__ O, int ldo, int M)
{
    extern __shared__ uint32_t sm[];
    uint32_t* As  = sm;
    uint32_t* Bs  = sm + 128 * LDA2;
    uint32_t* As2 = sm + 2 * 128 * LDA2;
    float acc[2][8][4];
    const int row0 = blockIdx.x * 128;
    mlp2_core(A, lda, W1t, b1, W2t, M, row0, As, Bs, As2, acc);

    const int tid = threadIdx.x;
    const int wid = tid >> 5, lane = tid & 31;
    const int lr = lane >> 2, lc = lane & 3;
    const int rw = (wid & 3) * 32, cw = (wid >> 2) * 64;
#pragma unroll
    for (int m = 0; m < 2; m++) {
#pragma unroll
        for (int n = 0; n < 8; n++) {
            int col = cw + n * 8 + lc * 2;
            float b0 = b2[col], bb1 = b2[col + 1];
            int r1 = row0 + rw + m * 16 + lr;
            int r2 = r1 + 8;
            if (r1 < M) {
                float2 ov = {acc[m][n][0] + b0, acc[m][n][1] + bb1};
                *(float2*)&O[(size_t)r1 * ldo + col] = ov;
            }
            if (r2 < M) {
                float2 ov = {acc[m][n][2] + b0, acc[m][n][3] + bb1};
                *(float2*)&O[(size_t)r2 * ldo + col] = ov;
            }
        }
    }
}

// edge MLP + fused GINE scatter
__global__ void __launch_bounds__(256, 2) k_mlp2s(
    const float* __restrict__ A, int lda,
    const __half* __restrict__ W1t, const float* __restrict__ b1,
    const __half* __restrict__ W2t, const float* __restrict__ b2,
    const int* __restrict__ src, const int* __restrict__ dst,
    const float* __restrict__ node, float* __restrict__ agg, int M)
{
    extern __shared__ uint32_t sm[];
    uint32_t* As  = sm;
    uint32_t* Bs  = sm + 128 * LDA2;
    uint32_t* As2 = sm + 2 * 128 * LDA2;
    float acc[2][8][4];
    const int row0 = blockIdx.x * 128;
    mlp2_core(A, lda, W1t, b1, W2t, M, row0, As, Bs, As2, acc);

    const int tid = threadIdx.x;
    const int wid = tid >> 5, lane = tid & 31;
    const int lr = lane >> 2, lc = lane & 3;
    const int rw = (wid & 3) * 32, cw = (wid >> 2) * 64;
#pragma unroll
    for (int m = 0; m < 2; m++) {
#pragma unroll
        for (int n = 0; n < 8; n++) {
            int col = cw + n * 8 + lc * 2;
            float b0 = b2[col], bb1 = b2[col + 1];
#pragma unroll
            for (int half = 0; half < 2; half++) {
                int e = row0 + rw + m * 16 + lr + half * 8;
                if (e < M) {
                    float v0 = acc[m][n][half * 2] + b0;
                    float v1 = acc[m][n][half * 2 + 1] + bb1;
                    int s = src[e], d = dst[e];
                    float2 nv = *(const float2*)&node[(size_t)s * 128 + col];
                    float m0 = fmaxf(nv.x + v0, 0.f);
                    float m1 = fmaxf(nv.y + v1, 0.f);
                    redv2(&agg[(size_t)d * 128 + col], m0, m1);
                }
            }
        }
    }
}

// ---------------- FFMA2 GEMM for embeddings; mode 0: node(+agg init), mode 1: edge(+scatter)
__global__ void __launch_bounds__(256) k_gemm(
    const float* __restrict__ A, int lda,
    const float* __restrict__ W, int ldw,
    const float* __restrict__ bias,
    float* __restrict__ O, int M, int K, int mode,
    const float* __restrict__ eps, float* __restrict__ agg,
    const int* __restrict__ src, const int* __restrict__ dst,
    const float* __restrict__ node)
{
    __shared__ __align__(16) unsigned long long Asd[16][65];
    __shared__ __align__(16) float Ws[16][128];
    const int tid = threadIdx.x;
    const int tx = tid & 31, ty = tid >> 5;
    const int row0 = blockIdx.x * 64;

    unsigned long long acc[8][2];
#pragma unroll
    for (int r = 0; r < 8; r++) { acc[r][0] = 0ULL; acc[r][1] = 0ULL; }

    for (int k0 = 0; k0 < K; k0 += 16) {
#pragma unroll
        for (int i = tid; i < 1024; i += 256) {
            int r = i >> 4, k = i & 15;
            int row = row0 + r, kk = k0 + k;
            float v = (row < M && kk < K) ? A[(size_t)row * lda + kk] : 0.f;
            U64F2 p; p.f.x = v; p.f.y = v;
            Asd[k][r] = p.u;
        }
#pragma unroll
        for (int i = tid; i < 2048; i += 256) {
            int k = i >> 7, j = i & 127;
            int kk = k0 + k;
            Ws[k][j] = (kk < K) ? W[(size_t)kk * ldw + j] : 0.f;
        }
        __syncthreads();
#pragma unroll
        for (int k = 0; k < 16; k++) {
            U128 w; w.v = *(const float4*)&Ws[k][tx << 2];
#pragma unroll
            for (int r = 0; r < 8; r++) {
                unsigned long long a = Asd[k][(ty << 3) + r];
                acc[r][0] = fma2(a, w.u[0], acc[r][0]);
                acc[r][1] = fma2(a, w.u[1], acc[r][1]);
            }
        }
        __syncthreads();
    }
    const int col = tx << 2;
    float4 b4 = *(const float4*)&bias[col];
    float escale = (mode == 0) ? (1.f + eps[0]) : 0.f;
#pragma unroll
    for (int r = 0; r < 8; r++) {
        int row = row0 + (ty << 3) + r;
        if (row < M) {
            U64F2 p0, p1; p0.u = acc[r][0]; p1.u = acc[r][1];
            float v0 = p0.f.x + b4.x, v1 = p0.f.y + b4.y;
            float v2 = p1.f.x + b4.z, v3 = p1.f.y + b4.w;
            float4 ov = {v0, v1, v2, v3};
            *(float4*)&O[(size_t)row * 128 + col] = ov;
            if (mode == 0) {
                float4 av = {escale * v0, escale * v1, escale * v2, escale * v3};
                *(float4*)&agg[(size_t)row * 128 + col] = av;
            } else {
                int s = src[row], d = dst[row];
                float4 nv = *(const float4*)&node[(size_t)s * 128 + col];
                redv4(&agg[(size_t)d * 128 + col],
                      fmaxf(nv.x + v0, 0.f), fmaxf(nv.y + v1, 0.f),
                      fmaxf(nv.z + v2, 0.f), fmaxf(nv.w + v3, 0.f));
            }
        }
    }
}

// ---------------- prep: weight transposes/stacks -> fp16 ----------------
__global__ void k_prep(const float* __restrict__ gin1, const float* __restrict__ gin2,
                       const float* __restrict__ em1, const float* __restrict__ em2,
                       const float* __restrict__ fcw1,
                       const float* __restrict__ gwih, const float* __restrict__ gwhh,
                       const float* __restrict__ gbih, const float* __restrict__ gbhh,
                       const float* __restrict__ lwih, const float* __restrict__ lwhh,
                       const float* __restrict__ lbih, const float* __restrict__ lbhh,
                       __half* __restrict__ tg1, __half* __restrict__ tg2,
                       __half* __restrict__ te1, __half* __restrict__ te2,
                       __half* __restrict__ tf1,
                       __half* __restrict__ tgall, float* __restrict__ tgallb,
                       __half* __restrict__ tgnh,
                       __half* __restrict__ tlw, float* __restrict__ tlb)
{
    int i = blockIdx.x * blockDim.x + threadIdx.x;
    if (i < 131072) {
        int m = i >> 14, j = i & 16383;
        int r = j >> 7, c = j & 127;
        int l = m & 1, which = m >> 1;
        const float* s = (which == 0) ? gin1 : (which == 1) ? gin2 : (which == 2) ? em1 : em2;
        __half* d = (which == 0) ? tg1 : (which == 1) ? tg2 : (which == 2) ? te1 : te2;
        d[(size_t)l * 16384 + c * 128 + r] = __float2half_rn(s[(size_t)l * 16384 + j]);
    } else if (i < 163840) {
        int j = i - 131072;
        int r = j >> 7, c = j & 127;
        tf1[(size_t)c * 256 + r] = __float2half_rn(fcw1[j]);
    } else if (i < 262144) {
        int j = i - 163840;
        int c = j >> 8, k = j & 255;
        float v = (k < 128) ? gwih[c * 128 + k]
                            : ((c < 256) ? gwhh[c * 128 + (k - 128)] : 0.f);
        tgall[j] = __float2half_rn(v);
    } else if (i < 458752) {
        int j = i - 262144;
        int c = j / 384, k = j % 384;
        tlw[j] = __float2half_rn((k < 256) ? lwih[c * 256 + k] : lwhh[c * 128 + (k - 256)]);
    } else if (i < 475136) {
        int j = i - 458752;
        tgnh[j] = __float2half_rn(gwhh[256 * 128 + j]);
    } else if (i < 475520) {
        int j = i - 475136;
        tgallb[j] = (j < 256) ? gbih[j] + gbhh[j] : gbih[j];
    } else if (i < 476032) {
        int j = i - 475520;
        tlb[j] = lbih[j] + lbhh[j];
    }
}

// Set2Set init: gl = broadcast(tlb) (step-0 LSTM GEMM result), hl = cl = 0
__global__ void k_s2sinit(float* __restrict__ gl, const float* __restrict__ tlb,
                          float4* __restrict__ hl, float4* __restrict__ cl, int G)
{
    int i = blockIdx.x * blockDim.x + threadIdx.x;
    if (i < G * 512) gl[i] = tlb[i & 511];
    if (i < G * 32) {
        float4 z = make_float4(0.f, 0.f, 0.f, 0.f);
        hl[i] = z;
        cl[i] = z;
    }
}

__device__ __forceinline__ void lstm1(float i_, float f_, float g_, float o_,
                                      float& c, float& hh) {
    c = sigf(f_) * c + sigf(i_) * tanhf(g_);
    hh = sigf(o_) * tanhf(c);
}

__global__ void k_lstm(const float* __restrict__ gl, float* __restrict__ hl,
                       float* __restrict__ cl, int nw)
{
    int idx = blockIdx.x * blockDim.x + threadIdx.x;
    if (idx >= nw) return;
    int g = idx >> 5, j = (idx & 31) * 4;
    const float* gr = &gl[(size_t)g * 512];
    float4 i_ = *(const float4*)&gr[j];
    float4 f_ = *(const float4*)&gr[j + 128];
    float4 g_ = *(const float4*)&gr[j + 256];
    float4 o_ = *(const float4*)&gr[j + 384];
    float4* cp = (float4*)&cl[(size_t)g * 128 + j];
    float4* hp = (float4*)&hl[(size_t)g * 128 + j];
    float4 c = *cp, hh;
    lstm1(i_.x, f_.x, g_.x, o_.x, c.x, hh.x);
    lstm1(i_.y, f_.y, g_.y, o_.y, c.y, hh.y);
    lstm1(i_.z, f_.z, g_.z, o_.z, c.z, hh.z);
    lstm1(i_.w, f_.w, g_.w, o_.w, c.w, hh.w);
    *cp = c;
    *hp = hh;
}

__global__ void k_set2set(const int* __restrict__ batch, const float* __restrict__ node,
                          const float* __restrict__ hl, float* __restrict__ qs,
                          int N, int G)
{
    int warp = (blockIdx.x * blockDim.x + threadIdx.x) >> 5;
    if (warp >= G) return;
    const int lane = threadIdx.x & 31;
    const int g = warp;

    int lo = 0, hi = N;
    while (lo < hi) { int mid = (lo + hi) >> 1; if (batch[mid] < g) lo = mid + 1; else hi = mid; }
    const int s0 = lo;
    hi = N;
    while (lo < hi) { int mid = (lo + hi) >> 1; if (batch[mid] < g + 1) lo = mid + 1; else hi = mid; }
    const int s1 = lo;

    float4 qv = *(const float4*)&hl[(size_t)g * H + lane * 4];

    float mx = -INFINITY, den = 0.f;
    float4 racc = make_float4(0.f, 0.f, 0.f, 0.f);
    for (int i = s0; i < s1; i++) {
        float4 nv = *(const float4*)&node[(size_t)i * H + lane * 4];
        float d = nv.x * qv.x + nv.y * qv.y + nv.z * qv.z + nv.w * qv.w;
#pragma unroll
        for (int o = 16; o; o >>= 1) d += __shfl_xor_sync(0xffffffffu, d, o);
        float nm = fmaxf(mx, d);
        float sc = expf(mx - nm);
        float ex = expf(d - nm);
        den = den * sc + ex;
        racc.x = racc.x * sc + ex * nv.x;
        racc.y = racc.y * sc + ex * nv.y;
        racc.z = racc.z * sc + ex * nv.z;
        racc.w = racc.w * sc + ex * nv.w;
        mx = nm;
    }
    float inv = 1.f / fmaxf(den, 1e-9f);
    float* qrow = &qs[(size_t)g * 2 * H];
    *(float4*)&qrow[lane * 4] = qv;
    float4 rv = {racc.x * inv, racc.y * inv, racc.z * inv, racc.w * inv};
    *(float4*)&qrow[H + lane * 4] = rv;
}

__global__ void k_fc2(const float* __restrict__ fcin, const float* __restrict__ w2,
                      const float* __restrict__ b2, float* __restrict__ out, int G)
{
    int tid = blockIdx.x * blockDim.x + threadIdx.x;
    int g = tid >> 5;
    if (g >= G) return;
    int lane = tid & 31;
    float s = 0.f;
#pragma unroll
    for (int t = 0; t < 4; t++) {
        int j = lane + t * 32;
        s += fcin[(size_t)g * H + j] * w2[j];
    }
#pragma unroll
    for (int off = 16; off; off >>= 1) s += __shfl_xor_sync(0xffffffffu, s, off);
    if (lane == 0) out[g] = s + b2[0];
}

// ---------------- host launcher ----------------
extern "C" void kernel_launch(void* const* d_in, const int* in_sizes, int n_in,
                              void* d_out, int out_size)
{
    const float* x       = (const float*)d_in[0];
    const float* eattr   = (const float*)d_in[1];
    const int*   eindex  = (const int*)d_in[2];
    const int*   batch   = (const int*)d_in[3];
    const float* node_w  = (const float*)d_in[4];
    const float* node_b  = (const float*)d_in[5];
    const float* edge_w  = (const float*)d_in[6];
    const float* edge_b  = (const float*)d_in[7];
    const float* eps     = (const float*)d_in[8];
    const float* gin_w1  = (const float*)d_in[9];
    const float* gin_b1  = (const float*)d_in[10];
    const float* gin_w2  = (const float*)d_in[11];
    const float* gin_b2  = (const float*)d_in[12];
    const float* em_w1   = (const float*)d_in[13];
    const float* em_b1   = (const float*)d_in[14];
    const float* em_w2   = (const float*)d_in[15];
    const float* em_b2   = (const float*)d_in[16];
    const float* gru_wih = (const float*)d_in[17];
    const float* gru_whh = (const float*)d_in[18];
    const float* gru_bih = (const float*)d_in[19];
    const float* gru_bhh = (const float*)d_in[20];
    const float* lstm_wih= (const float*)d_in[21];
    const float* lstm_whh= (const float*)d_in[22];
    const float* lstm_bih= (const float*)d_in[23];
    const float* lstm_bhh= (const float*)d_in[24];
    const float* fc_w1   = (const float*)d_in[25];
    const float* fc_b1   = (const float*)d_in[26];
    const float* fc_w2   = (const float*)d_in[27];
    const float* fc_b2   = (const float*)d_in[28];

    const int N = in_sizes[0] / 14;
    const int E = in_sizes[1] / 4;
    const int G = out_size;

    float *p_node, *p_edge, *p_agg, *p_m, *p_gates;
    float *p_qs, *p_hl, *p_cl, *p_gl, *p_fc;
    __half *p_tg1, *p_tg2, *p_te1, *p_te2, *p_tf1, *p_tgall, *p_tgnh, *p_tlw;
    float *p_tgallb, *p_tlb;
    cudaGetSymbolAddress((void**)&p_node, g_node);
    cudaGetSymbolAddress((void**)&p_edge, g_edge);
    cudaGetSymbolAddress((void**)&p_agg,  g_agg);
    cudaGetSymbolAddress((void**)&p_m,    g_m);
    cudaGetSymbolAddress((void**)&p_gates, g_gates);
    cudaGetSymbolAddress((void**)&p_qs,   g_qs);
    cudaGetSymbolAddress((void**)&p_hl,   g_hl);
    cudaGetSymbolAddress((void**)&p_cl,   g_cl);
    cudaGetSymbolAddress((void**)&p_gl,   g_gl);
    cudaGetSymbolAddress((void**)&p_fc,   g_fc);
    cudaGetSymbolAddress((void**)&p_tg1,  t_gin1);
    cudaGetSymbolAddress((void**)&p_tg2,  t_gin2);
    cudaGetSymbolAddress((void**)&p_te1,  t_em1);
    cudaGetSymbolAddress((void**)&p_te2,  t_em2);
    cudaGetSymbolAddress((void**)&p_tf1,  t_fc1);
    cudaGetSymbolAddress((void**)&p_tgall, t_gall);
    cudaGetSymbolAddress((void**)&p_tgallb, t_gallb);
    cudaGetSymbolAddress((void**)&p_tgnh, t_gnh);
    cudaGetSymbolAddress((void**)&p_tlw,  t_lw);
    cudaGetSymbolAddress((void**)&p_tlb,  t_lb);

    const int TB = 256;
    const int SMEM_MLP2 = (2 * 128 * LDA2 + 128 * LD2H) * 4;
    cudaFuncSetAttribute(k_mlp2, cudaFuncAttributeMaxDynamicSharedMemorySize, SMEM_MLP2);
    cudaFuncSetAttribute(k_mlp2s, cudaFuncAttributeMaxDynamicSharedMemorySize, SMEM_MLP2);

    k_prep<<<CDIV(476032, TB), TB>>>(gin_w1, gin_w2, em_w1, em_w2, fc_w1,
                                     gru_wih, gru_whh, gru_bih, gru_bhh,
                                     lstm_wih, lstm_whh, lstm_bih, lstm_bhh,
                                     p_tg1, p_tg2, p_te1, p_te2, p_tf1,
                                     p_tgall, p_tgallb, p_tgnh, p_tlw, p_tlb);

    const int* src = eindex;
    const int* dst = eindex + E;

    k_gemm<<<CDIV(N, 64), 256>>>(x, 14, node_w, 128, node_b, p_node, N, 14, 0,
                                 eps, p_agg, nullptr, nullptr, nullptr);
    k_gemm<<<CDIV(E, 64), 256>>>(eattr, 4, edge_w, 128, edge_b, p_edge, E, 4, 1,
                                 eps, p_agg, src, dst, p_node);

    const int NT = CDIV(N, 128), ET = CDIV(E, 128), GT = CDIV(G, 128);

    for (int l = 0; l < 2; l++) {
        k_mlp2<<<NT, 256, SMEM_MLP2>>>(p_agg, 128, p_tg1 + l * 16384, gin_b1 + l * H,
                                       p_tg2 + l * 16384, gin_b2 + l * H, p_m, 128, N);
        // gates: r|z use K=256 ([m|h]); n_i chunk (y==2) uses K=128 (m only)
        k_tmma<<<dim3(NT, 3), 256>>>(p_m, 128, 128, p_node, 128, p_tgall, 256, p_tgallb,
                                     p_gates, 384, N, 256, 128, 0,
                                     nullptr, nullptr, nullptr, 0);
        k_tmma<<<dim3(NT, 1), 256>>>(p_node, 128, 128, p_node, 128, p_tgnh, 128,
                                     gru_bhh + 256, p_node, 128, N, 128, 0, 4,
                                     p_gates, p_agg, eps, (l == 0) ? 1 : -1);
        if (l == 0) {
            k_mlp2s<<<ET, 256, SMEM_MLP2>>>(p_edge, 128, p_te1, em_b1, p_te2, em_b2,
                                            src, dst, p_node, p_agg, E);
        }
    }

    // Set2Set: step-0 LSTM GEMM is just the bias (qs=hl=0) -> broadcast init
    k_s2sinit<<<CDIV(G * 512, TB), TB>>>(p_gl, p_tlb, (float4*)p_hl, (float4*)p_cl, G);
    for (int step = 0; step < 3; step++) {
        if (step > 0)
            k_tmma<<<dim3(GT, 4), 256>>>(p_qs, 256, 256, p_hl, 128, p_tlw, 384, p_tlb,
                                         p_gl, 512, G, 384, 0, 0,
                                         nullptr, nullptr, nullptr, 0);
        k_lstm<<<CDIV(G * 32, TB), TB>>>(p_gl, p_hl, p_cl, G * 32);
        k_set2set<<<CDIV(G * 32, TB), TB>>>(batch, p_node, p_hl, p_qs, N, G);
    }

    // final MLP
    k_tmma<<<dim3(GT, 1), 256>>>(p_qs, 256, 256, p_qs, 256, p_tf1, 256, fc_b1,
                                 p_fc, 128, G, 256, 0, 1,
                                 nullptr, nullptr, nullptr, 0);
    k_fc2<<<CDIV(G * 32, TB), TB>>>(p_fc, fc_w2, fc_b2, (float*)d_out, G);
}

// round 13
// speedup vs baseline: 1.3991x; 1.0089x over previous
#include <cuda_runtime.h>
#include <cuda_fp16.h>
#include <math.h>
#include <stdint.h>

#define H 128
#define NMAX 100000
#define EMAX 200000
#define GMAX 4096

#define CDIV(a,b) (((a)+(b)-1)/(b))

// ---------------- scratch ----------------
__device__ __align__(16) float g_node[(size_t)NMAX*H];
__device__ __align__(16) float g_edge[(size_t)EMAX*H];
__device__ __align__(16) float g_agg [(size_t)NMAX*H];
__device__ __align__(16) float g_m   [(size_t)NMAX*H];
__device__ __align__(16) float g_gates[(size_t)NMAX*3*H];   // [N][384]: r | z | n_i
__device__ __align__(16) float g_qs  [(size_t)GMAX*2*H];
__device__ __align__(16) float g_hl  [(size_t)GMAX*H];
__device__ __align__(16) float g_cl  [(size_t)GMAX*H];
__device__ __align__(16) float g_gl  [(size_t)GMAX*4*H];
__device__ __align__(16) float g_fc  [(size_t)GMAX*H];
// prepared weights (fp16)
__device__ __align__(16) __half t_gin1[2*H*H];
__device__ __align__(16) __half t_gin2[2*H*H];
__device__ __align__(16) __half t_em1 [2*H*H];
__device__ __align__(16) __half t_em2 [2*H*H];
__device__ __align__(16) __half t_fc1 [H*2*H];       // [128,256]
__device__ __align__(16) __half t_gall[384*256];     // rz (wih|whh) + n_i (wih|0)
__device__ __align__(16) __half t_gnh [H*H];         // gru_whh n-part [128,128]
__device__ __align__(16) __half t_lw  [512*384];     // lwih(256)|lwhh(128)
__device__ __align__(16) float t_gallb[384];
__device__ __align__(16) float t_lb  [512];

// ---------------- helpers ----------------
__device__ __forceinline__ float sigf(float x) { return 1.f / (1.f + expf(-x)); }

__device__ __forceinline__ unsigned long long fma2(unsigned long long a,
                                                   unsigned long long b,
                                                   unsigned long long c) {
    unsigned long long d;
    asm("fma.rn.f32x2 %0, %1, %2, %3;" : "=l"(d) : "l"(a), "l"(b), "l"(c));
    return d;
}
union U64F2 { unsigned long long u; float2 f; };
union U128 { float4 v; unsigned long long u[2]; };

__device__ __forceinline__ uint32_t h2pack(float a, float b) {
    __half2 h = __floats2half2_rn(a, b);
    return *(uint32_t*)&h;
}
__device__ __forceinline__ void mma16(float* c, const uint32_t* a, const uint32_t* b) {
    asm volatile(
        "mma.sync.aligned.m16n8k16.row.col.f32.f16.f16.f32 "
        "{%0,%1,%2,%3}, {%4,%5,%6,%7}, {%8,%9}, {%0,%1,%2,%3};"
        : "+f"(c[0]), "+f"(c[1]), "+f"(c[2]), "+f"(c[3])
        : "r"(a[0]), "r"(a[1]), "r"(a[2]), "r"(a[3]), "r"(b[0]), "r"(b[1]));
}
__device__ __forceinline__ void ldm_x4(uint32_t& r0, uint32_t& r1, uint32_t& r2,
                                       uint32_t& r3, uint32_t addr) {
    asm volatile("ldmatrix.sync.aligned.m8n8.x4.shared.b16 {%0,%1,%2,%3}, [%4];"
                 : "=r"(r0), "=r"(r1), "=r"(r2), "=r"(r3) : "r"(addr));
}
__device__ __forceinline__ void redv4(float* p, float a, float b, float c, float d) {
    asm volatile("red.global.add.v4.f32 [%0], {%1, %2, %3, %4};"
                 :: "l"(p), "f"(a), "f"(b), "f"(c), "f"(d) : "memory");
}
__device__ __forceinline__ void redv2(float* p, float a, float b) {
    asm volatile("red.global.add.v2.f32 [%0], {%1, %2};"
                 :: "l"(p), "f"(a), "f"(b) : "memory");
}
__device__ __forceinline__ void cpasync8(uint32_t saddr, const void* g) {
    asm volatile("cp.async.ca.shared.global [%0], [%1], 8;" :: "r"(saddr), "l"(g));
}

#define LDA2 20   // half2 units per row (16 data + 4 pad)
#define LD2H 68   // mid-stage half2 row stride

// one k16 step: A tile rows [aRow0, +32), B cols [bCol0, +64), via ldmatrix
template<int SA, int SB>
__device__ __forceinline__ void mma_k16(uint32_t asA, int aRow0, int aK2,
                                        uint32_t asB, int bCol0, int bK2,
                                        float acc[2][8][4], int lane)
{
    const int g = lane >> 3, r8 = lane & 7;
    uint32_t aAddr = asA + (uint32_t)((((aRow0 + (g & 1) * 8 + r8) * SA) + aK2 + (g >> 1) * 4) * 4);
    uint32_t bAddr = asB + (uint32_t)((((bCol0 + (g >> 1) * 8 + r8) * SB) + bK2 + (g & 1) * 4) * 4);
    uint32_t af[2][4];
#pragma unroll
    for (int m = 0; m < 2; m++)
        ldm_x4(af[m][0], af[m][1], af[m][2], af[m][3], aAddr + m * 16 * SA * 4);
    uint32_t bf[8][2];
#pragma unroll
    for (int n2 = 0; n2 < 4; n2++)
        ldm_x4(bf[2*n2][0], bf[2*n2][1], bf[2*n2+1][0], bf[2*n2+1][1],
               bAddr + n2 * 16 * SB * 4);
#pragma unroll
    for (int m = 0; m < 2; m++)
#pragma unroll
        for (int n = 0; n < 8; n++) mma16(acc[m][n], af[m], bf[n]);
}

// stage B tile [128 cols x 32 k] via cp.async
__device__ __forceinline__ void stage_B(uint32_t* Bs, const __half* Bt, int ldb,
                                        int col0, int k0, int tid)
{
#pragma unroll
    for (int i = 0; i < 4; i++) {
        int r = (tid >> 3) + i * 32;
        int e = tid & 7;
        uint32_t sa = (uint32_t)__cvta_generic_to_shared(&Bs[r * LDA2 + e * 2]);
        cpasync8(sa, &Bt[(size_t)(col0 + r) * ldb + k0 + e * 4]);
    }
}

// ---------------- k_tmma: O[M, col0+128] = act(concat(A,A2)[M,K] @ Bt^T + bias) ----------------
// flags: bit0 relu, bit1 accumulate, bit2 GRU-finalize. Ky2 overrides K when blockIdx.y==2.
__global__ void __launch_bounds__(256, 2) k_tmma(
    const float* __restrict__ A, int lda, int K1,
    const float* __restrict__ A2, int lda2,
    const __half* __restrict__ Bt, int ldb,
    const float* __restrict__ bias,
    float* __restrict__ O, int ldo,
    int M, int K, int Ky2, int flags,
    const float* __restrict__ gates, float* __restrict__ aggw,
    const float* __restrict__ eps, int epsidx)
{
    __shared__ uint32_t As[128 * LDA2];
    __shared__ uint32_t Bs[128 * LDA2];
    const uint32_t asA = (uint32_t)__cvta_generic_to_shared(As);
    const uint32_t asB = (uint32_t)__cvta_generic_to_shared(Bs);
    const int tid = threadIdx.x;
    const int wid = tid >> 5, lane = tid & 31;
    const int lr = lane >> 2, lc = lane & 3;
    const int row0 = blockIdx.x * 128;
    const int col0 = blockIdx.y * 128;
    const int rw = (wid & 3) * 32;
    const int cw = (wid >> 2) * 64;
    const int r_ = tid >> 3, f4_ = tid & 7;

    if (blockIdx.y == 2 && Ky2) K = Ky2;

    float acc[2][8][4];
#pragma unroll
    for (int m = 0; m < 2; m++)
#pragma unroll
        for (int n = 0; n < 8; n++)
#pragma unroll
            for (int c = 0; c < 4; c++) acc[m][n][c] = 0.f;

    float4 aR[4];
    {
        const float* srcA = (0 < K1) ? A : A2;
        int ldx = (0 < K1) ? lda : lda2;
#pragma unroll
        for (int i = 0; i < 4; i++) {
            int row = row0 + r_ + i * 32;
            aR[i] = make_float4(0.f, 0.f, 0.f, 0.f);
            if (row < M) aR[i] = *(const float4*)&srcA[(size_t)row * ldx + f4_ * 4];
        }
    }

    for (int k0 = 0; k0 < K; k0 += 32) {
        stage_B(Bs, Bt, ldb, col0, k0, tid);
        asm volatile("cp.async.commit_group;" ::: "memory");
#pragma unroll
        for (int i = 0; i < 4; i++) {
            int r = r_ + i * 32;
            uint32_t* p = &As[r * LDA2 + f4_ * 2];
            p[0] = h2pack(aR[i].x, aR[i].y);
            p[1] = h2pack(aR[i].z, aR[i].w);
        }
        int kn = k0 + 32;
        if (kn < K) {
            const float* srcA = (kn < K1) ? A : A2;
            int koff = (kn < K1) ? kn : kn - K1;
            int ldx = (kn < K1) ? lda : lda2;
#pragma unroll
            for (int i = 0; i < 4; i++) {
                int row = row0 + r_ + i * 32;
                aR[i] = make_float4(0.f, 0.f, 0.f, 0.f);
                if (row < M) aR[i] = *(const float4*)&srcA[(size_t)row * ldx + koff + f4_ * 4];
            }
        }
        asm volatile("cp.async.wait_group 0;" ::: "memory");
        __syncthreads();
        mma_k16<LDA2, LDA2>(asA, rw, 0, asB, cw, 0, acc, lane);
        mma_k16<LDA2, LDA2>(asA, rw, 8, asB, cw, 8, acc, lane);
        __syncthreads();
    }

    if (flags & 4) {
        float escale = (epsidx >= 0) ? (1.f + eps[epsidx]) : 0.f;
#pragma unroll
        for (int m = 0; m < 2; m++) {
#pragma unroll
            for (int n = 0; n < 8; n++) {
                int col = cw + n * 8 + lc * 2;
                float b0 = bias[col], b1 = bias[col + 1];
#pragma unroll
                for (int half = 0; half < 2; half++) {
                    int row = row0 + rw + m * 16 + lr + half * 8;
                    if (row < M) {
                        float nh0 = acc[m][n][half * 2] + b0;
                        float nh1 = acc[m][n][half * 2 + 1] + b1;
                        const float* gr = &gates[(size_t)row * 384];
                        float2 rr = *(const float2*)&gr[col];
                        float2 zz = *(const float2*)&gr[col + 128];
                        float2 ni = *(const float2*)&gr[col + 256];
                        float* hp = &O[(size_t)row * ldo + col];
                        float2 hv = *(float2*)hp;
                        float r0 = sigf(rr.x), z0 = sigf(zz.x);
                        float nn0 = tanhf(ni.x + r0 * nh0);
                        float h0 = (1.f - z0) * nn0 + z0 * hv.x;
                        float r1 = sigf(rr.y), z1 = sigf(zz.y);
                        float nn1 = tanhf(ni.y + r1 * nh1);
                        float h1 = (1.f - z1) * nn1 + z1 * hv.y;
                        float2 ho = {h0, h1};
                        *(float2*)hp = ho;
                        if (epsidx >= 0) {
                            float2 ao = {escale * h0, escale * h1};
                            *(float2*)&aggw[(size_t)row * 128 + col] = ao;
                        }
                    }
                }
            }
        }
        return;
    }

#pragma unroll
    for (int m = 0; m < 2; m++) {
#pragma unroll
        for (int n = 0; n < 8; n++) {
            int col = col0 + cw + n * 8 + lc * 2;
            float b0 = bias[col], b1 = bias[col + 1];
            int r1 = row0 + rw + m * 16 + lr;
            int r2 = r1 + 8;
            if (r1 < M) {
                float v0 = acc[m][n][0] + b0, v1 = acc[m][n][1] + b1;
                float* op = &O[(size_t)r1 * ldo + col];
                if (flags & 2) { v0 += op[0]; v1 += op[1]; }
                if (flags & 1) { v0 = fmaxf(v0, 0.f); v1 = fmaxf(v1, 0.f); }
                float2 ov = {v0, v1};
                *(float2*)op = ov;
            }
            if (r2 < M) {
                float v0 = acc[m][n][2] + b0, v1 = acc[m][n][3] + b1;
                float* op = &O[(size_t)r2 * ldo + col];
                if (flags & 2) { v0 += op[0]; v1 += op[1]; }
                if (flags & 1) { v0 = fmaxf(v0, 0.f); v1 = fmaxf(v1, 0.f); }
                float2 ov = {v0, v1};
                *(float2*)op = ov;
            }
        }
    }
}

// ---------------- fused 2-layer MLP core ----------------
__device__ __forceinline__ void mlp2_core(
    const float* __restrict__ A, int lda,
    const __half* __restrict__ W1t, const float* __restrict__ b1,
    const __half* __restrict__ W2t, int M, int row0,
    uint32_t* As, uint32_t* Bs, uint32_t* As2, float acc[2][8][4])
{
    const uint32_t asA = (uint32_t)__cvta_generic_to_shared(As);
    const uint32_t asB = (uint32_t)__cvta_generic_to_shared(Bs);
    const uint32_t asA2 = (uint32_t)__cvta_generic_to_shared(As2);
    const int tid = threadIdx.x;
    const int wid = tid >> 5, lane = tid & 31;
    const int lr = lane >> 2, lc = lane & 3;
    const int rw = (wid & 3) * 32;
    const int cw = (wid >> 2) * 64;
    const int r_ = tid >> 3, f4_ = tid & 7;

#pragma unroll
    for (int m = 0; m < 2; m++)
#pragma unroll
        for (int n = 0; n < 8; n++)
#pragma unroll
            for (int c = 0; c < 4; c++) acc[m][n][c] = 0.f;

    float4 aR[4];
#pragma unroll
    for (int i = 0; i < 4; i++) {
        int row = row0 + r_ + i * 32;
        aR[i] = make_float4(0.f, 0.f, 0.f, 0.f);
        if (row < M) aR[i] = *(const float4*)&A[(size_t)row * lda + f4_ * 4];
    }

    // GEMM1
    for (int k0 = 0; k0 < 128; k0 += 32) {
        stage_B(Bs, W1t, 128, 0, k0, tid);
        asm volatile("cp.async.commit_group;" ::: "memory");
#pragma unroll
        for (int i = 0; i < 4; i++) {
            int r = r_ + i * 32;
            uint32_t* p = &As[r * LDA2 + f4_ * 2];
            p[0] = h2pack(aR[i].x, aR[i].y);
            p[1] = h2pack(aR[i].z, aR[i].w);
        }
        int kn = k0 + 32;
        if (kn < 128) {
#pragma unroll
            for (int i = 0; i < 4; i++) {
                int row = row0 + r_ + i * 32;
                aR[i] = make_float4(0.f, 0.f, 0.f, 0.f);
                if (row < M) aR[i] = *(const float4*)&A[(size_t)row * lda + kn + f4_ * 4];
            }
        }
        asm volatile("cp.async.wait_group 0;" ::: "memory");
        __syncthreads();
        mma_k16<LDA2, LDA2>(asA, rw, 0, asB, cw, 0, acc, lane);
        mma_k16<LDA2, LDA2>(asA, rw, 8, asB, cw, 8, acc, lane);
        __syncthreads();
    }

    // mid epilogue: relu(+b1) -> As2 (half2 per col pair)
#pragma unroll
    for (int m = 0; m < 2; m++) {
#pragma unroll
        for (int n = 0; n < 8; n++) {
            int c2 = (cw >> 1) + n * 4 + lc;
            int col = cw + n * 8 + lc * 2;
            float b0 = b1[col], bb1 = b1[col + 1];
            int r1 = rw + m * 16 + lr, r2 = r1 + 8;
            As2[r1 * LD2H + c2] = h2pack(fmaxf(acc[m][n][0] + b0, 0.f),
                                         fmaxf(acc[m][n][1] + bb1, 0.f));
            As2[r2 * LD2H + c2] = h2pack(fmaxf(acc[m][n][2] + b0, 0.f),
                                         fmaxf(acc[m][n][3] + bb1, 0.f));
            acc[m][n][0] = acc[m][n][1] = acc[m][n][2] = acc[m][n][3] = 0.f;
        }
    }
    __syncthreads();

    // GEMM2: As2 @ W2t
    for (int k0 = 0; k0 < 128; k0 += 32) {
        stage_B(Bs, W2t, 128, 0, k0, tid);
        asm volatile("cp.async.commit_group;" ::: "memory");
        asm volatile("cp.async.wait_group 0;" ::: "memory");
        __syncthreads();
        const int k2b = k0 >> 1;
        mma_k16<LD2H, LDA2>(asA2, rw, k2b,     asB, cw, 0, acc, lane);
        mma_k16<LD2H, LDA2>(asA2, rw, k2b + 8, asB, cw, 8, acc, lane);
        __syncthreads();
    }
}

// GIN MLP: plain output
__global__ void __launch_bounds__(256, 2) k_mlp2(
    const float* __restrict__ A, int lda,
    const __half* __restrict__ W1t, const float* __restrict__ b1,
    const __half* __restrict__ W2t, const float* __restrict__ b2,
    float* __restrict__ O, int ldo, int M)
{
    extern __shared__ uint32_t sm[];
    uint32_t* As  = sm;
    uint32_t* Bs  = sm + 128 * LDA2;
    uint32_t* As2 = sm + 2 * 128 * LDA2;
    float acc[2][8][4];
    const int row0 = blockIdx.x * 128;
    mlp2_core(A, lda, W1t, b1, W2t, M, row0, As, Bs, As2, acc);

    const int tid = threadIdx.x;
    const int wid = tid >> 5, lane = tid & 31;
    const int lr = lane >> 2, lc = lane & 3;
    const int rw = (wid & 3) * 32, cw = (wid >> 2) * 64;
#pragma unroll
    for (int m = 0; m < 2; m++) {
#pragma unroll
        for (int n = 0; n < 8; n++) {
            int col = cw + n * 8 + lc * 2;
            float b0 = b2[col], bb1 = b2[col + 1];
            int r1 = row0 + rw + m * 16 + lr;
            int r2 = r1 + 8;
            if (r1 < M) {
                float2 ov = {acc[m][n][0] + b0, acc[m][n][1] + bb1};
                *(float2*)&O[(size_t)r1 * ldo + col] = ov;
            }
            if (r2 < M) {
                float2 ov = {acc[m][n][2] + b0, acc[m][n][3] + bb1};
                *(float2*)&O[(size_t)r2 * ldo + col] = ov;
            }
        }
    }
}

// edge MLP + fused GINE scatter
__global__ void __launch_bounds__(256, 2) k_mlp2s(
    const float* __restrict__ A, int lda,
    const __half* __restrict__ W1t, const float* __restrict__ b1,
    const __half* __restrict__ W2t, const float* __restrict__ b2,
    const int* __restrict__ src, const int* __restrict__ dst,
    const float* __restrict__ node, float* __restrict__ agg, int M)
{
    extern __shared__ uint32_t sm[];
    uint32_t* As  = sm;
    uint32_t* Bs  = sm + 128 * LDA2;
    uint32_t* As2 = sm + 2 * 128 * LDA2;
    float acc[2][8][4];
    const int row0 = blockIdx.x * 128;
    mlp2_core(A, lda, W1t, b1, W2t, M, row0, As, Bs, As2, acc);

    const int tid = threadIdx.x;
    const int wid = tid >> 5, lane = tid & 31;
    const int lr = lane >> 2, lc = lane & 3;
    const int rw = (wid & 3) * 32, cw = (wid >> 2) * 64;
#pragma unroll
    for (int m = 0; m < 2; m++) {
#pragma unroll
        for (int n = 0; n < 8; n++) {
            int col = cw + n * 8 + lc * 2;
            float b0 = b2[col], bb1 = b2[col + 1];
#pragma unroll
            for (int half = 0; half < 2; half++) {
                int e = row0 + rw + m * 16 + lr + half * 8;
                if (e < M) {
                    float v0 = acc[m][n][half * 2] + b0;
                    float v1 = acc[m][n][half * 2 + 1] + bb1;
                    int s = src[e], d = dst[e];
                    float2 nv = *(const float2*)&node[(size_t)s * 128 + col];
                    float m0 = fmaxf(nv.x + v0, 0.f);
                    float m1 = fmaxf(nv.y + v1, 0.f);
                    redv2(&agg[(size_t)d * 128 + col], m0, m1);
                }
            }
        }
    }
}

// ---------------- FFMA2 GEMM for embeddings; mode 0: node(+agg init), mode 1: edge(+scatter)
__global__ void __launch_bounds__(256) k_gemm(
    const float* __restrict__ A, int lda,
    const float* __restrict__ W, int ldw,
    const float* __restrict__ bias,
    float* __restrict__ O, int M, int K, int mode,
    const float* __restrict__ eps, float* __restrict__ agg,
    const int* __restrict__ src, const int* __restrict__ dst,
    const float* __restrict__ node)
{
    __shared__ __align__(16) unsigned long long Asd[16][65];
    __shared__ __align__(16) float Ws[16][128];
    const int tid = threadIdx.x;
    const int tx = tid & 31, ty = tid >> 5;
    const int row0 = blockIdx.x * 64;

    unsigned long long acc[8][2];
#pragma unroll
    for (int r = 0; r < 8; r++) { acc[r][0] = 0ULL; acc[r][1] = 0ULL; }

    for (int k0 = 0; k0 < K; k0 += 16) {
#pragma unroll
        for (int i = tid; i < 1024; i += 256) {
            int r = i >> 4, k = i & 15;
            int row = row0 + r, kk = k0 + k;
            float v = (row < M && kk < K) ? A[(size_t)row * lda + kk] : 0.f;
            U64F2 p; p.f.x = v; p.f.y = v;
            Asd[k][r] = p.u;
        }
#pragma unroll
        for (int i = tid; i < 2048; i += 256) {
            int k = i >> 7, j = i & 127;
            int kk = k0 + k;
            Ws[k][j] = (kk < K) ? W[(size_t)kk * ldw + j] : 0.f;
        }
        __syncthreads();
#pragma unroll
        for (int k = 0; k < 16; k++) {
            U128 w; w.v = *(const float4*)&Ws[k][tx << 2];
#pragma unroll
            for (int r = 0; r < 8; r++) {
                unsigned long long a = Asd[k][(ty << 3) + r];
                acc[r][0] = fma2(a, w.u[0], acc[r][0]);
                acc[r][1] = fma2(a, w.u[1], acc[r][1]);
            }
        }
        __syncthreads();
    }
    const int col = tx << 2;
    float4 b4 = *(const float4*)&bias[col];
    float escale = (mode == 0) ? (1.f + eps[0]) : 0.f;
#pragma unroll
    for (int r = 0; r < 8; r++) {
        int row = row0 + (ty << 3) + r;
        if (row < M) {
            U64F2 p0, p1; p0.u = acc[r][0]; p1.u = acc[r][1];
            float v0 = p0.f.x + b4.x, v1 = p0.f.y + b4.y;
            float v2 = p1.f.x + b4.z, v3 = p1.f.y + b4.w;
            float4 ov = {v0, v1, v2, v3};
            *(float4*)&O[(size_t)row * 128 + col] = ov;
            if (mode == 0) {
                float4 av = {escale * v0, escale * v1, escale * v2, escale * v3};
                *(float4*)&agg[(size_t)row * 128 + col] = av;
            } else {
                int s = src[row], d = dst[row];
                float4 nv = *(const float4*)&node[(size_t)s * 128 + col];
                redv4(&agg[(size_t)d * 128 + col],
                      fmaxf(nv.x + v0, 0.f), fmaxf(nv.y + v1, 0.f),
                      fmaxf(nv.z + v2, 0.f), fmaxf(nv.w + v3, 0.f));
            }
        }
    }
}

// ---------------- prep: weight transposes/stacks -> fp16 ----------------
__global__ void k_prep(const float* __restrict__ gin1, const float* __restrict__ gin2,
                       const float* __restrict__ em1, const float* __restrict__ em2,
                       const float* __restrict__ fcw1,
                       const float* __restrict__ gwih, const float* __restrict__ gwhh,
                       const float* __restrict__ gbih, const float* __restrict__ gbhh,
                       const float* __restrict__ lwih, const float* __restrict__ lwhh,
                       const float* __restrict__ lbih, const float* __restrict__ lbhh,
                       __half* __restrict__ tg1, __half* __restrict__ tg2,
                       __half* __restrict__ te1, __half* __restrict__ te2,
                       __half* __restrict__ tf1,
                       __half* __restrict__ tgall, float* __restrict__ tgallb,
                       __half* __restrict__ tgnh,
                       __half* __restrict__ tlw, float* __restrict__ tlb)
{
    int i = blockIdx.x * blockDim.x + threadIdx.x;
    if (i < 131072) {
        int m = i >> 14, j = i & 16383;
        int r = j >> 7, c = j & 127;
        int l = m & 1, which = m >> 1;
        const float* s = (which == 0) ? gin1 : (which == 1) ? gin2 : (which == 2) ? em1 : em2;
        __half* d = (which == 0) ? tg1 : (which == 1) ? tg2 : (which == 2) ? te1 : te2;
        d[(size_t)l * 16384 + c * 128 + r] = __float2half_rn(s[(size_t)l * 16384 + j]);
    } else if (i < 163840) {
        int j = i - 131072;
        int r = j >> 7, c = j & 127;
        tf1[(size_t)c * 256 + r] = __float2half_rn(fcw1[j]);
    } else if (i < 262144) {
        int j = i - 163840;
        int c = j >> 8, k = j & 255;
        float v = (k < 128) ? gwih[c * 128 + k]
                            : ((c < 256) ? gwhh[c * 128 + (k - 128)] : 0.f);
        tgall[j] = __float2half_rn(v);
    } else if (i < 458752) {
        int j = i - 262144;
        int c = j / 384, k = j % 384;
        tlw[j] = __float2half_rn((k < 256) ? lwih[c * 256 + k] : lwhh[c * 128 + (k - 256)]);
    } else if (i < 475136) {
        int j = i - 458752;
        tgnh[j] = __float2half_rn(gwhh[256 * 128 + j]);
    } else if (i < 475520) {
        int j = i - 475136;
        tgallb[j] = (j < 256) ? gbih[j] + gbhh[j] : gbih[j];
    } else if (i < 476032) {
        int j = i - 475520;
        tlb[j] = lbih[j] + lbhh[j];
    }
}

// Set2Set init: gl = broadcast(tlb) (step-0 LSTM GEMM result), hl = cl = 0
__global__ void k_s2sinit(float* __restrict__ gl, const float* __restrict__ tlb,
                          float4* __restrict__ hl, float4* __restrict__ cl, int G)
{
    int i = blockIdx.x * blockDim.x + threadIdx.x;
    if (i < G * 512) gl[i] = tlb[i & 511];
    if (i < G * 32) {
        float4 z = make_float4(0.f, 0.f, 0.f, 0.f);
        hl[i] = z;
        cl[i] = z;
    }
}

__device__ __forceinline__ void lstm1(float i_, float f_, float g_, float o_,
                                      float& c, float& hh) {
    c = sigf(f_) * c + sigf(i_) * tanhf(g_);
    hh = sigf(o_) * tanhf(c);
}

__global__ void k_lstm(const float* __restrict__ gl, float* __restrict__ hl,
                       float* __restrict__ cl, int nw)
{
    int idx = blockIdx.x * blockDim.x + threadIdx.x;
    if (idx >= nw) return;
    int g = idx >> 5, j = (idx & 31) * 4;
    const float* gr = &gl[(size_t)g * 512];
    float4 i_ = *(const float4*)&gr[j];
    float4 f_ = *(const float4*)&gr[j + 128];
    float4 g_ = *(const float4*)&gr[j + 256];
    float4 o_ = *(const float4*)&gr[j + 384];
    float4* cp = (float4*)&cl[(size_t)g * 128 + j];
    float4* hp = (float4*)&hl[(size_t)g * 128 + j];
    float4 c = *cp, hh;
    lstm1(i_.x, f_.x, g_.x, o_.x, c.x, hh.x);
    lstm1(i_.y, f_.y, g_.y, o_.y, c.y, hh.y);
    lstm1(i_.z, f_.z, g_.z, o_.z, c.z, hh.z);
    lstm1(i_.w, f_.w, g_.w, o_.w, c.w, hh.w);
    *cp = c;
    *hp = hh;
}

__global__ void k_set2set(const int* __restrict__ batch, const float* __restrict__ node,
                          const float* __restrict__ hl, float* __restrict__ qs,
                          int N, int G)
{
    int warp = (blockIdx.x * blockDim.x + threadIdx.x) >> 5;
    if (warp >= G) return;
    const int lane = threadIdx.x & 31;
    const int g = warp;

    int lo = 0, hi = N;
    while (lo < hi) { int mid = (lo + hi) >> 1; if (batch[mid] < g) lo = mid + 1; else hi = mid; }
    const int s0 = lo;
    hi = N;
    while (lo < hi) { int mid = (lo + hi) >> 1; if (batch[mid] < g + 1) lo = mid + 1; else hi = mid; }
    const int s1 = lo;

    float4 qv = *(const float4*)&hl[(size_t)g * H + lane * 4];

    float mx = -INFINITY, den = 0.f;
    float4 racc = make_float4(0.f, 0.f, 0.f, 0.f);
    for (int i = s0; i < s1; i++) {
        float4 nv = *(const float4*)&node[(size_t)i * H + lane * 4];
        float d = nv.x * qv.x + nv.y * qv.y + nv.z * qv.z + nv.w * qv.w;
#pragma unroll
        for (int o = 16; o; o >>= 1) d += __shfl_xor_sync(0xffffffffu, d, o);
        float nm = fmaxf(mx, d);
        float sc = expf(mx - nm);
        float ex = expf(d - nm);
        den = den * sc + ex;
        racc.x = racc.x * sc + ex * nv.x;
        racc.y = racc.y * sc + ex * nv.y;
        racc.z = racc.z * sc + ex * nv.z;
        racc.w = racc.w * sc + ex * nv.w;
        mx = nm;
    }
    float inv = 1.f / fmaxf(den, 1e-9f);
    float* qrow = &qs[(size_t)g * 2 * H];
    *(float4*)&qrow[lane * 4] = qv;
    float4 rv = {racc.x * inv, racc.y * inv, racc.z * inv, racc.w * inv};
    *(float4*)&qrow[H + lane * 4] = rv;
}

__global__ void k_fc2(const float* __restrict__ fcin, const float* __restrict__ w2,
                      const float* __restrict__ b2, float* __restrict__ out, int G)
{
    int tid = blockIdx.x * blockDim.x + threadIdx.x;
    int g = tid >> 5;
    if (g >= G) return;
    int lane = tid & 31;
    float s = 0.f;
#pragma unroll
    for (int t = 0; t < 4; t++) {
        int j = lane + t * 32;
        s += fcin[(size_t)g * H + j] * w2[j];
    }
#pragma unroll
    for (int off = 16; off; off >>= 1) s += __shfl_xor_sync(0xffffffffu, s, off);
    if (lane == 0) out[g] = s + b2[0];
}

// ---------------- host launcher ----------------
extern "C" void kernel_launch(void* const* d_in, const int* in_sizes, int n_in,
                              void* d_out, int out_size)
{
    const float* x       = (const float*)d_in[0];
    const float* eattr   = (const float*)d_in[1];
    const int*   eindex  = (const int*)d_in[2];
    const int*   batch   = (const int*)d_in[3];
    const float* node_w  = (const float*)d_in[4];
    const float* node_b  = (const float*)d_in[5];
    const float* edge_w  = (const float*)d_in[6];
    const float* edge_b  = (const float*)d_in[7];
    const float* eps     = (const float*)d_in[8];
    const float* gin_w1  = (const float*)d_in[9];
    const float* gin_b1  = (const float*)d_in[10];
    const float* gin_w2  = (const float*)d_in[11];
    const float* gin_b2  = (const float*)d_in[12];
    const float* em_w1   = (const float*)d_in[13];
    const float* em_b1   = (const float*)d_in[14];
    const float* em_w2   = (const float*)d_in[15];
    const float* em_b2   = (const float*)d_in[16];
    const float* gru_wih = (const float*)d_in[17];
    const float* gru_whh = (const float*)d_in[18];
    const float* gru_bih = (const float*)d_in[19];
    const float* gru_bhh = (const float*)d_in[20];
    const float* lstm_wih= (const float*)d_in[21];
    const float* lstm_whh= (const float*)d_in[22];
    const float* lstm_bih= (const float*)d_in[23];
    const float* lstm_bhh= (const float*)d_in[24];
    const float* fc_w1   = (const float*)d_in[25];
    const float* fc_b1   = (const float*)d_in[26];
    const float* fc_w2   = (const float*)d_in[27];
    const float* fc_b2   = (const float*)d_in[28];

    const int N = in_sizes[0] / 14;
    const int E = in_sizes[1] / 4;
    const int G = out_size;

    float *p_node, *p_edge, *p_agg, *p_m, *p_gates;
    float *p_qs, *p_hl, *p_cl, *p_gl, *p_fc;
    __half *p_tg1, *p_tg2, *p_te1, *p_te2, *p_tf1, *p_tgall, *p_tgnh, *p_tlw;
    float *p_tgallb, *p_tlb;
    cudaGetSymbolAddress((void**)&p_node, g_node);
    cudaGetSymbolAddress((void**)&p_edge, g_edge);
    cudaGetSymbolAddress((void**)&p_agg,  g_agg);
    cudaGetSymbolAddress((void**)&p_m,    g_m);
    cudaGetSymbolAddress((void**)&p_gates, g_gates);
    cudaGetSymbolAddress((void**)&p_qs,   g_qs);
    cudaGetSymbolAddress((void**)&p_hl,   g_hl);
    cudaGetSymbolAddress((void**)&p_cl,   g_cl);
    cudaGetSymbolAddress((void**)&p_gl,   g_gl);
    cudaGetSymbolAddress((void**)&p_fc,   g_fc);
    cudaGetSymbolAddress((void**)&p_tg1,  t_gin1);
    cudaGetSymbolAddress((void**)&p_tg2,  t_gin2);
    cudaGetSymbolAddress((void**)&p_te1,  t_em1);
    cudaGetSymbolAddress((void**)&p_te2,  t_em2);
    cudaGetSymbolAddress((void**)&p_tf1,  t_fc1);
    cudaGetSymbolAddress((void**)&p_tgall, t_gall);
    cudaGetSymbolAddress((void**)&p_tgallb, t_gallb);
    cudaGetSymbolAddress((void**)&p_tgnh, t_gnh);
    cudaGetSymbolAddress((void**)&p_tlw,  t_lw);
    cudaGetSymbolAddress((void**)&p_tlb,  t_lb);

    const int TB = 256;
    const int SMEM_MLP2 = (2 * 128 * LDA2 + 128 * LD2H) * 4;
    cudaFuncSetAttribute(k_mlp2, cudaFuncAttributeMaxDynamicSharedMemorySize, SMEM_MLP2);
    cudaFuncSetAttribute(k_mlp2s, cudaFuncAttributeMaxDynamicSharedMemorySize, SMEM_MLP2);

    k_prep<<<CDIV(476032, TB), TB>>>(gin_w1, gin_w2, em_w1, em_w2, fc_w1,
                                     gru_wih, gru_whh, gru_bih, gru_bhh,
                                     lstm_wih, lstm_whh, lstm_bih, lstm_bhh,
                                     p_tg1, p_tg2, p_te1, p_te2, p_tf1,
                                     p_tgall, p_tgallb, p_tgnh, p_tlw, p_tlb);

    const int* src = eindex;
    const int* dst = eindex + E;

    k_gemm<<<CDIV(N, 64), 256>>>(x, 14, node_w, 128, node_b, p_node, N, 14, 0,
                                 eps, p_agg, nullptr, nullptr, nullptr);
    k_gemm<<<CDIV(E, 64), 256>>>(eattr, 4, edge_w, 128, edge_b, p_edge, E, 4, 1,
                                 eps, p_agg, src, dst, p_node);

    const int NT = CDIV(N, 128), ET = CDIV(E, 128), GT = CDIV(G, 128);

    for (int l = 0; l < 2; l++) {
        k_mlp2<<<NT, 256, SMEM_MLP2>>>(p_agg, 128, p_tg1 + l * 16384, gin_b1 + l * H,
                                       p_tg2 + l * 16384, gin_b2 + l * H, p_m, 128, N);
        // gates: r|z use K=256 ([m|h]); n_i chunk (y==2) uses K=128 (m only)
        k_tmma<<<dim3(NT, 3), 256>>>(p_m, 128, 128, p_node, 128, p_tgall, 256, p_tgallb,
                                     p_gates, 384, N, 256, 128, 0,
                                     nullptr, nullptr, nullptr, 0);
        k_tmma<<<dim3(NT, 1), 256>>>(p_node, 128, 128, p_node, 128, p_tgnh, 128,
                                     gru_bhh + 256, p_node, 128, N, 128, 0, 4,
                                     p_gates, p_agg, eps, (l == 0) ? 1 : -1);
        if (l == 0) {
            k_mlp2s<<<ET, 256, SMEM_MLP2>>>(p_edge, 128, p_te1, em_b1, p_te2, em_b2,
                                            src, dst, p_node, p_agg, E);
        }
    }

    // Set2Set: step-0 LSTM GEMM is just the bias (qs=hl=0) -> broadcast init
    k_s2sinit<<<CDIV(G * 512, TB), TB>>>(p_gl, p_tlb, (float4*)p_hl, (float4*)p_cl, G);
    for (int step = 0; step < 3; step++) {
        if (step > 0)
            k_tmma<<<dim3(GT, 4), 256>>>(p_qs, 256, 256, p_hl, 128, p_tlw, 384, p_tlb,
                                         p_gl, 512, G, 384, 0, 0,
                                         nullptr, nullptr, nullptr, 0);
        k_lstm<<<CDIV(G * 32, TB), TB>>>(p_gl, p_hl, p_cl, G * 32);
        k_set2set<<<CDIV(G * 32, TB), TB>>>(batch, p_node, p_hl, p_qs, N, G);
    }

    // final MLP
    k_tmma<<<dim3(GT, 1), 256>>>(p_qs, 256, 256, p_qs, 256, p_tf1, 256, fc_b1,
                                 p_fc, 128, G, 256, 0, 1,
                                 nullptr, nullptr, nullptr, 0);
    k_fc2<<<CDIV(G * 32, TB), TB>>>(p_fc, fc_w2, fc_b2, (float*)d_out, G);
}

// round 14
// speedup vs baseline: 1.5346x; 1.0969x over previous
#include <cuda_runtime.h>
#include <cuda_fp16.h>
#include <math.h>
#include <stdint.h>

#define H 128
#define NMAX 100000
#define EMAX 200000
#define GMAX 4096

#define CDIV(a,b) (((a)+(b)-1)/(b))

// ---------------- scratch ----------------
__device__ __align__(16) __half g_node[(size_t)NMAX*H];
__device__ __align__(16) float  g_edge[(size_t)EMAX*H];
__device__ __align__(16) float  g_agg [(size_t)NMAX*H];
__device__ __align__(16) __half g_m   [(size_t)NMAX*H];
__device__ __align__(16) __half g_gates[(size_t)NMAX*3*H];   // [N][384]: r | z | n_i
__device__ __align__(16) __half g_qs  [(size_t)GMAX*2*H];
__device__ __align__(16) __half g_hl  [(size_t)GMAX*H];
__device__ __align__(16) float  g_cl  [(size_t)GMAX*H];
__device__ __align__(16) float  g_gl  [(size_t)GMAX*4*H];
__device__ __align__(16) float  g_fc  [(size_t)GMAX*H];
// prepared weights (fp16)
__device__ __align__(16) __half t_gin1[2*H*H];
__device__ __align__(16) __half t_gin2[2*H*H];
__device__ __align__(16) __half t_em1 [2*H*H];
__device__ __align__(16) __half t_em2 [2*H*H];
__device__ __align__(16) __half t_fc1 [H*2*H];       // [128,256]
__device__ __align__(16) __half t_gall[384*256];     // rz (wih|whh) + n_i (wih|0)
__device__ __align__(16) __half t_gnh [H*H];         // gru_whh n-part [128,128]
__device__ __align__(16) __half t_lw  [512*384];     // lwih(256)|lwhh(128)
__device__ __align__(16) float t_gallb[384];
__device__ __align__(16) float t_lb  [512];

// ---------------- helpers ----------------
__device__ __forceinline__ float sigf(float x) { return 1.f / (1.f + expf(-x)); }

__device__ __forceinline__ unsigned long long fma2(unsigned long long a,
                                                   unsigned long long b,
                                                   unsigned long long c) {
    unsigned long long d;
    asm("fma.rn.f32x2 %0, %1, %2, %3;" : "=l"(d) : "l"(a), "l"(b), "l"(c));
    return d;
}
union U64F2 { unsigned long long u; float2 f; };
union U128 { float4 v; unsigned long long u[2]; };

__device__ __forceinline__ uint32_t h2pack(float a, float b) {
    __half2 h = __floats2half2_rn(a, b);
    return *(uint32_t*)&h;
}
__device__ __forceinline__ float2 h2unpack(uint32_t u) {
    return __half22float2(*(__half2*)&u);
}
__device__ __forceinline__ void mma16(float* c, const uint32_t* a, const uint32_t* b) {
    asm volatile(
        "mma.sync.aligned.m16n8k16.row.col.f32.f16.f16.f32 "
        "{%0,%1,%2,%3}, {%4,%5,%6,%7}, {%8,%9}, {%0,%1,%2,%3};"
        : "+f"(c[0]), "+f"(c[1]), "+f"(c[2]), "+f"(c[3])
        : "r"(a[0]), "r"(a[1]), "r"(a[2]), "r"(a[3]), "r"(b[0]), "r"(b[1]));
}
__device__ __forceinline__ void ldm_x4(uint32_t& r0, uint32_t& r1, uint32_t& r2,
                                       uint32_t& r3, uint32_t addr) {
    asm volatile("ldmatrix.sync.aligned.m8n8.x4.shared.b16 {%0,%1,%2,%3}, [%4];"
                 : "=r"(r0), "=r"(r1), "=r"(r2), "=r"(r3) : "r"(addr));
}
__device__ __forceinline__ void redv4(float* p, float a, float b, float c, float d) {
    asm volatile("red.global.add.v4.f32 [%0], {%1, %2, %3, %4};"
                 :: "l"(p), "f"(a), "f"(b), "f"(c), "f"(d) : "memory");
}
__device__ __forceinline__ void redv2(float* p, float a, float b) {
    asm volatile("red.global.add.v2.f32 [%0], {%1, %2};"
                 :: "l"(p), "f"(a), "f"(b) : "memory");
}
__device__ __forceinline__ void cpasync8(uint32_t saddr, const void* g) {
    asm volatile("cp.async.ca.shared.global [%0], [%1], 8;" :: "r"(saddr), "l"(g));
}

#define LDA2 20   // half2 units per row (16 data + 4 pad)
#define LD2H 68   // mid-stage half2 row stride

// one k16 step via ldmatrix: A tile rows [aRow0,+32), B cols [bCol0,+64)
template<int SA, int SB>
__device__ __forceinline__ void mma_k16(uint32_t asA, int aRow0, int aK2,
                                        uint32_t asB, int bCol0, int bK2,
                                        float acc[2][8][4], int lane)
{
    const int g = lane >> 3, r8 = lane & 7;
    uint32_t aAddr = asA + (uint32_t)((((aRow0 + (g & 1) * 8 + r8) * SA) + aK2 + (g >> 1) * 4) * 4);
    uint32_t bAddr = asB + (uint32_t)((((bCol0 + (g >> 1) * 8 + r8) * SB) + bK2 + (g & 1) * 4) * 4);
    uint32_t af[2][4];
#pragma unroll
    for (int m = 0; m < 2; m++)
        ldm_x4(af[m][0], af[m][1], af[m][2], af[m][3], aAddr + m * 16 * SA * 4);
    uint32_t bf[8][2];
#pragma unroll
    for (int n2 = 0; n2 < 4; n2++)
        ldm_x4(bf[2*n2][0], bf[2*n2][1], bf[2*n2+1][0], bf[2*n2+1][1],
               bAddr + n2 * 16 * SB * 4);
#pragma unroll
    for (int m = 0; m < 2; m++)
#pragma unroll
        for (int n = 0; n < 8; n++) mma16(acc[m][n], af[m], bf[n]);
}

// stage fp16 tile [128 rows x 32 k] via cp.async (row clamped to maxr-1)
__device__ __forceinline__ void stage_H(uint32_t* S, const __half* P, int ld,
                                        int row0, int maxr, int k0, int tid)
{
#pragma unroll
    for (int i = 0; i < 4; i++) {
        int r = (tid >> 3) + i * 32;
        int e = tid & 7;
        int row = row0 + r;
        if (row >= maxr) row = maxr - 1;
        uint32_t sa = (uint32_t)__cvta_generic_to_shared(&S[r * LDA2 + e * 2]);
        cpasync8(sa, &P[(size_t)row * ld + k0 + e * 4]);
    }
}

// ---------------- k_tmma: O = act(concat(A,A2)[M,K] @ Bt^T + bias), A fp16 ----------------
// flags: bit0 relu, bit2 GRU-finalize, bit3 fp16 output. Ky2 overrides K for blockIdx.y==2.
__global__ void __launch_bounds__(256, 2) k_tmma(
    const __half* __restrict__ A, int lda, int K1,
    const __half* __restrict__ A2, int lda2,
    const __half* __restrict__ Bt, int ldb,
    const float* __restrict__ bias,
    void* __restrict__ Optr, int ldo,
    int M, int K, int Ky2, int flags,
    const __half* __restrict__ gates, float* __restrict__ aggw,
    const float* __restrict__ eps, int epsidx)
{
    __shared__ uint32_t As[128 * LDA2];
    __shared__ uint32_t Bs[128 * LDA2];
    const uint32_t asA = (uint32_t)__cvta_generic_to_shared(As);
    const uint32_t asB = (uint32_t)__cvta_generic_to_shared(Bs);
    const int tid = threadIdx.x;
    const int wid = tid >> 5, lane = tid & 31;
    const int lr = lane >> 2, lc = lane & 3;
    const int row0 = blockIdx.x * 128;
    const int col0 = blockIdx.y * 128;
    const int rw = (wid & 3) * 32;
    const int cw = (wid >> 2) * 64;

    if (blockIdx.y == 2 && Ky2) K = Ky2;

    float acc[2][8][4];
#pragma unroll
    for (int m = 0; m < 2; m++)
#pragma unroll
        for (int n = 0; n < 8; n++)
#pragma unroll
            for (int c = 0; c < 4; c++) acc[m][n][c] = 0.f;

    for (int k0 = 0; k0 < K; k0 += 32) {
        const __half* srcA = (k0 < K1) ? A : A2;
        int koff = (k0 < K1) ? k0 : k0 - K1;
        int ldx = (k0 < K1) ? lda : lda2;
        stage_H(As, srcA, ldx, row0, M, koff, tid);
        stage_H(Bs, Bt, ldb, col0, 1 << 30, k0, tid);
        asm volatile("cp.async.commit_group;" ::: "memory");
        asm volatile("cp.async.wait_group 0;" ::: "memory");
        __syncthreads();
        mma_k16<LDA2, LDA2>(asA, rw, 0, asB, cw, 0, acc, lane);
        mma_k16<LDA2, LDA2>(asA, rw, 8, asB, cw, 8, acc, lane);
        __syncthreads();
    }

    if (flags & 4) {
        // GRU finalize: gates fp16, h (Optr) fp16, agg fp32
        __half* Oh = (__half*)Optr;
        float escale = (epsidx >= 0) ? (1.f + eps[epsidx]) : 0.f;
#pragma unroll
        for (int m = 0; m < 2; m++) {
#pragma unroll
            for (int n = 0; n < 8; n++) {
                int col = cw + n * 8 + lc * 2;
                float b0 = bias[col], b1 = bias[col + 1];
#pragma unroll
                for (int half = 0; half < 2; half++) {
                    int row = row0 + rw + m * 16 + lr + half * 8;
                    if (row < M) {
                        float nh0 = acc[m][n][half * 2] + b0;
                        float nh1 = acc[m][n][half * 2 + 1] + b1;
                        const __half* gr = &gates[(size_t)row * 384];
                        float2 rr = h2unpack(*(const uint32_t*)&gr[col]);
                        float2 zz = h2unpack(*(const uint32_t*)&gr[col + 128]);
                        float2 ni = h2unpack(*(const uint32_t*)&gr[col + 256]);
                        uint32_t* hp = (uint32_t*)&Oh[(size_t)row * ldo + col];
                        float2 hv = h2unpack(*hp);
                        float r0 = sigf(rr.x), z0 = sigf(zz.x);
                        float nn0 = tanhf(ni.x + r0 * nh0);
                        float h0 = (1.f - z0) * nn0 + z0 * hv.x;
                        float r1 = sigf(rr.y), z1 = sigf(zz.y);
                        float nn1 = tanhf(ni.y + r1 * nh1);
                        float h1 = (1.f - z1) * nn1 + z1 * hv.y;
                        *hp = h2pack(h0, h1);
                        if (epsidx >= 0) {
                            float2 ao = {escale * h0, escale * h1};
                            *(float2*)&aggw[(size_t)row * 128 + col] = ao;
                        }
                    }
                }
            }
        }
        return;
    }

    if (flags & 8) {
        __half* Oh = (__half*)Optr;
#pragma unroll
        for (int m = 0; m < 2; m++) {
#pragma unroll
            for (int n = 0; n < 8; n++) {
                int col = col0 + cw + n * 8 + lc * 2;
                float b0 = bias[col], b1 = bias[col + 1];
#pragma unroll
                for (int half = 0; half < 2; half++) {
                    int row = row0 + rw + m * 16 + lr + half * 8;
                    if (row < M) {
                        float v0 = acc[m][n][half * 2] + b0;
                        float v1 = acc[m][n][half * 2 + 1] + b1;
                        if (flags & 1) { v0 = fmaxf(v0, 0.f); v1 = fmaxf(v1, 0.f); }
                        *(uint32_t*)&Oh[(size_t)row * ldo + col] = h2pack(v0, v1);
                    }
                }
            }
        }
        return;
    }

    float* O = (float*)Optr;
#pragma unroll
    for (int m = 0; m < 2; m++) {
#pragma unroll
        for (int n = 0; n < 8; n++) {
            int col = col0 + cw + n * 8 + lc * 2;
            float b0 = bias[col], b1 = bias[col + 1];
#pragma unroll
            for (int half = 0; half < 2; half++) {
                int row = row0 + rw + m * 16 + lr + half * 8;
                if (row < M) {
                    float v0 = acc[m][n][half * 2] + b0;
                    float v1 = acc[m][n][half * 2 + 1] + b1;
                    if (flags & 1) { v0 = fmaxf(v0, 0.f); v1 = fmaxf(v1, 0.f); }
                    float2 ov = {v0, v1};
                    *(float2*)&O[(size_t)row * ldo + col] = ov;
                }
            }
        }
    }
}

// ---------------- fused 2-layer MLP core (A fp32: agg/edge) ----------------
__device__ __forceinline__ void mlp2_core(
    const float* __restrict__ A, int lda,
    const __half* __restrict__ W1t, const float* __restrict__ b1,
    const __half* __restrict__ W2t, int M, int row0,
    uint32_t* As, uint32_t* Bs, uint32_t* As2, float acc[2][8][4])
{
    const uint32_t asA = (uint32_t)__cvta_generic_to_shared(As);
    const uint32_t asB = (uint32_t)__cvta_generic_to_shared(Bs);
    const uint32_t asA2 = (uint32_t)__cvta_generic_to_shared(As2);
    const int tid = threadIdx.x;
    const int wid = tid >> 5, lane = tid & 31;
    const int lr = lane >> 2, lc = lane & 3;
    const int rw = (wid & 3) * 32;
    const int cw = (wid >> 2) * 64;
    const int r_ = tid >> 3, f4_ = tid & 7;

#pragma unroll
    for (int m = 0; m < 2; m++)
#pragma unroll
        for (int n = 0; n < 8; n++)
#pragma unroll
            for (int c = 0; c < 4; c++) acc[m][n][c] = 0.f;

    float4 aR[4];
#pragma unroll
    for (int i = 0; i < 4; i++) {
        int row = row0 + r_ + i * 32;
        aR[i] = make_float4(0.f, 0.f, 0.f, 0.f);
        if (row < M) aR[i] = *(const float4*)&A[(size_t)row * lda + f4_ * 4];
    }

    // GEMM1
    for (int k0 = 0; k0 < 128; k0 += 32) {
        stage_H(Bs, W1t, 128, 0, 1 << 30, k0, tid);
        asm volatile("cp.async.commit_group;" ::: "memory");
#pragma unroll
        for (int i = 0; i < 4; i++) {
            int r = r_ + i * 32;
            uint32_t* p = &As[r * LDA2 + f4_ * 2];
            p[0] = h2pack(aR[i].x, aR[i].y);
            p[1] = h2pack(aR[i].z, aR[i].w);
        }
        int kn = k0 + 32;
        if (kn < 128) {
#pragma unroll
            for (int i = 0; i < 4; i++) {
                int row = row0 + r_ + i * 32;
                aR[i] = make_float4(0.f, 0.f, 0.f, 0.f);
                if (row < M) aR[i] = *(const float4*)&A[(size_t)row * lda + kn + f4_ * 4];
            }
        }
        asm volatile("cp.async.wait_group 0;" ::: "memory");
        __syncthreads();
        mma_k16<LDA2, LDA2>(asA, rw, 0, asB, cw, 0, acc, lane);
        mma_k16<LDA2, LDA2>(asA, rw, 8, asB, cw, 8, acc, lane);
        __syncthreads();
    }

    // mid epilogue: relu(+b1) -> As2 (half2 per col pair)
#pragma unroll
    for (int m = 0; m < 2; m++) {
#pragma unroll
        for (int n = 0; n < 8; n++) {
            int c2 = (cw >> 1) + n * 4 + lc;
            int col = cw + n * 8 + lc * 2;
            float b0 = b1[col], bb1 = b1[col + 1];
            int r1 = rw + m * 16 + lr, r2 = r1 + 8;
            As2[r1 * LD2H + c2] = h2pack(fmaxf(acc[m][n][0] + b0, 0.f),
                                         fmaxf(acc[m][n][1] + bb1, 0.f));
            As2[r2 * LD2H + c2] = h2pack(fmaxf(acc[m][n][2] + b0, 0.f),
                                         fmaxf(acc[m][n][3] + bb1, 0.f));
            acc[m][n][0] = acc[m][n][1] = acc[m][n][2] = acc[m][n][3] = 0.f;
        }
    }
    __syncthreads();

    // GEMM2: As2 @ W2t
    for (int k0 = 0; k0 < 128; k0 += 32) {
        stage_H(Bs, W2t, 128, 0, 1 << 30, k0, tid);
        asm volatile("cp.async.commit_group;" ::: "memory");
        asm volatile("cp.async.wait_group 0;" ::: "memory");
        __syncthreads();
        const int k2b = k0 >> 1;
        mma_k16<LD2H, LDA2>(asA2, rw, k2b,     asB, cw, 0, acc, lane);
        mma_k16<LD2H, LDA2>(asA2, rw, k2b + 8, asB, cw, 8, acc, lane);
        __syncthreads();
    }
}

// GIN MLP: fp16 output (m)
__global__ void __launch_bounds__(256, 2) k_mlp2(
    const float* __restrict__ A, int lda,
    const __half* __restrict__ W1t, const float* __restrict__ b1,
    const __half* __restrict__ W2t, const float* __restrict__ b2,
    __half* __restrict__ O, int ldo, int M)
{
    extern __shared__ uint32_t sm[];
    uint32_t* As  = sm;
    uint32_t* Bs  = sm + 128 * LDA2;
    uint32_t* As2 = sm + 2 * 128 * LDA2;
    float acc[2][8][4];
    const int row0 = blockIdx.x * 128;
    mlp2_core(A, lda, W1t, b1, W2t, M, row0, As, Bs, As2, acc);

    const int tid = threadIdx.x;
    const int wid = tid >> 5, lane = tid & 31;
    const int lr = lane >> 2, lc = lane & 3;
    const int rw = (wid & 3) * 32, cw = (wid >> 2) * 64;
#pragma unroll
    for (int m = 0; m < 2; m++) {
#pragma unroll
        for (int n = 0; n < 8; n++) {
            int col = cw + n * 8 + lc * 2;
            float b0 = b2[col], bb1 = b2[col + 1];
#pragma unroll
            for (int half = 0; half < 2; half++) {
                int row = row0 + rw + m * 16 + lr + half * 8;
                if (row < M) {
                    *(uint32_t*)&O[(size_t)row * ldo + col] =
                        h2pack(acc[m][n][half * 2] + b0, acc[m][n][half * 2 + 1] + bb1);
                }
            }
        }
    }
}

// edge MLP + fused GINE scatter (node fp16)
__global__ void __launch_bounds__(256, 2) k_mlp2s(
    const float* __restrict__ A, int lda,
    const __half* __restrict__ W1t, const float* __restrict__ b1,
    const __half* __restrict__ W2t, const float* __restrict__ b2,
    const int* __restrict__ src, const int* __restrict__ dst,
    const __half* __restrict__ node, float* __restrict__ agg, int M)
{
    extern __shared__ uint32_t sm[];
    uint32_t* As  = sm;
    uint32_t* Bs  = sm + 128 * LDA2;
    uint32_t* As2 = sm + 2 * 128 * LDA2;
    float acc[2][8][4];
    const int row0 = blockIdx.x * 128;
    mlp2_core(A, lda, W1t, b1, W2t, M, row0, As, Bs, As2, acc);

    const int tid = threadIdx.x;
    const int wid = tid >> 5, lane = tid & 31;
    const int lr = lane >> 2, lc = lane & 3;
    const int rw = (wid & 3) * 32, cw = (wid >> 2) * 64;
#pragma unroll
    for (int m = 0; m < 2; m++) {
#pragma unroll
        for (int n = 0; n < 8; n++) {
            int col = cw + n * 8 + lc * 2;
            float b0 = b2[col], bb1 = b2[col + 1];
#pragma unroll
            for (int half = 0; half < 2; half++) {
                int e = row0 + rw + m * 16 + lr + half * 8;
                if (e < M) {
                    float v0 = acc[m][n][half * 2] + b0;
                    float v1 = acc[m][n][half * 2 + 1] + bb1;
                    int s = src[e], d = dst[e];
                    float2 nv = h2unpack(*(const uint32_t*)&node[(size_t)s * 128 + col]);
                    float m0 = fmaxf(nv.x + v0, 0.f);
                    float m1 = fmaxf(nv.y + v1, 0.f);
                    redv2(&agg[(size_t)d * 128 + col], m0, m1);
                }
            }
        }
    }
}

// ---------------- FFMA2 GEMM for embeddings; mode 0: node fp16 (+agg), mode 1: edge fp32 (+scatter)
__global__ void __launch_bounds__(256) k_gemm(
    const float* __restrict__ A, int lda,
    const float* __restrict__ W, int ldw,
    const float* __restrict__ bias,
    void* __restrict__ Optr, int M, int K, int mode,
    const float* __restrict__ eps, float* __restrict__ agg,
    const int* __restrict__ src, const int* __restrict__ dst,
    const __half* __restrict__ node)
{
    __shared__ __align__(16) unsigned long long Asd[16][65];
    __shared__ __align__(16) float Ws[16][128];
    const int tid = threadIdx.x;
    const int tx = tid & 31, ty = tid >> 5;
    const int row0 = blockIdx.x * 64;

    unsigned long long acc[8][2];
#pragma unroll
    for (int r = 0; r < 8; r++) { acc[r][0] = 0ULL; acc[r][1] = 0ULL; }

    for (int k0 = 0; k0 < K; k0 += 16) {
#pragma unroll
        for (int i = tid; i < 1024; i += 256) {
            int r = i >> 4, k = i & 15;
            int row = row0 + r, kk = k0 + k;
            float v = (row < M && kk < K) ? A[(size_t)row * lda + kk] : 0.f;
            U64F2 p; p.f.x = v; p.f.y = v;
            Asd[k][r] = p.u;
        }
#pragma unroll
        for (int i = tid; i < 2048; i += 256) {
            int k = i >> 7, j = i & 127;
            int kk = k0 + k;
            Ws[k][j] = (kk < K) ? W[(size_t)kk * ldw + j] : 0.f;
        }
        __syncthreads();
#pragma unroll
        for (int k = 0; k < 16; k++) {
            U128 w; w.v = *(const float4*)&Ws[k][tx << 2];
#pragma unroll
            for (int r = 0; r < 8; r++) {
                unsigned long long a = Asd[k][(ty << 3) + r];
                acc[r][0] = fma2(a, w.u[0], acc[r][0]);
                acc[r][1] = fma2(a, w.u[1], acc[r][1]);
            }
        }
        __syncthreads();
    }
    const int col = tx << 2;
    float4 b4 = *(const float4*)&bias[col];
    float escale = (mode == 0) ? (1.f + eps[0]) : 0.f;
#pragma unroll
    for (int r = 0; r < 8; r++) {
        int row = row0 + (ty << 3) + r;
        if (row < M) {
            U64F2 p0, p1; p0.u = acc[r][0]; p1.u = acc[r][1];
            float v0 = p0.f.x + b4.x, v1 = p0.f.y + b4.y;
            float v2 = p1.f.x + b4.z, v3 = p1.f.y + b4.w;
            if (mode == 0) {
                __half* Oh = (__half*)Optr;
                uint2 hv = { h2pack(v0, v1), h2pack(v2, v3) };
                *(uint2*)&Oh[(size_t)row * 128 + col] = hv;
                float4 av = {escale * v0, escale * v1, escale * v2, escale * v3};
                *(float4*)&agg[(size_t)row * 128 + col] = av;
            } else {
                float* O = (float*)Optr;
                float4 ov = {v0, v1, v2, v3};
                *(float4*)&O[(size_t)row * 128 + col] = ov;
                int s = src[row], d = dst[row];
                uint2 nu = *(const uint2*)&node[(size_t)s * 128 + col];
                float2 n01 = h2unpack(nu.x), n23 = h2unpack(nu.y);
                redv4(&agg[(size_t)d * 128 + col],
                      fmaxf(n01.x + v0, 0.f), fmaxf(n01.y + v1, 0.f),
                      fmaxf(n23.x + v2, 0.f), fmaxf(n23.y + v3, 0.f));
            }
        }
    }
}

// ---------------- prep: weight transposes/stacks -> fp16 ----------------
__global__ void k_prep(const float* __restrict__ gin1, const float* __restrict__ gin2,
                       const float* __restrict__ em1, const float* __restrict__ em2,
                       const float* __restrict__ fcw1,
                       const float* __restrict__ gwih, const float* __restrict__ gwhh,
                       const float* __restrict__ gbih, const float* __restrict__ gbhh,
                       const float* __restrict__ lwih, const float* __restrict__ lwhh,
                       const float* __restrict__ lbih, const float* __restrict__ lbhh,
                       __half* __restrict__ tg1, __half* __restrict__ tg2,
                       __half* __restrict__ te1, __half* __restrict__ te2,
                       __half* __restrict__ tf1,
                       __half* __restrict__ tgall, float* __restrict__ tgallb,
                       __half* __restrict__ tgnh,
                       __half* __restrict__ tlw, float* __restrict__ tlb)
{
    int i = blockIdx.x * blockDim.x + threadIdx.x;
    if (i < 131072) {
        int m = i >> 14, j = i & 16383;
        int r = j >> 7, c = j & 127;
        int l = m & 1, which = m >> 1;
        const float* s = (which == 0) ? gin1 : (which == 1) ? gin2 : (which == 2) ? em1 : em2;
        __half* d = (which == 0) ? tg1 : (which == 1) ? tg2 : (which == 2) ? te1 : te2;
        d[(size_t)l * 16384 + c * 128 + r] = __float2half_rn(s[(size_t)l * 16384 + j]);
    } else if (i < 163840) {
        int j = i - 131072;
        int r = j >> 7, c = j & 127;
        tf1[(size_t)c * 256 + r] = __float2half_rn(fcw1[j]);
    } else if (i < 262144) {
        int j = i - 163840;
        int c = j >> 8, k = j & 255;
        float v = (k < 128) ? gwih[c * 128 + k]
                            : ((c < 256) ? gwhh[c * 128 + (k - 128)] : 0.f);
        tgall[j] = __float2half_rn(v);
    } else if (i < 458752) {
        int j = i - 262144;
        int c = j / 384, k = j % 384;
        tlw[j] = __float2half_rn((k < 256) ? lwih[c * 256 + k] : lwhh[c * 128 + (k - 256)]);
    } else if (i < 475136) {
        int j = i - 458752;
        tgnh[j] = __float2half_rn(gwhh[256 * 128 + j]);
    } else if (i < 475520) {
        int j = i - 475136;
        tgallb[j] = (j < 256) ? gbih[j] + gbhh[j] : gbih[j];
    } else if (i < 476032) {
        int j = i - 475520;
        tlb[j] = lbih[j] + lbhh[j];
    }
}

// Set2Set init: gl = broadcast(tlb), hl = cl = 0 (hl fp16)
__global__ void k_s2sinit(float* __restrict__ gl, const float* __restrict__ tlb,
                          uint2* __restrict__ hl, float4* __restrict__ cl, int G)
{
    int i = blockIdx.x * blockDim.x + threadIdx.x;
    if (i < G * 512) gl[i] = tlb[i & 511];
    if (i < G * 32) {
        uint2 hz = {0u, 0u};
        hl[i] = hz;
        cl[i] = make_float4(0.f, 0.f, 0.f, 0.f);
    }
}

__device__ __forceinline__ void lstm1(float i_, float f_, float g_, float o_,
                                      float& c, float& hh) {
    c = sigf(f_) * c + sigf(i_) * tanhf(g_);
    hh = sigf(o_) * tanhf(c);
}

__global__ void k_lstm(const float* __restrict__ gl, __half* __restrict__ hl,
                       float* __restrict__ cl, int nw)
{
    int idx = blockIdx.x * blockDim.x + threadIdx.x;
    if (idx >= nw) return;
    int g = idx >> 5, j = (idx & 31) * 4;
    const float* gr = &gl[(size_t)g * 512];
    float4 i_ = *(const float4*)&gr[j];
    float4 f_ = *(const float4*)&gr[j + 128];
    float4 g_ = *(const float4*)&gr[j + 256];
    float4 o_ = *(const float4*)&gr[j + 384];
    float4* cp = (float4*)&cl[(size_t)g * 128 + j];
    float4 c = *cp, hh;
    lstm1(i_.x, f_.x, g_.x, o_.x, c.x, hh.x);
    lstm1(i_.y, f_.y, g_.y, o_.y, c.y, hh.y);
    lstm1(i_.z, f_.z, g_.z, o_.z, c.z, hh.z);
    lstm1(i_.w, f_.w, g_.w, o_.w, c.w, hh.w);
    *cp = c;
    uint2 ho = { h2pack(hh.x, hh.y), h2pack(hh.z, hh.w) };
    *(uint2*)&hl[(size_t)g * 128 + j] = ho;
}

__global__ void k_set2set(const int* __restrict__ batch, const __half* __restrict__ node,
                          const __half* __restrict__ hl, __half* __restrict__ qs,
                          int N, int G)
{
    int warp = (blockIdx.x * blockDim.x + threadIdx.x) >> 5;
    if (warp >= G) return;
    const int lane = threadIdx.x & 31;
    const int g = warp;

    int lo = 0, hi = N;
    while (lo < hi) { int mid = (lo + hi) >> 1; if (batch[mid] < g) lo = mid + 1; else hi = mid; }
    const int s0 = lo;
    hi = N;
    while (lo < hi) { int mid = (lo + hi) >> 1; if (batch[mid] < g + 1) lo = mid + 1; else hi = mid; }
    const int s1 = lo;

    uint2 qu = *(const uint2*)&hl[(size_t)g * H + lane * 4];
    float2 qa = h2unpack(qu.x), qb = h2unpack(qu.y);
    float4 qv = {qa.x, qa.y, qb.x, qb.y};

    float mx = -INFINITY, den = 0.f;
    float4 racc = make_float4(0.f, 0.f, 0.f, 0.f);
    for (int i = s0; i < s1; i++) {
        uint2 nu = *(const uint2*)&node[(size_t)i * H + lane * 4];
        float2 na = h2unpack(nu.x), nb = h2unpack(nu.y);
        float d = na.x * qv.x + na.y * qv.y + nb.x * qv.z + nb.y * qv.w;
#pragma unroll
        for (int o = 16; o; o >>= 1) d += __shfl_xor_sync(0xffffffffu, d, o);
        float nm = fmaxf(mx, d);
        float sc = expf(mx - nm);
        float ex = expf(d - nm);
        den = den * sc + ex;
        racc.x = racc.x * sc + ex * na.x;
        racc.y = racc.y * sc + ex * na.y;
        racc.z = racc.z * sc + ex * nb.x;
        racc.w = racc.w * sc + ex * nb.y;
        mx = nm;
    }
    float inv = 1.f / fmaxf(den, 1e-9f);
    __half* qrow = &qs[(size_t)g * 2 * H];
    uint2 qo = { h2pack(qv.x, qv.y), h2pack(qv.z, qv.w) };
    *(uint2*)&qrow[lane * 4] = qo;
    uint2 ro = { h2pack(racc.x * inv, racc.y * inv), h2pack(racc.z * inv, racc.w * inv) };
    *(uint2*)&qrow[H + lane * 4] = ro;
}

__global__ void k_fc2(const float* __restrict__ fcin, const float* __restrict__ w2,
                      const float* __restrict__ b2, float* __restrict__ out, int G)
{
    int tid = blockIdx.x * blockDim.x + threadIdx.x;
    int g = tid >> 5;
    if (g >= G) return;
    int lane = tid & 31;
    float s = 0.f;
#pragma unroll
    for (int t = 0; t < 4; t++) {
        int j = lane + t * 32;
        s += fcin[(size_t)g * H + j] * w2[j];
    }
#pragma unroll
    for (int off = 16; off; off >>= 1) s += __shfl_xor_sync(0xffffffffu, s, off);
    if (lane == 0) out[g] = s + b2[0];
}

// ---------------- host launcher ----------------
extern "C" void kernel_launch(void* const* d_in, const int* in_sizes, int n_in,
                              void* d_out, int out_size)
{
    const float* x       = (const float*)d_in[0];
    const float* eattr   = (const float*)d_in[1];
    const int*   eindex  = (const int*)d_in[2];
    const int*   batch   = (const int*)d_in[3];
    const float* node_w  = (const float*)d_in[4];
    const float* node_b  = (const float*)d_in[5];
    const float* edge_w  = (const float*)d_in[6];
    const float* edge_b  = (const float*)d_in[7];
    const float* eps     = (const float*)d_in[8];
    const float* gin_w1  = (const float*)d_in[9];
    const float* gin_b1  = (const float*)d_in[10];
    const float* gin_w2  = (const float*)d_in[11];
    const float* gin_b2  = (const float*)d_in[12];
    const float* em_w1   = (const float*)d_in[13];
    const float* em_b1   = (const float*)d_in[14];
    const float* em_w2   = (const float*)d_in[15];
    const float* em_b2   = (const float*)d_in[16];
    const float* gru_wih = (const float*)d_in[17];
    const float* gru_whh = (const float*)d_in[18];
    const float* gru_bih = (const float*)d_in[19];
    const float* gru_bhh = (const float*)d_in[20];
    const float* lstm_wih= (const float*)d_in[21];
    const float* lstm_whh= (const float*)d_in[22];
    const float* lstm_bih= (const float*)d_in[23];
    const float* lstm_bhh= (const float*)d_in[24];
    const float* fc_w1   = (const float*)d_in[25];
    const float* fc_b1   = (const float*)d_in[26];
    const float* fc_w2   = (const float*)d_in[27];
    const float* fc_b2   = (const float*)d_in[28];

    const int N = in_sizes[0] / 14;
    const int E = in_sizes[1] / 4;
    const int G = out_size;

    __half *p_node, *p_m, *p_gates, *p_qs, *p_hl;
    float *p_edge, *p_agg, *p_cl, *p_gl, *p_fc;
    __half *p_tg1, *p_tg2, *p_te1, *p_te2, *p_tf1, *p_tgall, *p_tgnh, *p_tlw;
    float *p_tgallb, *p_tlb;
    cudaGetSymbolAddress((void**)&p_node, g_node);
    cudaGetSymbolAddress((void**)&p_edge, g_edge);
    cudaGetSymbolAddress((void**)&p_agg,  g_agg);
    cudaGetSymbolAddress((void**)&p_m,    g_m);
    cudaGetSymbolAddress((void**)&p_gates, g_gates);
    cudaGetSymbolAddress((void**)&p_qs,   g_qs);
    cudaGetSymbolAddress((void**)&p_hl,   g_hl);
    cudaGetSymbolAddress((void**)&p_cl,   g_cl);
    cudaGetSymbolAddress((void**)&p_gl,   g_gl);
    cudaGetSymbolAddress((void**)&p_fc,   g_fc);
    cudaGetSymbolAddress((void**)&p_tg1,  t_gin1);
    cudaGetSymbolAddress((void**)&p_tg2,  t_gin2);
    cudaGetSymbolAddress((void**)&p_te1,  t_em1);
    cudaGetSymbolAddress((void**)&p_te2,  t_em2);
    cudaGetSymbolAddress((void**)&p_tf1,  t_fc1);
    cudaGetSymbolAddress((void**)&p_tgall, t_gall);
    cudaGetSymbolAddress((void**)&p_tgallb, t_gallb);
    cudaGetSymbolAddress((void**)&p_tgnh, t_gnh);
    cudaGetSymbolAddress((void**)&p_tlw,  t_lw);
    cudaGetSymbolAddress((void**)&p_tlb,  t_lb);

    const int TB = 256;
    const int SMEM_MLP2 = (2 * 128 * LDA2 + 128 * LD2H) * 4;
    cudaFuncSetAttribute(k_mlp2, cudaFuncAttributeMaxDynamicSharedMemorySize, SMEM_MLP2);
    cudaFuncSetAttribute(k_mlp2s, cudaFuncAttributeMaxDynamicSharedMemorySize, SMEM_MLP2);

    k_prep<<<CDIV(476032, TB), TB>>>(gin_w1, gin_w2, em_w1, em_w2, fc_w1,
                                     gru_wih, gru_whh, gru_bih, gru_bhh,
                                     lstm_wih, lstm_whh, lstm_bih, lstm_bhh,
                                     p_tg1, p_tg2, p_te1, p_te2, p_tf1,
                                     p_tgall, p_tgallb, p_tgnh, p_tlw, p_tlb);

    const int* src = eindex;
    const int* dst = eindex + E;

    k_gemm<<<CDIV(N, 64), 256>>>(x, 14, node_w, 128, node_b, p_node, N, 14, 0,
                                 eps, p_agg, nullptr, nullptr, nullptr);
    k_gemm<<<CDIV(E, 64), 256>>>(eattr, 4, edge_w, 128, edge_b, p_edge, E, 4, 1,
                                 eps, p_agg, src, dst, p_node);

    const int NT = CDIV(N, 128), ET = CDIV(E, 128), GT = CDIV(G, 128);

    for (int l = 0; l < 2; l++) {
        k_mlp2<<<NT, 256, SMEM_MLP2>>>(p_agg, 128, p_tg1 + l * 16384, gin_b1 + l * H,
                                       p_tg2 + l * 16384, gin_b2 + l * H, p_m, 128, N);
        // gates: r|z use K=256 ([m|h]); n_i chunk (y==2) uses K=128 (m only); fp16 out
        k_tmma<<<dim3(NT, 3), 256>>>(p_m, 128, 128, p_node, 128, p_tgall, 256, p_tgallb,
                                     p_gates, 384, N, 256, 128, 8,
                                     nullptr, nullptr, nullptr, 0);
        k_tmma<<<dim3(NT, 1), 256>>>(p_node, 128, 128, p_node, 128, p_tgnh, 128,
                                     gru_bhh + 256, p_node, 128, N, 128, 0, 4,
                                     p_gates, p_agg, eps, (l == 0) ? 1 : -1);
        if (l == 0) {
            k_mlp2s<<<ET, 256, SMEM_MLP2>>>(p_edge, 128, p_te1, em_b1, p_te2, em_b2,
                                            src, dst, p_node, p_agg, E);
        }
    }

    // Set2Set: step-0 LSTM GEMM is just the bias (qs=hl=0) -> broadcast init
    k_s2sinit<<<CDIV(G * 512, TB), TB>>>(p_gl, p_tlb, (uint2*)p_hl, (float4*)p_cl, G);
    for (int step = 0; step < 3; step++) {
        if (step > 0)
            k_tmma<<<dim3(GT, 4), 256>>>(p_qs, 256, 256, p_hl, 128, p_tlw, 384, p_tlb,
                                         p_gl, 512, G, 384, 0, 0,
                                         nullptr, nullptr, nullptr, 0);
        k_lstm<<<CDIV(G * 32, TB), TB>>>(p_gl, p_hl, p_cl, G * 32);
        k_set2set<<<CDIV(G * 32, TB), TB>>>(batch, p_node, p_hl, p_qs, N, G);
    }

    // final MLP
    k_tmma<<<dim3(GT, 1), 256>>>(p_qs, 256, 256, p_qs, 256, p_tf1, 256, fc_b1,
                                 p_fc, 128, G, 256, 0, 1,
                                 nullptr, nullptr, nullptr, 0);
    k_fc2<<<CDIV(G * 32, TB), TB>>>(p_fc, fc_w2, fc_b2, (float*)d_out, G);
}

// round 15
// speedup vs baseline: 1.6009x; 1.0432x over previous
#include <cuda_runtime.h>
#include <cuda_fp16.h>
#include <math.h>
#include <stdint.h>

#define H 128
#define NMAX 100000
#define EMAX 200000
#define GMAX 4096

#define CDIV(a,b) (((a)+(b)-1)/(b))

// ---------------- scratch ----------------
__device__ __align__(16) __half g_node[(size_t)NMAX*H];
__device__ __align__(16) float  g_edge[(size_t)EMAX*H];
__device__ __align__(16) float  g_agg [(size_t)NMAX*H];
__device__ __align__(16) __half g_m   [(size_t)NMAX*H];
__device__ __align__(16) __half g_gates[(size_t)NMAX*3*H];   // [N][384]: r | z | n_i
__device__ __align__(16) __half g_qs  [(size_t)GMAX*2*H];
__device__ __align__(16) __half g_hl  [(size_t)GMAX*H];
__device__ __align__(16) float  g_cl  [(size_t)GMAX*H];
__device__ __align__(16) float  g_gl  [(size_t)GMAX*4*H];
__device__ __align__(16) float  g_fc  [(size_t)GMAX*H];
// prepared weights (fp16)
__device__ __align__(16) __half t_gin1[2*H*H];
__device__ __align__(16) __half t_gin2[2*H*H];
__device__ __align__(16) __half t_em1 [2*H*H];
__device__ __align__(16) __half t_em2 [2*H*H];
__device__ __align__(16) __half t_fc1 [H*2*H];       // [128,256]
__device__ __align__(16) __half t_gall[384*256];     // rz (wih|whh) + n_i (wih|0)
__device__ __align__(16) __half t_gnh [H*H];         // gru_whh n-part [128,128]
__device__ __align__(16) __half t_lw  [512*384];     // lwih(256)|lwhh(128)
__device__ __align__(16) float t_gallb[384];
__device__ __align__(16) float t_lb  [512];

// ---------------- helpers ----------------
__device__ __forceinline__ float sigf(float x) { return 1.f / (1.f + expf(-x)); }

__device__ __forceinline__ unsigned long long fma2(unsigned long long a,
                                                   unsigned long long b,
                                                   unsigned long long c) {
    unsigned long long d;
    asm("fma.rn.f32x2 %0, %1, %2, %3;" : "=l"(d) : "l"(a), "l"(b), "l"(c));
    return d;
}
union U64F2 { unsigned long long u; float2 f; };
union U128 { float4 v; unsigned long long u[2]; };

__device__ __forceinline__ uint32_t h2pack(float a, float b) {
    __half2 h = __floats2half2_rn(a, b);
    return *(uint32_t*)&h;
}
__device__ __forceinline__ float2 h2unpack(uint32_t u) {
    return __half22float2(*(__half2*)&u);
}
__device__ __forceinline__ void mma16(float* c, const uint32_t* a, const uint32_t* b) {
    asm volatile(
        "mma.sync.aligned.m16n8k16.row.col.f32.f16.f16.f32 "
        "{%0,%1,%2,%3}, {%4,%5,%6,%7}, {%8,%9}, {%0,%1,%2,%3};"
        : "+f"(c[0]), "+f"(c[1]), "+f"(c[2]), "+f"(c[3])
        : "r"(a[0]), "r"(a[1]), "r"(a[2]), "r"(a[3]), "r"(b[0]), "r"(b[1]));
}
__device__ __forceinline__ void ldm_x4(uint32_t& r0, uint32_t& r1, uint32_t& r2,
                                       uint32_t& r3, uint32_t addr) {
    asm volatile("ldmatrix.sync.aligned.m8n8.x4.shared.b16 {%0,%1,%2,%3}, [%4];"
                 : "=r"(r0), "=r"(r1), "=r"(r2), "=r"(r3) : "r"(addr));
}
__device__ __forceinline__ void redv4(float* p, float a, float b, float c, float d) {
    asm volatile("red.global.add.v4.f32 [%0], {%1, %2, %3, %4};"
                 :: "l"(p), "f"(a), "f"(b), "f"(c), "f"(d) : "memory");
}
__device__ __forceinline__ void redv2(float* p, float a, float b) {
    asm volatile("red.global.add.v2.f32 [%0], {%1, %2};"
                 :: "l"(p), "f"(a), "f"(b) : "memory");
}
__device__ __forceinline__ void cpasync8(uint32_t saddr, const void* g) {
    asm volatile("cp.async.ca.shared.global [%0], [%1], 8;" :: "r"(saddr), "l"(g));
}
#define CP_COMMIT() asm volatile("cp.async.commit_group;" ::: "memory")
#define CP_WAIT0()  asm volatile("cp.async.wait_group 0;" ::: "memory")
#define CP_WAIT1()  asm volatile("cp.async.wait_group 1;" ::: "memory")

#define LDA2 20   // half2 units per row (16 data + 4 pad)
#define LD2H 68   // mid-stage half2 row stride

// one k16 step via ldmatrix: A tile rows [aRow0,+32), B cols [bCol0,+64)
template<int SA, int SB>
__device__ __forceinline__ void mma_k16(uint32_t asA, int aRow0, int aK2,
                                        uint32_t asB, int bCol0, int bK2,
                                        float acc[2][8][4], int lane)
{
    const int g = lane >> 3, r8 = lane & 7;
    uint32_t aAddr = asA + (uint32_t)((((aRow0 + (g & 1) * 8 + r8) * SA) + aK2 + (g >> 1) * 4) * 4);
    uint32_t bAddr = asB + (uint32_t)((((bCol0 + (g >> 1) * 8 + r8) * SB) + bK2 + (g & 1) * 4) * 4);
    uint32_t af[2][4];
#pragma unroll
    for (int m = 0; m < 2; m++)
        ldm_x4(af[m][0], af[m][1], af[m][2], af[m][3], aAddr + m * 16 * SA * 4);
    uint32_t bf[8][2];
#pragma unroll
    for (int n2 = 0; n2 < 4; n2++)
        ldm_x4(bf[2*n2][0], bf[2*n2][1], bf[2*n2+1][0], bf[2*n2+1][1],
               bAddr + n2 * 16 * SB * 4);
#pragma unroll
    for (int m = 0; m < 2; m++)
#pragma unroll
        for (int n = 0; n < 8; n++) mma16(acc[m][n], af[m], bf[n]);
}

// stage fp16 tile [128 rows x 32 k] via cp.async (row clamped to maxr-1)
__device__ __forceinline__ void stage_H(uint32_t* S, const __half* P, int ld,
                                        int row0, int maxr, int k0, int tid)
{
#pragma unroll
    for (int i = 0; i < 4; i++) {
        int r = (tid >> 3) + i * 32;
        int e = tid & 7;
        int row = row0 + r;
        if (row >= maxr) row = maxr - 1;
        uint32_t sa = (uint32_t)__cvta_generic_to_shared(&S[r * LDA2 + e * 2]);
        cpasync8(sa, &P[(size_t)row * ld + k0 + e * 4]);
    }
}

// ---------------- k_tmma: O = act(concat(A,A2)[M,K] @ Bt^T + bias), A fp16, double-buffered ----
// flags: bit0 relu, bit2 GRU-finalize, bit3 fp16 output. Ky2 overrides K for blockIdx.y==2.
__global__ void __launch_bounds__(256, 2) k_tmma(
    const __half* __restrict__ A, int lda, int K1,
    const __half* __restrict__ A2, int lda2,
    const __half* __restrict__ Bt, int ldb,
    const float* __restrict__ bias,
    void* __restrict__ Optr, int ldo,
    int M, int K, int Ky2, int flags,
    const __half* __restrict__ gates, float* __restrict__ aggw,
    const float* __restrict__ eps, int epsidx)
{
    __shared__ uint32_t AsB[2][128 * LDA2];
    __shared__ uint32_t BsB[2][128 * LDA2];
    const int tid = threadIdx.x;
    const int wid = tid >> 5, lane = tid & 31;
    const int lr = lane >> 2, lc = lane & 3;
    const int row0 = blockIdx.x * 128;
    const int col0 = blockIdx.y * 128;
    const int rw = (wid & 3) * 32;
    const int cw = (wid >> 2) * 64;

    if (blockIdx.y == 2 && Ky2) K = Ky2;

    float acc[2][8][4];
#pragma unroll
    for (int m = 0; m < 2; m++)
#pragma unroll
        for (int n = 0; n < 8; n++)
#pragma unroll
            for (int c = 0; c < 4; c++) acc[m][n][c] = 0.f;

    const int nb = K >> 5;
    // prologue
    {
        const __half* srcA = (0 < K1) ? A : A2;
        int ldx = (0 < K1) ? lda : lda2;
        stage_H(AsB[0], srcA, ldx, row0, M, 0, tid);
        stage_H(BsB[0], Bt, ldb, col0, 1 << 30, 0, tid);
        CP_COMMIT();
    }
    for (int kb = 0; kb < nb; kb++) {
        int kn = (kb + 1) * 32;
        if (kn < K) {
            const __half* srcA = (kn < K1) ? A : A2;
            int koff = (kn < K1) ? kn : kn - K1;
            int ldx = (kn < K1) ? lda : lda2;
            stage_H(AsB[(kb + 1) & 1], srcA, ldx, row0, M, koff, tid);
            stage_H(BsB[(kb + 1) & 1], Bt, ldb, col0, 1 << 30, kn, tid);
            CP_COMMIT();
            CP_WAIT1();
        } else {
            CP_WAIT0();
        }
        __syncthreads();
        const uint32_t asA = (uint32_t)__cvta_generic_to_shared(AsB[kb & 1]);
        const uint32_t asB = (uint32_t)__cvta_generic_to_shared(BsB[kb & 1]);
        mma_k16<LDA2, LDA2>(asA, rw, 0, asB, cw, 0, acc, lane);
        mma_k16<LDA2, LDA2>(asA, rw, 8, asB, cw, 8, acc, lane);
        __syncthreads();
    }

    if (flags & 4) {
        // GRU finalize: gates fp16, h (Optr) fp16, agg fp32
        __half* Oh = (__half*)Optr;
        float escale = (epsidx >= 0) ? (1.f + eps[epsidx]) : 0.f;
#pragma unroll
        for (int m = 0; m < 2; m++) {
#pragma unroll
            for (int n = 0; n < 8; n++) {
                int col = cw + n * 8 + lc * 2;
                float b0 = bias[col], b1 = bias[col + 1];
#pragma unroll
                for (int half = 0; half < 2; half++) {
                    int row = row0 + rw + m * 16 + lr + half * 8;
                    if (row < M) {
                        float nh0 = acc[m][n][half * 2] + b0;
                        float nh1 = acc[m][n][half * 2 + 1] + b1;
                        const __half* gr = &gates[(size_t)row * 384];
                        float2 rr = h2unpack(*(const uint32_t*)&gr[col]);
                        float2 zz = h2unpack(*(const uint32_t*)&gr[col + 128]);
                        float2 ni = h2unpack(*(const uint32_t*)&gr[col + 256]);
                        uint32_t* hp = (uint32_t*)&Oh[(size_t)row * ldo + col];
                        float2 hv = h2unpack(*hp);
                        float r0 = sigf(rr.x), z0 = sigf(zz.x);
                        float nn0 = tanhf(ni.x + r0 * nh0);
                        float h0 = (1.f - z0) * nn0 + z0 * hv.x;
                        float r1 = sigf(rr.y), z1 = sigf(zz.y);
                        float nn1 = tanhf(ni.y + r1 * nh1);
                        float h1 = (1.f - z1) * nn1 + z1 * hv.y;
                        *hp = h2pack(h0, h1);
                        if (epsidx >= 0) {
                            float2 ao = {escale * h0, escale * h1};
                            *(float2*)&aggw[(size_t)row * 128 + col] = ao;
                        }
                    }
                }
            }
        }
        return;
    }

    if (flags & 8) {
        __half* Oh = (__half*)Optr;
#pragma unroll
        for (int m = 0; m < 2; m++) {
#pragma unroll
            for (int n = 0; n < 8; n++) {
                int col = col0 + cw + n * 8 + lc * 2;
                float b0 = bias[col], b1 = bias[col + 1];
#pragma unroll
                for (int half = 0; half < 2; half++) {
                    int row = row0 + rw + m * 16 + lr + half * 8;
                    if (row < M) {
                        float v0 = acc[m][n][half * 2] + b0;
                        float v1 = acc[m][n][half * 2 + 1] + b1;
                        if (flags & 1) { v0 = fmaxf(v0, 0.f); v1 = fmaxf(v1, 0.f); }
                        *(uint32_t*)&Oh[(size_t)row * ldo + col] = h2pack(v0, v1);
                    }
                }
            }
        }
        return;
    }

    float* O = (float*)Optr;
#pragma unroll
    for (int m = 0; m < 2; m++) {
#pragma unroll
        for (int n = 0; n < 8; n++) {
            int col = col0 + cw + n * 8 + lc * 2;
            float b0 = bias[col], b1 = bias[col + 1];
#pragma unroll
            for (int half = 0; half < 2; half++) {
                int row = row0 + rw + m * 16 + lr + half * 8;
                if (row < M) {
                    float v0 = acc[m][n][half * 2] + b0;
                    float v1 = acc[m][n][half * 2 + 1] + b1;
                    if (flags & 1) { v0 = fmaxf(v0, 0.f); v1 = fmaxf(v1, 0.f); }
                    float2 ov = {v0, v1};
                    *(float2*)&O[(size_t)row * ldo + col] = ov;
                }
            }
        }
    }
}

// ---------------- fused 2-layer MLP core (A fp32; B double-buffered) ----------------
__device__ __forceinline__ void mlp2_core(
    const float* __restrict__ A, int lda,
    const __half* __restrict__ W1t, const float* __restrict__ b1,
    const __half* __restrict__ W2t, int M, int row0,
    uint32_t* As, uint32_t* Bs0, uint32_t* Bs1, uint32_t* As2, float acc[2][8][4])
{
    const uint32_t asA = (uint32_t)__cvta_generic_to_shared(As);
    const uint32_t asA2 = (uint32_t)__cvta_generic_to_shared(As2);
    uint32_t* BsB[2] = { Bs0, Bs1 };
    const int tid = threadIdx.x;
    const int wid = tid >> 5, lane = tid & 31;
    const int lr = lane >> 2, lc = lane & 3;
    const int rw = (wid & 3) * 32;
    const int cw = (wid >> 2) * 64;
    const int r_ = tid >> 3, f4_ = tid & 7;

#pragma unroll
    for (int m = 0; m < 2; m++)
#pragma unroll
        for (int n = 0; n < 8; n++)
#pragma unroll
            for (int c = 0; c < 4; c++) acc[m][n][c] = 0.f;

    float4 aR[4];
#pragma unroll
    for (int i = 0; i < 4; i++) {
        int row = row0 + r_ + i * 32;
        aR[i] = make_float4(0.f, 0.f, 0.f, 0.f);
        if (row < M) aR[i] = *(const float4*)&A[(size_t)row * lda + f4_ * 4];
    }
    stage_H(BsB[0], W1t, 128, 0, 1 << 30, 0, tid);
    CP_COMMIT();

    // GEMM1 (A reg-prefetch, B double-buffered)
#pragma unroll
    for (int kb = 0; kb < 4; kb++) {
#pragma unroll
        for (int i = 0; i < 4; i++) {
            int r = r_ + i * 32;
            uint32_t* p = &As[r * LDA2 + f4_ * 2];
            p[0] = h2pack(aR[i].x, aR[i].y);
            p[1] = h2pack(aR[i].z, aR[i].w);
        }
        if (kb + 1 < 4) {
            stage_H(BsB[(kb + 1) & 1], W1t, 128, 0, 1 << 30, (kb + 1) * 32, tid);
            CP_COMMIT();
#pragma unroll
            for (int i = 0; i < 4; i++) {
                int row = row0 + r_ + i * 32;
                aR[i] = make_float4(0.f, 0.f, 0.f, 0.f);
                if (row < M) aR[i] = *(const float4*)&A[(size_t)row * lda + (kb + 1) * 32 + f4_ * 4];
            }
            CP_WAIT1();
        } else {
            CP_WAIT0();
        }
        __syncthreads();
        const uint32_t asB = (uint32_t)__cvta_generic_to_shared(BsB[kb & 1]);
        mma_k16<LDA2, LDA2>(asA, rw, 0, asB, cw, 0, acc, lane);
        mma_k16<LDA2, LDA2>(asA, rw, 8, asB, cw, 8, acc, lane);
        __syncthreads();
    }

    // mid epilogue: relu(+b1) -> As2 (half2 per col pair)
#pragma unroll
    for (int m = 0; m < 2; m++) {
#pragma unroll
        for (int n = 0; n < 8; n++) {
            int c2 = (cw >> 1) + n * 4 + lc;
            int col = cw + n * 8 + lc * 2;
            float b0 = b1[col], bb1 = b1[col + 1];
            int r1 = rw + m * 16 + lr, r2 = r1 + 8;
            As2[r1 * LD2H + c2] = h2pack(fmaxf(acc[m][n][0] + b0, 0.f),
                                         fmaxf(acc[m][n][1] + bb1, 0.f));
            As2[r2 * LD2H + c2] = h2pack(fmaxf(acc[m][n][2] + b0, 0.f),
                                         fmaxf(acc[m][n][3] + bb1, 0.f));
            acc[m][n][0] = acc[m][n][1] = acc[m][n][2] = acc[m][n][3] = 0.f;
        }
    }
    stage_H(BsB[0], W2t, 128, 0, 1 << 30, 0, tid);
    CP_COMMIT();
    __syncthreads();

    // GEMM2: As2 @ W2t (B double-buffered)
#pragma unroll
    for (int kb = 0; kb < 4; kb++) {
        if (kb + 1 < 4) {
            stage_H(BsB[(kb + 1) & 1], W2t, 128, 0, 1 << 30, (kb + 1) * 32, tid);
            CP_COMMIT();
            CP_WAIT1();
        } else {
            CP_WAIT0();
        }
        __syncthreads();
        const int k2b = kb * 16;
        const uint32_t asB = (uint32_t)__cvta_generic_to_shared(BsB[kb & 1]);
        mma_k16<LD2H, LDA2>(asA2, rw, k2b,     asB, cw, 0, acc, lane);
        mma_k16<LD2H, LDA2>(asA2, rw, k2b + 8, asB, cw, 8, acc, lane);
        __syncthreads();
    }
}

// GIN MLP: fp16 output (m)
__global__ void __launch_bounds__(256, 2) k_mlp2(
    const float* __restrict__ A, int lda,
    const __half* __restrict__ W1t, const float* __restrict__ b1,
    const __half* __restrict__ W2t, const float* __restrict__ b2,
    __half* __restrict__ O, int ldo, int M)
{
    extern __shared__ uint32_t sm[];
    uint32_t* As  = sm;
    uint32_t* Bs0 = sm + 128 * LDA2;
    uint32_t* Bs1 = sm + 2 * 128 * LDA2;
    uint32_t* As2 = sm + 3 * 128 * LDA2;
    float acc[2][8][4];
    const int row0 = blockIdx.x * 128;
    mlp2_core(A, lda, W1t, b1, W2t, M, row0, As, Bs0, Bs1, As2, acc);

    const int tid = threadIdx.x;
    const int wid = tid >> 5, lane = tid & 31;
    const int lr = lane >> 2, lc = lane & 3;
    const int rw = (wid & 3) * 32, cw = (wid >> 2) * 64;
#pragma unroll
    for (int m = 0; m < 2; m++) {
#pragma unroll
        for (int n = 0; n < 8; n++) {
            int col = cw + n * 8 + lc * 2;
            float b0 = b2[col], bb1 = b2[col + 1];
#pragma unroll
            for (int half = 0; half < 2; half++) {
                int row = row0 + rw + m * 16 + lr + half * 8;
                if (row < M) {
                    *(uint32_t*)&O[(size_t)row * ldo + col] =
                        h2pack(acc[m][n][half * 2] + b0, acc[m][n][half * 2 + 1] + bb1);
                }
            }
        }
    }
}

// edge MLP + fused GINE scatter (node fp16)
__global__ void __launch_bounds__(256, 2) k_mlp2s(
    const float* __restrict__ A, int lda,
    const __half* __restrict__ W1t, const float* __restrict__ b1,
    const __half* __restrict__ W2t, const float* __restrict__ b2,
    const int* __restrict__ src, const int* __restrict__ dst,
    const __half* __restrict__ node, float* __restrict__ agg, int M)
{
    extern __shared__ uint32_t sm[];
    uint32_t* As  = sm;
    uint32_t* Bs0 = sm + 128 * LDA2;
    uint32_t* Bs1 = sm + 2 * 128 * LDA2;
    uint32_t* As2 = sm + 3 * 128 * LDA2;
    float acc[2][8][4];
    const int row0 = blockIdx.x * 128;
    mlp2_core(A, lda, W1t, b1, W2t, M, row0, As, Bs0, Bs1, As2, acc);

    const int tid = threadIdx.x;
    const int wid = tid >> 5, lane = tid & 31;
    const int lr = lane >> 2, lc = lane & 3;
    const int rw = (wid & 3) * 32, cw = (wid >> 2) * 64;
#pragma unroll
    for (int m = 0; m < 2; m++) {
#pragma unroll
        for (int n = 0; n < 8; n++) {
            int col = cw + n * 8 + lc * 2;
            float b0 = b2[col], bb1 = b2[col + 1];
#pragma unroll
            for (int half = 0; half < 2; half++) {
                int e = row0 + rw + m * 16 + lr + half * 8;
                if (e < M) {
                    float v0 = acc[m][n][half * 2] + b0;
                    float v1 = acc[m][n][half * 2 + 1] + bb1;
                    int s = src[e], d = dst[e];
                    float2 nv = h2unpack(*(const uint32_t*)&node[(size_t)s * 128 + col]);
                    float m0 = fmaxf(nv.x + v0, 0.f);
                    float m1 = fmaxf(nv.y + v1, 0.f);
                    redv2(&agg[(size_t)d * 128 + col], m0, m1);
                }
            }
        }
    }
}

// ---------------- FFMA2 GEMM for embeddings; mode 0: node fp16 (+agg), mode 1: edge fp32 (+scatter)
__global__ void __launch_bounds__(256) k_gemm(
    const float* __restrict__ A, int lda,
    const float* __restrict__ W, int ldw,
    const float* __restrict__ bias,
    void* __restrict__ Optr, int M, int K, int mode,
    const float* __restrict__ eps, float* __restrict__ agg,
    const int* __restrict__ src, const int* __restrict__ dst,
    const __half* __restrict__ node)
{
    __shared__ __align__(16) unsigned long long Asd[16][65];
    __shared__ __align__(16) float Ws[16][128];
    const int tid = threadIdx.x;
    const int tx = tid & 31, ty = tid >> 5;
    const int row0 = blockIdx.x * 64;

    unsigned long long acc[8][2];
#pragma unroll
    for (int r = 0; r < 8; r++) { acc[r][0] = 0ULL; acc[r][1] = 0ULL; }

    for (int k0 = 0; k0 < K; k0 += 16) {
#pragma unroll
        for (int i = tid; i < 1024; i += 256) {
            int r = i >> 4, k = i & 15;
            int row = row0 + r, kk = k0 + k;
            float v = (row < M && kk < K) ? A[(size_t)row * lda + kk] : 0.f;
            U64F2 p; p.f.x = v; p.f.y = v;
            Asd[k][r] = p.u;
        }
#pragma unroll
        for (int i = tid; i < 2048; i += 256) {
            int k = i >> 7, j = i & 127;
            int kk = k0 + k;
            Ws[k][j] = (kk < K) ? W[(size_t)kk * ldw + j] : 0.f;
        }
        __syncthreads();
#pragma unroll
        for (int k = 0; k < 16; k++) {
            U128 w; w.v = *(const float4*)&Ws[k][tx << 2];
#pragma unroll
            for (int r = 0; r < 8; r++) {
                unsigned long long a = Asd[k][(ty << 3) + r];
                acc[r][0] = fma2(a, w.u[0], acc[r][0]);
                acc[r][1] = fma2(a, w.u[1], acc[r][1]);
            }
        }
        __syncthreads();
    }
    const int col = tx << 2;
    float4 b4 = *(const float4*)&bias[col];
    float escale = (mode == 0) ? (1.f + eps[0]) : 0.f;
#pragma unroll
    for (int r = 0; r < 8; r++) {
        int row = row0 + (ty << 3) + r;
        if (row < M) {
            U64F2 p0, p1; p0.u = acc[r][0]; p1.u = acc[r][1];
            float v0 = p0.f.x + b4.x, v1 = p0.f.y + b4.y;
            float v2 = p1.f.x + b4.z, v3 = p1.f.y + b4.w;
            if (mode == 0) {
                __half* Oh = (__half*)Optr;
                uint2 hv = { h2pack(v0, v1), h2pack(v2, v3) };
                *(uint2*)&Oh[(size_t)row * 128 + col] = hv;
                float4 av = {escale * v0, escale * v1, escale * v2, escale * v3};
                *(float4*)&agg[(size_t)row * 128 + col] = av;
            } else {
                float* O = (float*)Optr;
                float4 ov = {v0, v1, v2, v3};
                *(float4*)&O[(size_t)row * 128 + col] = ov;
                int s = src[row], d = dst[row];
                uint2 nu = *(const uint2*)&node[(size_t)s * 128 + col];
                float2 n01 = h2unpack(nu.x), n23 = h2unpack(nu.y);
                redv4(&agg[(size_t)d * 128 + col],
                      fmaxf(n01.x + v0, 0.f), fmaxf(n01.y + v1, 0.f),
                      fmaxf(n23.x + v2, 0.f), fmaxf(n23.y + v3, 0.f));
            }
        }
    }
}

// ---------------- prep: weight transposes/stacks -> fp16 ----------------
__global__ void k_prep(const float* __restrict__ gin1, const float* __restrict__ gin2,
                       const float* __restrict__ em1, const float* __restrict__ em2,
                       const float* __restrict__ fcw1,
                       const float* __restrict__ gwih, const float* __restrict__ gwhh,
                       const float* __restrict__ gbih, const float* __restrict__ gbhh,
                       const float* __restrict__ lwih, const float* __restrict__ lwhh,
                       const float* __restrict__ lbih, const float* __restrict__ lbhh,
                       __half* __restrict__ tg1, __half* __restrict__ tg2,
                       __half* __restrict__ te1, __half* __restrict__ te2,
                       __half* __restrict__ tf1,
                       __half* __restrict__ tgall, float* __restrict__ tgallb,
                       __half* __restrict__ tgnh,
                       __half* __restrict__ tlw, float* __restrict__ tlb)
{
    int i = blockIdx.x * blockDim.x + threadIdx.x;
    if (i < 131072) {
        int m = i >> 14, j = i & 16383;
        int r = j >> 7, c = j & 127;
        int l = m & 1, which = m >> 1;
        const float* s = (which == 0) ? gin1 : (which == 1) ? gin2 : (which == 2) ? em1 : em2;
        __half* d = (which == 0) ? tg1 : (which == 1) ? tg2 : (which == 2) ? te1 : te2;
        d[(size_t)l * 16384 + c * 128 + r] = __float2half_rn(s[(size_t)l * 16384 + j]);
    } else if (i < 163840) {
        int j = i - 131072;
        int r = j >> 7, c = j & 127;
        tf1[(size_t)c * 256 + r] = __float2half_rn(fcw1[j]);
    } else if (i < 262144) {
        int j = i - 163840;
        int c = j >> 8, k = j & 255;
        float v = (k < 128) ? gwih[c * 128 + k]
                            : ((c < 256) ? gwhh[c * 128 + (k - 128)] : 0.f);
        tgall[j] = __float2half_rn(v);
    } else if (i < 458752) {
        int j = i - 262144;
        int c = j / 384, k = j % 384;
        tlw[j] = __float2half_rn((k < 256) ? lwih[c * 256 + k] : lwhh[c * 128 + (k - 256)]);
    } else if (i < 475136) {
        int j = i - 458752;
        tgnh[j] = __float2half_rn(gwhh[256 * 128 + j]);
    } else if (i < 475520) {
        int j = i - 475136;
        tgallb[j] = (j < 256) ? gbih[j] + gbhh[j] : gbih[j];
    } else if (i < 476032) {
        int j = i - 475520;
        tlb[j] = lbih[j] + lbhh[j];
    }
}

// Set2Set init: gl = broadcast(tlb), hl = cl = 0 (hl fp16)
__global__ void k_s2sinit(float* __restrict__ gl, const float* __restrict__ tlb,
                          uint2* __restrict__ hl, float4* __restrict__ cl, int G)
{
    int i = blockIdx.x * blockDim.x + threadIdx.x;
    if (i < G * 512) gl[i] = tlb[i & 511];
    if (i < G * 32) {
        uint2 hz = {0u, 0u};
        hl[i] = hz;
        cl[i] = make_float4(0.f, 0.f, 0.f, 0.f);
    }
}

__device__ __forceinline__ void lstm1(float i_, float f_, float g_, float o_,
                                      float& c, float& hh) {
    c = sigf(f_) * c + sigf(i_) * tanhf(g_);
    hh = sigf(o_) * tanhf(c);
}

__global__ void k_lstm(const float* __restrict__ gl, __half* __restrict__ hl,
                       float* __restrict__ cl, int nw)
{
    int idx = blockIdx.x * blockDim.x + threadIdx.x;
    if (idx >= nw) return;
    int g = idx >> 5, j = (idx & 31) * 4;
    const float* gr = &gl[(size_t)g * 512];
    float4 i_ = *(const float4*)&gr[j];
    float4 f_ = *(const float4*)&gr[j + 128];
    float4 g_ = *(const float4*)&gr[j + 256];
    float4 o_ = *(const float4*)&gr[j + 384];
    float4* cp = (float4*)&cl[(size_t)g * 128 + j];
    float4 c = *cp, hh;
    lstm1(i_.x, f_.x, g_.x, o_.x, c.x, hh.x);
    lstm1(i_.y, f_.y, g_.y, o_.y, c.y, hh.y);
    lstm1(i_.z, f_.z, g_.z, o_.z, c.z, hh.z);
    lstm1(i_.w, f_.w, g_.w, o_.w, c.w, hh.w);
    *cp = c;
    uint2 ho = { h2pack(hh.x, hh.y), h2pack(hh.z, hh.w) };
    *(uint2*)&hl[(size_t)g * 128 + j] = ho;
}

__global__ void k_set2set(const int* __restrict__ batch, const __half* __restrict__ node,
                          const __half* __restrict__ hl, __half* __restrict__ qs,
                          int N, int G)
{
    int warp = (blockIdx.x * blockDim.x + threadIdx.x) >> 5;
    if (warp >= G) return;
    const int lane = threadIdx.x & 31;
    const int g = warp;

    int lo = 0, hi = N;
    while (lo < hi) { int mid = (lo + hi) >> 1; if (batch[mid] < g) lo = mid + 1; else hi = mid; }
    const int s0 = lo;
    hi = N;
    while (lo < hi) { int mid = (lo + hi) >> 1; if (batch[mid] < g + 1) lo = mid + 1; else hi = mid; }
    const int s1 = lo;

    uint2 qu = *(const uint2*)&hl[(size_t)g * H + lane * 4];
    float2 qa = h2unpack(qu.x), qb = h2unpack(qu.y);
    float4 qv = {qa.x, qa.y, qb.x, qb.y};

    float mx = -INFINITY, den = 0.f;
    float4 racc = make_float4(0.f, 0.f, 0.f, 0.f);
    for (int i = s0; i < s1; i++) {
        uint2 nu = *(const uint2*)&node[(size_t)i * H + lane * 4];
        float2 na = h2unpack(nu.x), nb = h2unpack(nu.y);
        float d = na.x * qv.x + na.y * qv.y + nb.x * qv.z + nb.y * qv.w;
#pragma unroll
        for (int o = 16; o; o >>= 1) d += __shfl_xor_sync(0xffffffffu, d, o);
        float nm = fmaxf(mx, d);
        float sc = expf(mx - nm);
        float ex = expf(d - nm);
        den = den * sc + ex;
        racc.x = racc.x * sc + ex * na.x;
        racc.y = racc.y * sc + ex * na.y;
        racc.z = racc.z * sc + ex * nb.x;
        racc.w = racc.w * sc + ex * nb.y;
        mx = nm;
    }
    float inv = 1.f / fmaxf(den, 1e-9f);
    __half* qrow = &qs[(size_t)g * 2 * H];
    uint2 qo = { h2pack(qv.x, qv.y), h2pack(qv.z, qv.w) };
    *(uint2*)&qrow[lane * 4] = qo;
    uint2 ro = { h2pack(racc.x * inv, racc.y * inv), h2pack(racc.z * inv, racc.w * inv) };
    *(uint2*)&qrow[H + lane * 4] = ro;
}

__global__ void k_fc2(const float* __restrict__ fcin, const float* __restrict__ w2,
                      const float* __restrict__ b2, float* __restrict__ out, int G)
{
    int tid = blockIdx.x * blockDim.x + threadIdx.x;
    int g = tid >> 5;
    if (g >= G) return;
    int lane = tid & 31;
    float s = 0.f;
#pragma unroll
    for (int t = 0; t < 4; t++) {
        int j = lane + t * 32;
        s += fcin[(size_t)g * H + j] * w2[j];
    }
#pragma unroll
    for (int off = 16; off; off >>= 1) s += __shfl_xor_sync(0xffffffffu, s, off);
    if (lane == 0) out[g] = s + b2[0];
}

// ---------------- host launcher ----------------
extern "C" void kernel_launch(void* const* d_in, const int* in_sizes, int n_in,
                              void* d_out, int out_size)
{
    const float* x       = (const float*)d_in[0];
    const float* eattr   = (const float*)d_in[1];
    const int*   eindex  = (const int*)d_in[2];
    const int*   batch   = (const int*)d_in[3];
    const float* node_w  = (const float*)d_in[4];
    const float* node_b  = (const float*)d_in[5];
    const float* edge_w  = (const float*)d_in[6];
    const float* edge_b  = (const float*)d_in[7];
    const float* eps     = (const float*)d_in[8];
    const float* gin_w1  = (const float*)d_in[9];
    const float* gin_b1  = (const float*)d_in[10];
    const float* gin_w2  = (const float*)d_in[11];
    const float* gin_b2  = (const float*)d_in[12];
    const float* em_w1   = (const float*)d_in[13];
    const float* em_b1   = (const float*)d_in[14];
    const float* em_w2   = (const float*)d_in[15];
    const float* em_b2   = (const float*)d_in[16];
    const float* gru_wih = (const float*)d_in[17];
    const float* gru_whh = (const float*)d_in[18];
    const float* gru_bih = (const float*)d_in[19];
    const float* gru_bhh = (const float*)d_in[20];
    const float* lstm_wih= (const float*)d_in[21];
    const float* lstm_whh= (const float*)d_in[22];
    const float* lstm_bih= (const float*)d_in[23];
    const float* lstm_bhh= (const float*)d_in[24];
    const float* fc_w1   = (const float*)d_in[25];
    const float* fc_b1   = (const float*)d_in[26];
    const float* fc_w2   = (const float*)d_in[27];
    const float* fc_b2   = (const float*)d_in[28];

    const int N = in_sizes[0] / 14;
    const int E = in_sizes[1] / 4;
    const int G = out_size;

    __half *p_node, *p_m, *p_gates, *p_qs, *p_hl;
    float *p_edge, *p_agg, *p_cl, *p_gl, *p_fc;
    __half *p_tg1, *p_tg2, *p_te1, *p_te2, *p_tf1, *p_tgall, *p_tgnh, *p_tlw;
    float *p_tgallb, *p_tlb;
    cudaGetSymbolAddress((void**)&p_node, g_node);
    cudaGetSymbolAddress((void**)&p_edge, g_edge);
    cudaGetSymbolAddress((void**)&p_agg,  g_agg);
    cudaGetSymbolAddress((void**)&p_m,    g_m);
    cudaGetSymbolAddress((void**)&p_gates, g_gates);
    cudaGetSymbolAddress((void**)&p_qs,   g_qs);
    cudaGetSymbolAddress((void**)&p_hl,   g_hl);
    cudaGetSymbolAddress((void**)&p_cl,   g_cl);
    cudaGetSymbolAddress((void**)&p_gl,   g_gl);
    cudaGetSymbolAddress((void**)&p_fc,   g_fc);
    cudaGetSymbolAddress((void**)&p_tg1,  t_gin1);
    cudaGetSymbolAddress((void**)&p_tg2,  t_gin2);
    cudaGetSymbolAddress((void**)&p_te1,  t_em1);
    cudaGetSymbolAddress((void**)&p_te2,  t_em2);
    cudaGetSymbolAddress((void**)&p_tf1,  t_fc1);
    cudaGetSymbolAddress((void**)&p_tgall, t_gall);
    cudaGetSymbolAddress((void**)&p_tgallb, t_gallb);
    cudaGetSymbolAddress((void**)&p_tgnh, t_gnh);
    cudaGetSymbolAddress((void**)&p_tlw,  t_lw);
    cudaGetSymbolAddress((void**)&p_tlb,  t_lb);

    const int TB = 256;
    const int SMEM_MLP2 = (3 * 128 * LDA2 + 128 * LD2H) * 4;
    cudaFuncSetAttribute(k_mlp2, cudaFuncAttributeMaxDynamicSharedMemorySize, SMEM_MLP2);
    cudaFuncSetAttribute(k_mlp2s, cudaFuncAttributeMaxDynamicSharedMemorySize, SMEM_MLP2);

    k_prep<<<CDIV(476032, TB), TB>>>(gin_w1, gin_w2, em_w1, em_w2, fc_w1,
                                     gru_wih, gru_whh, gru_bih, gru_bhh,
                                     lstm_wih, lstm_whh, lstm_bih, lstm_bhh,
                                     p_tg1, p_tg2, p_te1, p_te2, p_tf1,
                                     p_tgall, p_tgallb, p_tgnh, p_tlw, p_tlb);

    const int* src = eindex;
    const int* dst = eindex + E;

    k_gemm<<<CDIV(N, 64), 256>>>(x, 14, node_w, 128, node_b, p_node, N, 14, 0,
                                 eps, p_agg, nullptr, nullptr, nullptr);
    k_gemm<<<CDIV(E, 64), 256>>>(eattr, 4, edge_w, 128, edge_b, p_edge, E, 4, 1,
                                 eps, p_agg, src, dst, p_node);

    const int NT = CDIV(N, 128), ET = CDIV(E, 128), GT = CDIV(G, 128);

    for (int l = 0; l < 2; l++) {
        k_mlp2<<<NT, 256, SMEM_MLP2>>>(p_agg, 128, p_tg1 + l * 16384, gin_b1 + l * H,
                                       p_tg2 + l * 16384, gin_b2 + l * H, p_m, 128, N);
        // gates: r|z use K=256 ([m|h]); n_i chunk (y==2) uses K=128 (m only); fp16 out
        k_tmma<<<dim3(NT, 3), 256>>>(p_m, 128, 128, p_node, 128, p_tgall, 256, p_tgallb,
                                     p_gates, 384, N, 256, 128, 8,
                                     nullptr, nullptr, nullptr, 0);
        k_tmma<<<dim3(NT, 1), 256>>>(p_node, 128, 128, p_node, 128, p_tgnh, 128,
                                     gru_bhh + 256, p_node, 128, N, 128, 0, 4,
                                     p_gates, p_agg, eps, (l == 0) ? 1 : -1);
        if (l == 0) {
            k_mlp2s<<<ET, 256, SMEM_MLP2>>>(p_edge, 128, p_te1, em_b1, p_te2, em_b2,
                                            src, dst, p_node, p_agg, E);
        }
    }

    // Set2Set: step-0 LSTM GEMM is just the bias (qs=hl=0) -> broadcast init
    k_s2sinit<<<CDIV(G * 512, TB), TB>>>(p_gl, p_tlb, (uint2*)p_hl, (float4*)p_cl, G);
    for (int step = 0; step < 3; step++) {
        if (step > 0)
            k_tmma<<<dim3(GT, 4), 256>>>(p_qs, 256, 256, p_hl, 128, p_tlw, 384, p_tlb,
                                         p_gl, 512, G, 384, 0, 0,
                                         nullptr, nullptr, nullptr, 0);
        k_lstm<<<CDIV(G * 32, TB), TB>>>(p_gl, p_hl, p_cl, G * 32);
        k_set2set<<<CDIV(G * 32, TB), TB>>>(batch, p_node, p_hl, p_qs, N, G);
    }

    // final MLP
    k_tmma<<<dim3(GT, 1), 256>>>(p_qs, 256, 256, p_qs, 256, p_tf1, 256, fc_b1,
                                 p_fc, 128, G, 256, 0, 1,
                                 nullptr, nullptr, nullptr, 0);
    k_fc2<<<CDIV(G * 32, TB), TB>>>(p_fc, fc_w2, fc_b2, (float*)d_out, G);
}

// round 16
// speedup vs baseline: 1.6073x; 1.0040x over previous
#include <cuda_runtime.h>
#include <cuda_fp16.h>
#include <math.h>
#include <stdint.h>

#define H 128
#define NMAX 100000
#define EMAX 200000
#define GMAX 4096

#define CDIV(a,b) (((a)+(b)-1)/(b))

// ---------------- scratch ----------------
__device__ __align__(16) __half g_node[(size_t)NMAX*H];
__device__ __align__(16) __half g_edge[(size_t)EMAX*H];
__device__ __align__(16) float  g_agg [(size_t)NMAX*H];
__device__ __align__(16) __half g_m   [(size_t)NMAX*H];
__device__ __align__(16) __half g_gates[(size_t)NMAX*3*H];   // [N][384]: r | z | n_i
__device__ __align__(16) __half g_qs  [(size_t)GMAX*2*H];
__device__ __align__(16) __half g_hl  [(size_t)GMAX*H];
__device__ __align__(16) float  g_cl  [(size_t)GMAX*H];
__device__ __align__(16) float  g_gl  [(size_t)GMAX*4*H];
__device__ __align__(16) float  g_fc  [(size_t)GMAX*H];
// prepared weights (fp16)
__device__ __align__(16) __half t_gin1[2*H*H];
__device__ __align__(16) __half t_gin2[2*H*H];
__device__ __align__(16) __half t_em1 [2*H*H];
__device__ __align__(16) __half t_em2 [2*H*H];
__device__ __align__(16) __half t_fc1 [H*2*H];
__device__ __align__(16) __half t_gall[384*256];
__device__ __align__(16) __half t_gnh [H*H];
__device__ __align__(16) __half t_lw  [512*384];
__device__ __align__(16) float t_gallb[384];
__device__ __align__(16) float t_lb  [512];

// ---------------- helpers ----------------
__device__ __forceinline__ float sigf(float x) { return 1.f / (1.f + expf(-x)); }

__device__ __forceinline__ unsigned long long fma2(unsigned long long a,
                                                   unsigned long long b,
                                                   unsigned long long c) {
    unsigned long long d;
    asm("fma.rn.f32x2 %0, %1, %2, %3;" : "=l"(d) : "l"(a), "l"(b), "l"(c));
    return d;
}
union U64F2 { unsigned long long u; float2 f; };
union U128 { float4 v; unsigned long long u[2]; };

__device__ __forceinline__ uint32_t h2pack(float a, float b) {
    __half2 h = __floats2half2_rn(a, b);
    return *(uint32_t*)&h;
}
__device__ __forceinline__ float2 h2unpack(uint32_t u) {
    return __half22float2(*(__half2*)&u);
}
__device__ __forceinline__ void mma16(float* c, const uint32_t* a, const uint32_t* b) {
    asm volatile(
        "mma.sync.aligned.m16n8k16.row.col.f32.f16.f16.f32 "
        "{%0,%1,%2,%3}, {%4,%5,%6,%7}, {%8,%9}, {%0,%1,%2,%3};"
        : "+f"(c[0]), "+f"(c[1]), "+f"(c[2]), "+f"(c[3])
        : "r"(a[0]), "r"(a[1]), "r"(a[2]), "r"(a[3]), "r"(b[0]), "r"(b[1]));
}
__device__ __forceinline__ void ldm_x4(uint32_t& r0, uint32_t& r1, uint32_t& r2,
                                       uint32_t& r3, uint32_t addr) {
    asm volatile("ldmatrix.sync.aligned.m8n8.x4.shared.b16 {%0,%1,%2,%3}, [%4];"
                 : "=r"(r0), "=r"(r1), "=r"(r2), "=r"(r3) : "r"(addr));
}
__device__ __forceinline__ void redv4(float* p, float a, float b, float c, float d) {
    asm volatile("red.global.add.v4.f32 [%0], {%1, %2, %3, %4};"
                 :: "l"(p), "f"(a), "f"(b), "f"(c), "f"(d) : "memory");
}
__device__ __forceinline__ void redv2(float* p, float a, float b) {
    asm volatile("red.global.add.v2.f32 [%0], {%1, %2};"
                 :: "l"(p), "f"(a), "f"(b) : "memory");
}
__device__ __forceinline__ void cpasync8(uint32_t saddr, const void* g) {
    asm volatile("cp.async.ca.shared.global [%0], [%1], 8;" :: "r"(saddr), "l"(g));
}
#define CP_COMMIT() asm volatile("cp.async.commit_group;" ::: "memory")
#define CP_WAIT0()  asm volatile("cp.async.wait_group 0;" ::: "memory")
#define CP_WAIT1()  asm volatile("cp.async.wait_group 1;" ::: "memory")

#define LDA2 20   // half2 units per row (16 data + 4 pad)
#define LD2H 68   // mid-stage half2 row stride

// one k16 step via ldmatrix: A tile rows [aRow0,+32), B cols [bCol0,+64)
template<int SA, int SB>
__device__ __forceinline__ void mma_k16(uint32_t asA, int aRow0, int aK2,
                                        uint32_t asB, int bCol0, int bK2,
                                        float acc[2][8][4], int lane)
{
    const int g = lane >> 3, r8 = lane & 7;
    uint32_t aAddr = asA + (uint32_t)((((aRow0 + (g & 1) * 8 + r8) * SA) + aK2 + (g >> 1) * 4) * 4);
    uint32_t bAddr = asB + (uint32_t)((((bCol0 + (g >> 1) * 8 + r8) * SB) + bK2 + (g & 1) * 4) * 4);
    uint32_t af[2][4];
#pragma unroll
    for (int m = 0; m < 2; m++)
        ldm_x4(af[m][0], af[m][1], af[m][2], af[m][3], aAddr + m * 16 * SA * 4);
    uint32_t bf[8][2];
#pragma unroll
    for (int n2 = 0; n2 < 4; n2++)
        ldm_x4(bf[2*n2][0], bf[2*n2][1], bf[2*n2+1][0], bf[2*n2+1][1],
               bAddr + n2 * 16 * SB * 4);
#pragma unroll
    for (int m = 0; m < 2; m++)
#pragma unroll
        for (int n = 0; n < 8; n++) mma16(acc[m][n], af[m], bf[n]);
}

// stage fp16 tile [128 rows x 32 k] via cp.async (row clamped to maxr-1)
__device__ __forceinline__ void stage_H(uint32_t* S, const __half* P, int ld,
                                        int row0, int maxr, int k0, int tid)
{
#pragma unroll
    for (int i = 0; i < 4; i++) {
        int r = (tid >> 3) + i * 32;
        int e = tid & 7;
        int row = row0 + r;
        if (row >= maxr) row = maxr - 1;
        uint32_t sa = (uint32_t)__cvta_generic_to_shared(&S[r * LDA2 + e * 2]);
        cpasync8(sa, &P[(size_t)row * ld + k0 + e * 4]);
    }
}

// ---------------- k_tmma: triple-buffered, ONE sync per k-block ----------------
// flags: bit0 relu, bit2 GRU-finalize, bit3 fp16 output. Ky2 overrides K for blockIdx.y==2.
__global__ void __launch_bounds__(256, 2) k_tmma(
    const __half* __restrict__ A, int lda, int K1,
    const __half* __restrict__ A2, int lda2,
    const __half* __restrict__ Bt, int ldb,
    const float* __restrict__ bias,
    void* __restrict__ Optr, int ldo,
    int M, int K, int Ky2, int flags,
    const __half* __restrict__ gates, float* __restrict__ aggw,
    const float* __restrict__ eps, int epsidx)
{
    extern __shared__ uint32_t smT[];   // 3*(A 2560) + 3*(B 2560) = 15360 u32
    uint32_t* AsB[3] = { smT, smT + 2560, smT + 5120 };
    uint32_t* BsB[3] = { smT + 7680, smT + 10240, smT + 12800 };
    const int tid = threadIdx.x;
    const int wid = tid >> 5, lane = tid & 31;
    const int lr = lane >> 2, lc = lane & 3;
    const int row0 = blockIdx.x * 128;
    const int col0 = blockIdx.y * 128;
    const int rw = (wid & 3) * 32;
    const int cw = (wid >> 2) * 64;

    if (blockIdx.y == 2 && Ky2) K = Ky2;

    float acc[2][8][4];
#pragma unroll
    for (int m = 0; m < 2; m++)
#pragma unroll
        for (int n = 0; n < 8; n++)
#pragma unroll
            for (int c = 0; c < 4; c++) acc[m][n][c] = 0.f;

    const int nb = K >> 5;

    // stage block kb into buffer b
    auto stage_blk = [&](int kb, int b) {
        int k0 = kb * 32;
        const __half* srcA = (k0 < K1) ? A : A2;
        int koff = (k0 < K1) ? k0 : k0 - K1;
        int ldx = (k0 < K1) ? lda : lda2;
        stage_H(AsB[b], srcA, ldx, row0, M, koff, tid);
        stage_H(BsB[b], Bt, ldb, col0, 1 << 30, k0, tid);
        CP_COMMIT();
    };

    stage_blk(0, 0);
    if (nb > 1) stage_blk(1, 1);

    for (int kb = 0; kb < nb; kb++) {
        if (kb + 1 < nb) { CP_WAIT1(); } else { CP_WAIT0(); }
        __syncthreads();                        // buffer kb%3 ready; mma(kb-1) done by all
        if (kb + 2 < nb) stage_blk(kb + 2, (kb + 2) % 3);   // overwrites buf (kb-1)%3: safe
        const int b = kb % 3;
        const uint32_t asA = (uint32_t)__cvta_generic_to_shared(AsB[b]);
        const uint32_t asB = (uint32_t)__cvta_generic_to_shared(BsB[b]);
        mma_k16<LDA2, LDA2>(asA, rw, 0, asB, cw, 0, acc, lane);
        mma_k16<LDA2, LDA2>(asA, rw, 8, asB, cw, 8, acc, lane);
    }

    if (flags & 4) {
        __half* Oh = (__half*)Optr;
        float escale = (epsidx >= 0) ? (1.f + eps[epsidx]) : 0.f;
#pragma unroll
        for (int m = 0; m < 2; m++) {
#pragma unroll
            for (int n = 0; n < 8; n++) {
                int col = cw + n * 8 + lc * 2;
                float b0 = bias[col], b1 = bias[col + 1];
#pragma unroll
                for (int half = 0; half < 2; half++) {
                    int row = row0 + rw + m * 16 + lr + half * 8;
                    if (row < M) {
                        float nh0 = acc[m][n][half * 2] + b0;
                        float nh1 = acc[m][n][half * 2 + 1] + b1;
                        const __half* gr = &gates[(size_t)row * 384];
                        float2 rr = h2unpack(*(const uint32_t*)&gr[col]);
                        float2 zz = h2unpack(*(const uint32_t*)&gr[col + 128]);
                        float2 ni = h2unpack(*(const uint32_t*)&gr[col + 256]);
                        uint32_t* hp = (uint32_t*)&Oh[(size_t)row * ldo + col];
                        float2 hv = h2unpack(*hp);
                        float r0 = sigf(rr.x), z0 = sigf(zz.x);
                        float nn0 = tanhf(ni.x + r0 * nh0);
                        float h0 = (1.f - z0) * nn0 + z0 * hv.x;
                        float r1 = sigf(rr.y), z1 = sigf(zz.y);
                        float nn1 = tanhf(ni.y + r1 * nh1);
                        float h1 = (1.f - z1) * nn1 + z1 * hv.y;
                        *hp = h2pack(h0, h1);
                        if (epsidx >= 0) {
                            float2 ao = {escale * h0, escale * h1};
                            *(float2*)&aggw[(size_t)row * 128 + col] = ao;
                        }
                    }
                }
            }
        }
        return;
    }

    if (flags & 8) {
        __half* Oh = (__half*)Optr;
#pragma unroll
        for (int m = 0; m < 2; m++) {
#pragma unroll
            for (int n = 0; n < 8; n++) {
                int col = col0 + cw + n * 8 + lc * 2;
                float b0 = bias[col], b1 = bias[col + 1];
#pragma unroll
                for (int half = 0; half < 2; half++) {
                    int row = row0 + rw + m * 16 + lr + half * 8;
                    if (row < M) {
                        float v0 = acc[m][n][half * 2] + b0;
                        float v1 = acc[m][n][half * 2 + 1] + b1;
                        if (flags & 1) { v0 = fmaxf(v0, 0.f); v1 = fmaxf(v1, 0.f); }
                        *(uint32_t*)&Oh[(size_t)row * ldo + col] = h2pack(v0, v1);
                    }
                }
            }
        }
        return;
    }

    float* O = (float*)Optr;
#pragma unroll
    for (int m = 0; m < 2; m++) {
#pragma unroll
        for (int n = 0; n < 8; n++) {
            int col = col0 + cw + n * 8 + lc * 2;
            float b0 = bias[col], b1 = bias[col + 1];
#pragma unroll
            for (int half = 0; half < 2; half++) {
                int row = row0 + rw + m * 16 + lr + half * 8;
                if (row < M) {
                    float v0 = acc[m][n][half * 2] + b0;
                    float v1 = acc[m][n][half * 2 + 1] + b1;
                    if (flags & 1) { v0 = fmaxf(v0, 0.f); v1 = fmaxf(v1, 0.f); }
                    float2 ov = {v0, v1};
                    *(float2*)&O[(size_t)row * ldo + col] = ov;
                }
            }
        }
    }
}

// ---------------- shared GEMM2 of the fused MLP (As2 @ W2t, B double-buffered) ---------
__device__ __forceinline__ void mlp2_gemm2(
    const __half* __restrict__ W2t, uint32_t* Bs0, uint32_t* Bs1,
    uint32_t asA2, float acc[2][8][4], int tid, int rw, int cw, int lane)
{
    uint32_t* BsB[2] = { Bs0, Bs1 };
    stage_H(BsB[0], W2t, 128, 0, 1 << 30, 0, tid);
    CP_COMMIT();
    __syncthreads();
#pragma unroll
    for (int kb = 0; kb < 4; kb++) {
        if (kb + 1 < 4) {
            stage_H(BsB[(kb + 1) & 1], W2t, 128, 0, 1 << 30, (kb + 1) * 32, tid);
            CP_COMMIT();
            CP_WAIT1();
        } else {
            CP_WAIT0();
        }
        __syncthreads();
        const int k2b = kb * 16;
        const uint32_t asB = (uint32_t)__cvta_generic_to_shared(BsB[kb & 1]);
        mma_k16<LD2H, LDA2>(asA2, rw, k2b,     asB, cw, 0, acc, lane);
        mma_k16<LD2H, LDA2>(asA2, rw, k2b + 8, asB, cw, 8, acc, lane);
        __syncthreads();
    }
}

// mid epilogue: relu(+b1) -> As2 (half2 per col pair)
__device__ __forceinline__ void mlp2_mid(uint32_t* As2, const float* b1,
                                         float acc[2][8][4], int rw, int cw,
                                         int lr, int lc)
{
#pragma unroll
    for (int m = 0; m < 2; m++) {
#pragma unroll
        for (int n = 0; n < 8; n++) {
            int c2 = (cw >> 1) + n * 4 + lc;
            int col = cw + n * 8 + lc * 2;
            float b0 = b1[col], bb1 = b1[col + 1];
            int r1 = rw + m * 16 + lr, r2 = r1 + 8;
            As2[r1 * LD2H + c2] = h2pack(fmaxf(acc[m][n][0] + b0, 0.f),
                                         fmaxf(acc[m][n][1] + bb1, 0.f));
            As2[r2 * LD2H + c2] = h2pack(fmaxf(acc[m][n][2] + b0, 0.f),
                                         fmaxf(acc[m][n][3] + bb1, 0.f));
            acc[m][n][0] = acc[m][n][1] = acc[m][n][2] = acc[m][n][3] = 0.f;
        }
    }
}

// ---------------- GIN MLP (A fp32 agg), fp16 output ----------------
__global__ void __launch_bounds__(256, 2) k_mlp2(
    const float* __restrict__ A, int lda,
    const __half* __restrict__ W1t, const float* __restrict__ b1,
    const __half* __restrict__ W2t, const float* __restrict__ b2,
    __half* __restrict__ O, int ldo, int M)
{
    extern __shared__ uint32_t sm[];
    uint32_t* As  = sm;                 // 2560
    uint32_t* Bs0 = sm + 2560;
    uint32_t* Bs1 = sm + 5120;
    uint32_t* As2 = sm + 7680;          // 8704
    const uint32_t asA = (uint32_t)__cvta_generic_to_shared(As);
    const uint32_t asA2 = (uint32_t)__cvta_generic_to_shared(As2);
    uint32_t* BsB[2] = { Bs0, Bs1 };
    const int tid = threadIdx.x;
    const int wid = tid >> 5, lane = tid & 31;
    const int lr = lane >> 2, lc = lane & 3;
    const int rw = (wid & 3) * 32;
    const int cw = (wid >> 2) * 64;
    const int r_ = tid >> 3, f4_ = tid & 7;
    const int row0 = blockIdx.x * 128;

    float acc[2][8][4];
#pragma unroll
    for (int m = 0; m < 2; m++)
#pragma unroll
        for (int n = 0; n < 8; n++)
#pragma unroll
            for (int c = 0; c < 4; c++) acc[m][n][c] = 0.f;

    float4 aR[4];
#pragma unroll
    for (int i = 0; i < 4; i++) {
        int row = row0 + r_ + i * 32;
        aR[i] = make_float4(0.f, 0.f, 0.f, 0.f);
        if (row < M) aR[i] = *(const float4*)&A[(size_t)row * lda + f4_ * 4];
    }
    stage_H(BsB[0], W1t, 128, 0, 1 << 30, 0, tid);
    CP_COMMIT();

    // GEMM1 (A reg-prefetch, B double-buffered)
#pragma unroll
    for (int kb = 0; kb < 4; kb++) {
#pragma unroll
        for (int i = 0; i < 4; i++) {
            int r = r_ + i * 32;
            uint32_t* p = &As[r * LDA2 + f4_ * 2];
            p[0] = h2pack(aR[i].x, aR[i].y);
            p[1] = h2pack(aR[i].z, aR[i].w);
        }
        if (kb + 1 < 4) {
            stage_H(BsB[(kb + 1) & 1], W1t, 128, 0, 1 << 30, (kb + 1) * 32, tid);
            CP_COMMIT();
#pragma unroll
            for (int i = 0; i < 4; i++) {
                int row = row0 + r_ + i * 32;
                aR[i] = make_float4(0.f, 0.f, 0.f, 0.f);
                if (row < M) aR[i] = *(const float4*)&A[(size_t)row * lda + (kb + 1) * 32 + f4_ * 4];
            }
            CP_WAIT1();
        } else {
            CP_WAIT0();
        }
        __syncthreads();
        const uint32_t asB = (uint32_t)__cvta_generic_to_shared(BsB[kb & 1]);
        mma_k16<LDA2, LDA2>(asA, rw, 0, asB, cw, 0, acc, lane);
        mma_k16<LDA2, LDA2>(asA, rw, 8, asB, cw, 8, acc, lane);
        __syncthreads();
    }

    mlp2_mid(As2, b1, acc, rw, cw, lr, lc);
    mlp2_gemm2(W2t, Bs0, Bs1, asA2, acc, tid, rw, cw, lane);

#pragma unroll
    for (int m = 0; m < 2; m++) {
#pragma unroll
        for (int n = 0; n < 8; n++) {
            int col = cw + n * 8 + lc * 2;
            float b0 = b2[col], bb1 = b2[col + 1];
#pragma unroll
            for (int half = 0; half < 2; half++) {
                int row = row0 + rw + m * 16 + lr + half * 8;
                if (row < M) {
                    *(uint32_t*)&O[(size_t)row * ldo + col] =
                        h2pack(acc[m][n][half * 2] + b0, acc[m][n][half * 2 + 1] + bb1);
                }
            }
        }
    }
}

// ---------------- edge MLP (A fp16 edge) + fused GINE scatter ----------------
__global__ void __launch_bounds__(256, 2) k_mlp2s(
    const __half* __restrict__ A, int lda,
    const __half* __restrict__ W1t, const float* __restrict__ b1,
    const __half* __restrict__ W2t, const float* __restrict__ b2,
    const int* __restrict__ src, const int* __restrict__ dst,
    const __half* __restrict__ node, float* __restrict__ agg, int M)
{
    extern __shared__ uint32_t sm[];
    uint32_t* As0 = sm;
    uint32_t* As1 = sm + 2560;
    uint32_t* Bs0 = sm + 5120;
    uint32_t* Bs1 = sm + 7680;
    uint32_t* As2 = sm + 10240;         // 8704
    const uint32_t asA2 = (uint32_t)__cvta_generic_to_shared(As2);
    uint32_t* AsB[2] = { As0, As1 };
    uint32_t* BsB[2] = { Bs0, Bs1 };
    const int tid = threadIdx.x;
    const int wid = tid >> 5, lane = tid & 31;
    const int lr = lane >> 2, lc = lane & 3;
    const int rw = (wid & 3) * 32;
    const int cw = (wid >> 2) * 64;
    const int row0 = blockIdx.x * 128;

    float acc[2][8][4];
#pragma unroll
    for (int m = 0; m < 2; m++)
#pragma unroll
        for (int n = 0; n < 8; n++)
#pragma unroll
            for (int c = 0; c < 4; c++) acc[m][n][c] = 0.f;

    // GEMM1: A & B double-buffered cp.async
    stage_H(AsB[0], A, lda, row0, M, 0, tid);
    stage_H(BsB[0], W1t, 128, 0, 1 << 30, 0, tid);
    CP_COMMIT();
#pragma unroll
    for (int kb = 0; kb < 4; kb++) {
        if (kb + 1 < 4) {
            stage_H(AsB[(kb + 1) & 1], A, lda, row0, M, (kb + 1) * 32, tid);
            stage_H(BsB[(kb + 1) & 1], W1t, 128, 0, 1 << 30, (kb + 1) * 32, tid);
            CP_COMMIT();
            CP_WAIT1();
        } else {
            CP_WAIT0();
        }
        __syncthreads();
        const uint32_t asA = (uint32_t)__cvta_generic_to_shared(AsB[kb & 1]);
        const uint32_t asB = (uint32_t)__cvta_generic_to_shared(BsB[kb & 1]);
        mma_k16<LDA2, LDA2>(asA, rw, 0, asB, cw, 0, acc, lane);
        mma_k16<LDA2, LDA2>(asA, rw, 8, asB, cw, 8, acc, lane);
        __syncthreads();
    }

    mlp2_mid(As2, b1, acc, rw, cw, lr, lc);
    mlp2_gemm2(W2t, Bs0, Bs1, asA2, acc, tid, rw, cw, lane);

#pragma unroll
    for (int m = 0; m < 2; m++) {
#pragma unroll
        for (int n = 0; n < 8; n++) {
            int col = cw + n * 8 + lc * 2;
            float b0 = b2[col], bb1 = b2[col + 1];
#pragma unroll
            for (int half = 0; half < 2; half++) {
                int e = row0 + rw + m * 16 + lr + half * 8;
                if (e < M) {
                    float v0 = acc[m][n][half * 2] + b0;
                    float v1 = acc[m][n][half * 2 + 1] + bb1;
                    int s = src[e], d = dst[e];
                    float2 nv = h2unpack(*(const uint32_t*)&node[(size_t)s * 128 + col]);
                    float m0 = fmaxf(nv.x + v0, 0.f);
                    float m1 = fmaxf(nv.y + v1, 0.f);
                    redv2(&agg[(size_t)d * 128 + col], m0, m1);
                }
            }
        }
    }
}

// ---------------- FFMA2 GEMM: embeddings (fp16 out); mode 0: node(+agg), mode 1: edge(+scatter)
__global__ void __launch_bounds__(256) k_gemm(
    const float* __restrict__ A, int lda,
    const float* __restrict__ W, int ldw,
    const float* __restrict__ bias,
    __half* __restrict__ Oh, int M, int K, int mode,
    const float* __restrict__ eps, float* __restrict__ agg,
    const int* __restrict__ src, const int* __restrict__ dst,
    const __half* __restrict__ node)
{
    __shared__ __align__(16) unsigned long long Asd[16][65];
    __shared__ __align__(16) float Ws[16][128];
    const int tid = threadIdx.x;
    const int tx = tid & 31, ty = tid >> 5;
    const int row0 = blockIdx.x * 64;

    unsigned long long acc[8][2];
#pragma unroll
    for (int r = 0; r < 8; r++) { acc[r][0] = 0ULL; acc[r][1] = 0ULL; }

    for (int k0 = 0; k0 < K; k0 += 16) {
#pragma unroll
        for (int i = tid; i < 1024; i += 256) {
            int r = i >> 4, k = i & 15;
            int row = row0 + r, kk = k0 + k;
            float v = (row < M && kk < K) ? A[(size_t)row * lda + kk] : 0.f;
            U64F2 p; p.f.x = v; p.f.y = v;
            Asd[k][r] = p.u;
        }
#pragma unroll
        for (int i = tid; i < 2048; i += 256) {
            int k = i >> 7, j = i & 127;
            int kk = k0 + k;
            Ws[k][j] = (kk < K) ? W[(size_t)kk * ldw + j] : 0.f;
        }
        __syncthreads();
#pragma unroll
        for (int k = 0; k < 16; k++) {
            U128 w; w.v = *(const float4*)&Ws[k][tx << 2];
#pragma unroll
            for (int r = 0; r < 8; r++) {
                unsigned long long a = Asd[k][(ty << 3) + r];
                acc[r][0] = fma2(a, w.u[0], acc[r][0]);
                acc[r][1] = fma2(a, w.u[1], acc[r][1]);
            }
        }
        __syncthreads();
    }
    const int col = tx << 2;
    float4 b4 = *(const float4*)&bias[col];
    float escale = (mode == 0) ? (1.f + eps[0]) : 0.f;
#pragma unroll
    for (int r = 0; r < 8; r++) {
        int row = row0 + (ty << 3) + r;
        if (row < M) {
            U64F2 p0, p1; p0.u = acc[r][0]; p1.u = acc[r][1];
            float v0 = p0.f.x + b4.x, v1 = p0.f.y + b4.y;
            float v2 = p1.f.x + b4.z, v3 = p1.f.y + b4.w;
            uint2 hv = { h2pack(v0, v1), h2pack(v2, v3) };
            *(uint2*)&Oh[(size_t)row * 128 + col] = hv;
            if (mode == 0) {
                float4 av = {escale * v0, escale * v1, escale * v2, escale * v3};
                *(float4*)&agg[(size_t)row * 128 + col] = av;
            } else {
                int s = src[row], d = dst[row];
                uint2 nu = *(const uint2*)&node[(size_t)s * 128 + col];
                float2 n01 = h2unpack(nu.x), n23 = h2unpack(nu.y);
                redv4(&agg[(size_t)d * 128 + col],
                      fmaxf(n01.x + v0, 0.f), fmaxf(n01.y + v1, 0.f),
                      fmaxf(n23.x + v2, 0.f), fmaxf(n23.y + v3, 0.f));
            }
        }
    }
}

// ---------------- prep: weight transposes/stacks -> fp16 ----------------
__global__ void k_prep(const float* __restrict__ gin1, const float* __restrict__ gin2,
                       const float* __restrict__ em1, const float* __restrict__ em2,
                       const float* __restrict__ fcw1,
                       const float* __restrict__ gwih, const float* __restrict__ gwhh,
                       const float* __restrict__ gbih, const float* __restrict__ gbhh,
                       const float* __restrict__ lwih, const float* __restrict__ lwhh,
                       const float* __restrict__ lbih, const float* __restrict__ lbhh,
                       __half* __restrict__ tg1, __half* __restrict__ tg2,
                       __half* __restrict__ te1, __half* __restrict__ te2,
                       __half* __restrict__ tf1,
                       __half* __restrict__ tgall, float* __restrict__ tgallb,
                       __half* __restrict__ tgnh,
                       __half* __restrict__ tlw, float* __restrict__ tlb)
{
    int i = blockIdx.x * blockDim.x + threadIdx.x;
    if (i < 131072) {
        int m = i >> 14, j = i & 16383;
        int r = j >> 7, c = j & 127;
        int l = m & 1, which = m >> 1;
        const float* s = (which == 0) ? gin1 : (which == 1) ? gin2 : (which == 2) ? em1 : em2;
        __half* d = (which == 0) ? tg1 : (which == 1) ? tg2 : (which == 2) ? te1 : te2;
        d[(size_t)l * 16384 + c * 128 + r] = __float2half_rn(s[(size_t)l * 16384 + j]);
    } else if (i < 163840) {
        int j = i - 131072;
        int r = j >> 7, c = j & 127;
        tf1[(size_t)c * 256 + r] = __float2half_rn(fcw1[j]);
    } else if (i < 262144) {
        int j = i - 163840;
        int c = j >> 8, k = j & 255;
        float v = (k < 128) ? gwih[c * 128 + k]
                            : ((c < 256) ? gwhh[c * 128 + (k - 128)] : 0.f);
        tgall[j] = __float2half_rn(v);
    } else if (i < 458752) {
        int j = i - 262144;
        int c = j / 384, k = j % 384;
        tlw[j] = __float2half_rn((k < 256) ? lwih[c * 256 + k] : lwhh[c * 128 + (k - 256)]);
    } else if (i < 475136) {
        int j = i - 458752;
        tgnh[j] = __float2half_rn(gwhh[256 * 128 + j]);
    } else if (i < 475520) {
        int j = i - 475136;
        tgallb[j] = (j < 256) ? gbih[j] + gbhh[j] : gbih[j];
    } else if (i < 476032) {
        int j = i - 475520;
        tlb[j] = lbih[j] + lbhh[j];
    }
}

// Set2Set init: gl = broadcast(tlb), cl = 0
__global__ void k_s2sinit(float* __restrict__ gl, const float* __restrict__ tlb,
                          float4* __restrict__ cl, int G)
{
    int i = blockIdx.x * blockDim.x + threadIdx.x;
    if (i < G * 512) gl[i] = tlb[i & 511];
    if (i < G * 32) cl[i] = make_float4(0.f, 0.f, 0.f, 0.f);
}

__device__ __forceinline__ void lstm1(float i_, float f_, float g_, float o_,
                                      float& c, float& hh) {
    c = sigf(f_) * c + sigf(i_) * tanhf(g_);
    hh = sigf(o_) * tanhf(c);
}

// fused LSTM + Set2Set attention: one warp per graph
__global__ void k_s2s(const int* __restrict__ batch, const __half* __restrict__ node,
                      const float* __restrict__ gl, float* __restrict__ cl,
                      __half* __restrict__ hl, __half* __restrict__ qs,
                      int N, int G)
{
    int warp = (blockIdx.x * blockDim.x + threadIdx.x) >> 5;
    if (warp >= G) return;
    const int lane = threadIdx.x & 31;
    const int g = warp;
    const int j = lane * 4;

    // LSTM cell (each lane: 4 columns)
    const float* gr = &gl[(size_t)g * 512];
    float4 i_ = *(const float4*)&gr[j];
    float4 f_ = *(const float4*)&gr[j + 128];
    float4 g_ = *(const float4*)&gr[j + 256];
    float4 o_ = *(const float4*)&gr[j + 384];
    float4* cp = (float4*)&cl[(size_t)g * 128 + j];
    float4 c = *cp, qv;
    lstm1(i_.x, f_.x, g_.x, o_.x, c.x, qv.x);
    lstm1(i_.y, f_.y, g_.y, o_.y, c.y, qv.y);
    lstm1(i_.z, f_.z, g_.z, o_.z, c.z, qv.z);
    lstm1(i_.w, f_.w, g_.w, o_.w, c.w, qv.w);
    *cp = c;
    uint2 ho = { h2pack(qv.x, qv.y), h2pack(qv.z, qv.w) };
    *(uint2*)&hl[(size_t)g * 128 + j] = ho;

    // segment bounds
    int lo = 0, hi = N;
    while (lo < hi) { int mid = (lo + hi) >> 1; if (batch[mid] < g) lo = mid + 1; else hi = mid; }
    const int s0 = lo;
    hi = N;
    while (lo < hi) { int mid = (lo + hi) >> 1; if (batch[mid] < g + 1) lo = mid + 1; else hi = mid; }
    const int s1 = lo;

    float mx = -INFINITY, den = 0.f;
    float4 racc = make_float4(0.f, 0.f, 0.f, 0.f);
    for (int i = s0; i < s1; i++) {
        uint2 nu = *(const uint2*)&node[(size_t)i * H + j];
        float2 na = h2unpack(nu.x), nb = h2unpack(nu.y);
        float d = na.x * qv.x + na.y * qv.y + nb.x * qv.z + nb.y * qv.w;
#pragma unroll
        for (int o = 16; o; o >>= 1) d += __shfl_xor_sync(0xffffffffu, d, o);
        float nm = fmaxf(mx, d);
        float sc = expf(mx - nm);
        float ex = expf(d - nm);
        den = den * sc + ex;
        racc.x = racc.x * sc + ex * na.x;
        racc.y = racc.y * sc + ex * na.y;
        racc.z = racc.z * sc + ex * nb.x;
        racc.w = racc.w * sc + ex * nb.y;
        mx = nm;
    }
    float inv = 1.f / fmaxf(den, 1e-9f);
    __half* qrow = &qs[(size_t)g * 2 * H];
    *(uint2*)&qrow[j] = ho;
    uint2 ro = { h2pack(racc.x * inv, racc.y * inv), h2pack(racc.z * inv, racc.w * inv) };
    *(uint2*)&qrow[H + j] = ro;
}

__global__ void k_fc2(const float* __restrict__ fcin, const float* __restrict__ w2,
                      const float* __restrict__ b2, float* __restrict__ out, int G)
{
    int tid = blockIdx.x * blockDim.x + threadIdx.x;
    int g = tid >> 5;
    if (g >= G) return;
    int lane = tid & 31;
    float s = 0.f;
#pragma unroll
    for (int t = 0; t < 4; t++) {
        int j = lane + t * 32;
        s += fcin[(size_t)g * H + j] * w2[j];
    }
#pragma unroll
    for (int off = 16; off; off >>= 1) s += __shfl_xor_sync(0xffffffffu, s, off);
    if (lane == 0) out[g] = s + b2[0];
}

// ---------------- host launcher ----------------
extern "C" void kernel_launch(void* const* d_in, const int* in_sizes, int n_in,
                              void* d_out, int out_size)
{
    const float* x       = (const float*)d_in[0];
    const float* eattr   = (const float*)d_in[1];
    const int*   eindex  = (const int*)d_in[2];
    const int*   batch   = (const int*)d_in[3];
    const float* node_w  = (const float*)d_in[4];
    const float* node_b  = (const float*)d_in[5];
    const float* edge_w  = (const float*)d_in[6];
    const float* edge_b  = (const float*)d_in[7];
    const float* eps     = (const float*)d_in[8];
    const float* gin_w1  = (const float*)d_in[9];
    const float* gin_b1  = (const float*)d_in[10];
    const float* gin_w2  = (const float*)d_in[11];
    const float* gin_b2  = (const float*)d_in[12];
    const float* em_w1   = (const float*)d_in[13];
    const float* em_b1   = (const float*)d_in[14];
    const float* em_w2   = (const float*)d_in[15];
    const float* em_b2   = (const float*)d_in[16];
    const float* gru_wih = (const float*)d_in[17];
    const float* gru_whh = (const float*)d_in[18];
    const float* gru_bih = (const float*)d_in[19];
    const float* gru_bhh = (const float*)d_in[20];
    const float* lstm_wih= (const float*)d_in[21];
    const float* lstm_whh= (const float*)d_in[22];
    const float* lstm_bih= (const float*)d_in[23];
    const float* lstm_bhh= (const float*)d_in[24];
    const float* fc_w1   = (const float*)d_in[25];
    const float* fc_b1   = (const float*)d_in[26];
    const float* fc_w2   = (const float*)d_in[27];
    const float* fc_b2   = (const float*)d_in[28];

    const int N = in_sizes[0] / 14;
    const int E = in_sizes[1] / 4;
    const int G = out_size;

    __half *p_node, *p_edge, *p_m, *p_gates, *p_qs, *p_hl;
    float *p_agg, *p_cl, *p_gl, *p_fc;
    __half *p_tg1, *p_tg2, *p_te1, *p_te2, *p_tf1, *p_tgall, *p_tgnh, *p_tlw;
    float *p_tgallb, *p_tlb;
    cudaGetSymbolAddress((void**)&p_node, g_node);
    cudaGetSymbolAddress((void**)&p_edge, g_edge);
    cudaGetSymbolAddress((void**)&p_agg,  g_agg);
    cudaGetSymbolAddress((void**)&p_m,    g_m);
    cudaGetSymbolAddress((void**)&p_gates, g_gates);
    cudaGetSymbolAddress((void**)&p_qs,   g_qs);
    cudaGetSymbolAddress((void**)&p_hl,   g_hl);
    cudaGetSymbolAddress((void**)&p_cl,   g_cl);
    cudaGetSymbolAddress((void**)&p_gl,   g_gl);
    cudaGetSymbolAddress((void**)&p_fc,   g_fc);
    cudaGetSymbolAddress((void**)&p_tg1,  t_gin1);
    cudaGetSymbolAddress((void**)&p_tg2,  t_gin2);
    cudaGetSymbolAddress((void**)&p_te1,  t_em1);
    cudaGetSymbolAddress((void**)&p_te2,  t_em2);
    cudaGetSymbolAddress((void**)&p_tf1,  t_fc1);
    cudaGetSymbolAddress((void**)&p_tgall, t_gall);
    cudaGetSymbolAddress((void**)&p_tgallb, t_gallb);
    cudaGetSymbolAddress((void**)&p_tgnh, t_gnh);
    cudaGetSymbolAddress((void**)&p_tlw,  t_lw);
    cudaGetSymbolAddress((void**)&p_tlb,  t_lb);

    const int TB = 256;
    const int SMEM_T    = 15360 * 4;                 // k_tmma: 3x(A+B)
    const int SMEM_MLP2 = (3 * 2560 + 8704) * 4;     // k_mlp2
    const int SMEM_MLPS = (4 * 2560 + 8704) * 4;     // k_mlp2s
    cudaFuncSetAttribute(k_tmma, cudaFuncAttributeMaxDynamicSharedMemorySize, SMEM_T);
    cudaFuncSetAttribute(k_mlp2, cudaFuncAttributeMaxDynamicSharedMemorySize, SMEM_MLP2);
    cudaFuncSetAttribute(k_mlp2s, cudaFuncAttributeMaxDynamicSharedMemorySize, SMEM_MLPS);

    k_prep<<<CDIV(476032, TB), TB>>>(gin_w1, gin_w2, em_w1, em_w2, fc_w1,
                                     gru_wih, gru_whh, gru_bih, gru_bhh,
                                     lstm_wih, lstm_whh, lstm_bih, lstm_bhh,
                                     p_tg1, p_tg2, p_te1, p_te2, p_tf1,
                                     p_tgall, p_tgallb, p_tgnh, p_tlw, p_tlb);

    const int* src = eindex;
    const int* dst = eindex + E;

    k_gemm<<<CDIV(N, 64), 256>>>(x, 14, node_w, 128, node_b, p_node, N, 14, 0,
                                 eps, p_agg, nullptr, nullptr, nullptr);
    k_gemm<<<CDIV(E, 64), 256>>>(eattr, 4, edge_w, 128, edge_b, p_edge, E, 4, 1,
                                 eps, p_agg, src, dst, p_node);

    const int NT = CDIV(N, 128), ET = CDIV(E, 128), GT = CDIV(G, 128);

    for (int l = 0; l < 2; l++) {
        k_mlp2<<<NT, 256, SMEM_MLP2>>>(p_agg, 128, p_tg1 + l * 16384, gin_b1 + l * H,
                                       p_tg2 + l * 16384, gin_b2 + l * H, p_m, 128, N);
        k_tmma<<<dim3(NT, 3), 256, SMEM_T>>>(p_m, 128, 128, p_node, 128, p_tgall, 256,
                                             p_tgallb, p_gates, 384, N, 256, 128, 8,
                                             nullptr, nullptr, nullptr, 0);
        k_tmma<<<dim3(NT, 1), 256, SMEM_T>>>(p_node, 128, 128, p_node, 128, p_tgnh, 128,
                                             gru_bhh + 256, p_node, 128, N, 128, 0, 4,
                                             p_gates, p_agg, eps, (l == 0) ? 1 : -1);
        if (l == 0) {
            k_mlp2s<<<ET, 256, SMEM_MLPS>>>(p_edge, 128, p_te1, em_b1, p_te2, em_b2,
                                            src, dst, p_node, p_agg, E);
        }
    }

    // Set2Set: step-0 LSTM GEMM result is just the combined bias
    k_s2sinit<<<CDIV(G * 512, TB), TB>>>(p_gl, p_tlb, (float4*)p_cl, G);
    for (int step = 0; step < 3; step++) {
        if (step > 0)
            k_tmma<<<dim3(GT, 4), 256, SMEM_T>>>(p_qs, 256, 256, p_hl, 128, p_tlw, 384,
                                                 p_tlb, p_gl, 512, G, 384, 0, 0,
                                                 nullptr, nullptr, nullptr, 0);
        k_s2s<<<CDIV(G * 32, TB), TB>>>(batch, p_node, p_gl, p_cl, p_hl, p_qs, N, G);
    }

    // final MLP
    k_tmma<<<dim3(GT, 1), 256, SMEM_T>>>(p_qs, 256, 256, p_qs, 256, p_tf1, 256, fc_b1,
                                         p_fc, 128, G, 256, 0, 1,
                                         nullptr, nullptr, nullptr, 0);
    k_fc2<<<CDIV(G * 32, TB), TB>>>(p_fc, fc_w2, fc_b2, (float*)d_out, G);
}